// round 1
// baseline (speedup 1.0000x reference)
#include <cuda_runtime.h>
#include <cuda_bf16.h>
#include <cstdint>

// ---------------------------------------------------------------------------
// Problem dims (compile-time)
// ---------------------------------------------------------------------------
#define BATCH 64
#define CCH   16
#define SZ    128
#define WS    32
#define PS    8
#define NH    8
#define WN    4          // windows per side
#define PPW   4          // patches per side per window
#define NWIN  16
#define NPAT  16
#define PD    1024
#define PDH   128
#define PLD   1024
#define WDH   128
#define WIN_INNER 1024
#define WD    16384
#define NTOK_P (BATCH*NWIN*NPAT)   // 16384 patch tokens
#define NTOK_W (BATCH*NWIN)        // 1024 window tokens
#define ATT_SCALE 0.08838834764831845f  // 128^-0.5

// ---------------------------------------------------------------------------
// Scratch (device globals; allocation-free per harness rules)
// ---------------------------------------------------------------------------
__device__ float g_fl  [(size_t)NTOK_P * PD];        // LN'd patch tokens
__device__ float g_qkp [(size_t)NTOK_P * 2 * PD];    // patch q|k
__device__ float g_pv  [(size_t)NTOK_P * PD];        // patch v
__device__ float g_pf  [(size_t)NTOK_P * PD];        // attn+conv merged
__device__ float g_pfo [(size_t)NTOK_P * PD];        // pf @ Wout_p
__device__ float g_plln[(size_t)NTOK_W * PLD];       // LN'd pooled tokens
__device__ float g_qkw [(size_t)NTOK_W * 2 * WIN_INNER];
__device__ float g_nds [(size_t)BATCH * NH * NWIN * NWIN];
__device__ float g_ds  [(size_t)BATCH * NH * NWIN];
__device__ float g_lnxw[(size_t)NTOK_W * WD];        // LN'd window pixels
__device__ float g_wv  [(size_t)NTOK_W * WIN_INNER];
__device__ float g_wf  [(size_t)NTOK_W * WIN_INNER];
__device__ float g_wfo [(size_t)NTOK_W * WD];

// ---------------------------------------------------------------------------
// Block reduce
// ---------------------------------------------------------------------------
__device__ __forceinline__ float blockReduceSum(float v, float* sh) {
    int lane = threadIdx.x & 31, wid = threadIdx.x >> 5;
    #pragma unroll
    for (int o = 16; o > 0; o >>= 1) v += __shfl_down_sync(0xffffffffu, v, o);
    if (lane == 0) sh[wid] = v;
    __syncthreads();
    int nw = blockDim.x >> 5;
    v = (threadIdx.x < (unsigned)nw) ? sh[threadIdx.x] : 0.f;
    if (wid == 0) {
        #pragma unroll
        for (int o = 16; o > 0; o >>= 1) v += __shfl_down_sync(0xffffffffu, v, o);
        if (lane == 0) sh[0] = v;
    }
    __syncthreads();
    float r = sh[0];
    __syncthreads();
    return r;
}

// ---------------------------------------------------------------------------
// Generic tiled SGEMM body: C[M,N] = A[M,K] @ B[K,N], all row-major,
// dims compile-time, 128x128x8 tile, 256 threads, 8x8 per-thread microtile.
// ---------------------------------------------------------------------------
template<int M, int N, int K>
__device__ __forceinline__ void gemm_body(const float* __restrict__ A,
                                          const float* __restrict__ B,
                                          float* __restrict__ C) {
    constexpr int BM = 128, BN = 128, BK = 8, TM = 8, TN = 8;
    __shared__ float As[BK][BM];
    __shared__ float Bs[BK][BN];
    const int bx = blockIdx.x;          // N tile
    const int by = blockIdx.y;          // M tile
    const int tid = threadIdx.x;
    const int tr = tid >> 4, tc = tid & 15;
    float acc[TM][TN];
    #pragma unroll
    for (int i = 0; i < TM; i++)
        #pragma unroll
        for (int j = 0; j < TN; j++) acc[i][j] = 0.f;

    const float* Ab = A + (size_t)by * BM * K;
    const float* Bb = B + (size_t)bx * BN;
    const int aRow = tid >> 1, aCol = (tid & 1) * 4;   // 128 x 8
    const int bRow = tid >> 5, bCol = (tid & 31) * 4;  // 8 x 128

    for (int k0 = 0; k0 < K; k0 += BK) {
        float4 av = *(const float4*)(Ab + (size_t)aRow * K + k0 + aCol);
        As[aCol + 0][aRow] = av.x;
        As[aCol + 1][aRow] = av.y;
        As[aCol + 2][aRow] = av.z;
        As[aCol + 3][aRow] = av.w;
        float4 bv = *(const float4*)(Bb + (size_t)(k0 + bRow) * N + bCol);
        *(float4*)&Bs[bRow][bCol] = bv;
        __syncthreads();
        #pragma unroll
        for (int k = 0; k < BK; k++) {
            float ar[TM], br[TN];
            #pragma unroll
            for (int i = 0; i < TM; i++) ar[i] = As[k][tr * TM + i];
            #pragma unroll
            for (int j = 0; j < TN; j++) br[j] = Bs[k][tc * TN + j];
            #pragma unroll
            for (int i = 0; i < TM; i++)
                #pragma unroll
                for (int j = 0; j < TN; j++) acc[i][j] += ar[i] * br[j];
        }
        __syncthreads();
    }
    #pragma unroll
    for (int i = 0; i < TM; i++) {
        size_t row = (size_t)by * BM + tr * TM + i;
        float* Crow = C + row * N + (size_t)bx * BN + tc * TN;
        #pragma unroll
        for (int j = 0; j < TN; j += 4) {
            float4 v = make_float4(acc[i][j], acc[i][j+1], acc[i][j+2], acc[i][j+3]);
            *(float4*)(Crow + j) = v;
        }
    }
}

// GEMM instantiations referencing device globals directly (capture-safe).
__global__ void gemm_qkp(const float* __restrict__ W) { gemm_body<NTOK_P, 2*PD, PD>(g_fl, W, g_qkp); }
__global__ void gemm_pv (const float* __restrict__ W) { gemm_body<NTOK_P, PD,   PD>(g_fl, W, g_pv);  }
__global__ void gemm_pfo(const float* __restrict__ W) { gemm_body<NTOK_P, PD,   PD>(g_pf, W, g_pfo); }
__global__ void gemm_qkw(const float* __restrict__ W) { gemm_body<NTOK_W, 2*WIN_INNER, PLD>(g_plln, W, g_qkw); }
__global__ void gemm_wv (const float* __restrict__ W) { gemm_body<NTOK_W, WIN_INNER, WD>(g_lnxw, W, g_wv); }
__global__ void gemm_wfo(const float* __restrict__ W) { gemm_body<NTOK_W, WD, WIN_INNER>(g_wf, W, g_wfo); }

// ---------------------------------------------------------------------------
// kA: gather patch token + LayerNorm -> g_fl
// One block per patch token (16384 blocks x 256 threads, 4 dims/thread).
// ---------------------------------------------------------------------------
__global__ void kA_fl(const float* __restrict__ x,
                      const float* __restrict__ gam, const float* __restrict__ bet) {
    int t = blockIdx.x;                  // (b*16+w)*16+p
    int b = t >> 8, w = (t >> 4) & 15, p = t & 15;
    int wy = w >> 2, wx = w & 3, py = p >> 2, px = p & 3;
    int i0 = wy * WS + py * PS, j0 = wx * WS + px * PS;
    __shared__ float red[32];
    float vals[4], s = 0.f, s2 = 0.f;
    #pragma unroll
    for (int r = 0; r < 4; r++) {
        int d = threadIdx.x + r * 256;
        int sidx = d >> 4, c = d & 15;
        int sy = sidx >> 3, sx = sidx & 7;
        float v = x[(((size_t)b * CCH + c) * SZ + (i0 + sy)) * SZ + (j0 + sx)];
        vals[r] = v; s += v; s2 += v * v;
    }
    s  = blockReduceSum(s,  red);
    s2 = blockReduceSum(s2, red);
    float m  = s  * (1.f / PD);
    float rs = rsqrtf(s2 * (1.f / PD) - m * m + 1e-5f);
    #pragma unroll
    for (int r = 0; r < 4; r++) {
        int d = threadIdx.x + r * 256;
        g_fl[(size_t)t * PD + d] = (vals[r] - m) * rs * gam[d] + bet[d];
    }
}

// ---------------------------------------------------------------------------
// kB: patch attention + LePE conv, per (b,win,head). 8192 blocks x 256.
// ---------------------------------------------------------------------------
__global__ void kB_pattn(const float* __restrict__ cw, const float* __restrict__ cb) {
    int bid = blockIdx.x;
    int h = bid & 7;
    size_t tb = (size_t)(bid >> 3) * NPAT;   // token base (b*16+w)*16
    __shared__ float qs[NPAT][129], ks[NPAT][129], S[NPAT][NPAT];
    int tid = threadIdx.x;
    #pragma unroll
    for (int r = 0; r < 8; r++) {
        int idx = tid + r * 256;             // 2048
        int p = idx >> 7, d = idx & 127;
        qs[p][d] = g_qkp[(tb + p) * (2 * PD) + h * PDH + d];
        ks[p][d] = g_qkp[(tb + p) * (2 * PD) + PD + h * PDH + d];
    }
    __syncthreads();
    {
        int p = tid >> 4, v = tid & 15;
        float acc = 0.f;
        #pragma unroll 8
        for (int d = 0; d < PDH; d++) acc += qs[p][d] * ks[v][d];
        S[p][v] = acc * ATT_SCALE;
    }
    __syncthreads();
    if (tid < NPAT) {
        float mx = -1e30f;
        #pragma unroll
        for (int v = 0; v < NPAT; v++) mx = fmaxf(mx, S[tid][v]);
        float e[NPAT], sum = 0.f;
        #pragma unroll
        for (int v = 0; v < NPAT; v++) { e[v] = __expf(S[tid][v] - mx); sum += e[v]; }
        float inv = 1.f / sum;
        #pragma unroll
        for (int v = 0; v < NPAT; v++) S[tid][v] = e[v] * inv;
    }
    __syncthreads();
    // reuse ks[] as V
    #pragma unroll
    for (int r = 0; r < 8; r++) {
        int idx = tid + r * 256;
        int p = idx >> 7, d = idx & 127;
        ks[p][d] = g_pv[(tb + p) * PD + h * PDH + d];
    }
    __syncthreads();
    #pragma unroll
    for (int r = 0; r < 8; r++) {
        int idx = tid + r * 256;
        int p = idx >> 7, d = idx & 127;
        float acc = 0.f;
        #pragma unroll
        for (int v = 0; v < NPAT; v++) acc += S[p][v] * ks[v][d];
        int py = p >> 2, px = p & 3;
        #pragma unroll
        for (int ky = 0; ky < 3; ky++) {
            int yy = py + ky - 1;
            if (yy < 0 || yy > 3) continue;
            #pragma unroll
            for (int kx = 0; kx < 3; kx++) {
                int xx = px + kx - 1;
                if (xx < 0 || xx > 3) continue;
                acc += cw[d * 9 + ky * 3 + kx] * ks[yy * 4 + xx][d];
            }
        }
        acc += cb[d];
        g_pf[(tb + p) * PD + h * PDH + d] = acc;
    }
}

// ---------------------------------------------------------------------------
// kC: 4x4 average pool + window-token gather + LayerNorm -> g_plln
// One block per window token (1024 blocks x 256).
// ---------------------------------------------------------------------------
__global__ void kC_pl(const float* __restrict__ x,
                      const float* __restrict__ gam, const float* __restrict__ bet) {
    int t = blockIdx.x;                  // b*16+w
    int b = t >> 4, w = t & 15, wy = w >> 2, wx = w & 3;
    __shared__ float red[32];
    float vals[4], s = 0.f, s2 = 0.f;
    #pragma unroll
    for (int r = 0; r < 4; r++) {
        int d = threadIdx.x + r * 256;
        int uy = (d >> 4) >> 3, ux = (d >> 4) & 7, c = d & 15;
        int i0 = wy * WS + uy * 4, j0 = wx * WS + ux * 4;
        const float* xb = x + (((size_t)b * CCH + c) * SZ + i0) * SZ + j0;
        float acc = 0.f;
        #pragma unroll
        for (int a = 0; a < 4; a++)
            #pragma unroll
            for (int e = 0; e < 4; e++) acc += xb[a * SZ + e];
        float v = acc * (1.f / 16.f);
        vals[r] = v; s += v; s2 += v * v;
    }
    s  = blockReduceSum(s,  red);
    s2 = blockReduceSum(s2, red);
    float m  = s  * (1.f / PLD);
    float rs = rsqrtf(s2 * (1.f / PLD) - m * m + 1e-5f);
    #pragma unroll
    for (int r = 0; r < 4; r++) {
        int d = threadIdx.x + r * 256;
        g_plln[(size_t)t * PLD + d] = (vals[r] - m) * rs * gam[d] + bet[d];
    }
}

// ---------------------------------------------------------------------------
// kD: window attention scores + diag/non-diag rescale -> g_nds, g_ds
// One block per (b,head). 512 blocks x 256.
// ---------------------------------------------------------------------------
__global__ void kD_wscores() {
    int bid = blockIdx.x;                // b*8+h
    int h = bid & 7, b = bid >> 3;
    __shared__ float qs[NWIN][129], ks[NWIN][129], S[NWIN][NWIN];
    int tid = threadIdx.x;
    #pragma unroll
    for (int r = 0; r < 8; r++) {
        int idx = tid + r * 256;
        int n = idx >> 7, d = idx & 127;
        qs[n][d] = g_qkw[((size_t)b * NWIN + n) * (2 * WIN_INNER) + h * WDH + d];
        ks[n][d] = g_qkw[((size_t)b * NWIN + n) * (2 * WIN_INNER) + WIN_INNER + h * WDH + d];
    }
    __syncthreads();
    int n = tid >> 4, m = tid & 15;
    {
        float acc = 0.f;
        #pragma unroll 8
        for (int d = 0; d < WDH; d++) acc += qs[n][d] * ks[m][d];
        S[n][m] = acc * ATT_SCALE;
    }
    __syncthreads();
    if (tid < NWIN) {
        float mx = -1e30f;
        #pragma unroll
        for (int v = 0; v < NWIN; v++) mx = fmaxf(mx, S[tid][v]);
        float e[NWIN], sum = 0.f;
        #pragma unroll
        for (int v = 0; v < NWIN; v++) { e[v] = __expf(S[tid][v] - mx); sum += e[v]; }
        float inv = 1.f / sum;
        #pragma unroll
        for (int v = 0; v < NWIN; v++) S[tid][v] = e[v] * inv;
    }
    __syncthreads();
    float dn = S[n][n];
    bool line = dn < 0.5f;
    if (m == 0) g_ds[((size_t)b * NH + h) * NWIN + n] = line ? 0.5f : dn;
    float val = (m == n) ? 0.f : S[n][m];
    if (line) val *= 0.5f / (1.f - dn);
    g_nds[(((size_t)b * NH + h) * NWIN + n) * NWIN + m] = val;
}

// ---------------------------------------------------------------------------
// kE: window-pixel gather + LayerNorm over WD=16384 -> g_lnxw (two-pass)
// One block per window token. 1024 blocks x 256.
// ---------------------------------------------------------------------------
__global__ void kE_lnxw(const float* __restrict__ x,
                        const float* __restrict__ gam, const float* __restrict__ bet) {
    int t = blockIdx.x;
    int b = t >> 4, w = t & 15, wy = w >> 2, wx = w & 3;
    __shared__ float red[32];
    float s = 0.f, s2 = 0.f;
    for (int r = 0; r < 64; r++) {
        int d = threadIdx.x + r * 256;
        int sidx = d >> 4, c = d & 15;
        int sy = sidx >> 5, sx = sidx & 31;
        float v = x[(((size_t)b * CCH + c) * SZ + (wy * WS + sy)) * SZ + (wx * WS + sx)];
        s += v; s2 += v * v;
    }
    s  = blockReduceSum(s,  red);
    s2 = blockReduceSum(s2, red);
    float m  = s  * (1.f / WD);
    float rs = rsqrtf(s2 * (1.f / WD) - m * m + 1e-5f);
    for (int r = 0; r < 64; r++) {
        int d = threadIdx.x + r * 256;
        int sidx = d >> 4, c = d & 15;
        int sy = sidx >> 5, sx = sidx & 31;
        float v = x[(((size_t)b * CCH + c) * SZ + (wy * WS + sy)) * SZ + (wx * WS + sx)];
        g_lnxw[(size_t)t * WD + d] = (v - m) * rs * gam[d] + bet[d];
    }
}

// ---------------------------------------------------------------------------
// kF: window value mixing with nds + LePE conv -> g_wf
// One block per (b,head). 512 blocks x 256.
// ---------------------------------------------------------------------------
__global__ void kF_wattn(const float* __restrict__ cw, const float* __restrict__ cb) {
    int bid = blockIdx.x;                // b*8+h
    int h = bid & 7, b = bid >> 3;
    __shared__ float vs[NWIN][129], P[NWIN][NWIN];
    int tid = threadIdx.x;
    #pragma unroll
    for (int r = 0; r < 8; r++) {
        int idx = tid + r * 256;
        int n = idx >> 7, d = idx & 127;
        vs[n][d] = g_wv[((size_t)b * NWIN + n) * WIN_INNER + h * WDH + d];
    }
    {
        int n = tid >> 4, m = tid & 15;
        P[n][m] = g_nds[(((size_t)b * NH + h) * NWIN + n) * NWIN + m];
    }
    __syncthreads();
    #pragma unroll
    for (int r = 0; r < 8; r++) {
        int idx = tid + r * 256;
        int n = idx >> 7, d = idx & 127;
        float acc = 0.f;
        #pragma unroll
        for (int m = 0; m < NWIN; m++) acc += P[n][m] * vs[m][d];
        int wyy = n >> 2, wxx = n & 3;
        #pragma unroll
        for (int ky = 0; ky < 3; ky++) {
            int yy = wyy + ky - 1;
            if (yy < 0 || yy > 3) continue;
            #pragma unroll
            for (int kx = 0; kx < 3; kx++) {
                int xx = wxx + kx - 1;
                if (xx < 0 || xx > 3) continue;
                acc += cw[d * 9 + ky * 3 + kx] * vs[yy * 4 + xx][d];
            }
        }
        acc += cb[d];
        g_wf[((size_t)b * NWIN + n) * WIN_INNER + h * WDH + d] = acc;
    }
}

// ---------------------------------------------------------------------------
// kG: out = ds*pfo + wfo scattered back to image layout + residual x
// ---------------------------------------------------------------------------
__global__ void kG_out(const float* __restrict__ x, float* __restrict__ out) {
    size_t idx = (size_t)blockIdx.x * blockDim.x + threadIdx.x;
    if (idx >= (size_t)BATCH * CCH * SZ * SZ) return;
    int j = idx & 127;
    int i = (idx >> 7) & 127;
    int c = (idx >> 14) & 15;
    int b = (int)(idx >> 18);
    int wy = i >> 5, sy = i & 31, wx = j >> 5, sx = j & 31;
    int n = wy * 4 + wx;
    int wd = ((sy << 5) + sx) * 16 + c;      // linear WD index in pixel layout
    int h = wd >> 11;                         // WD/H = 2048 per head
    size_t base = ((size_t)b * NWIN + n) * WD + wd;
    float v = g_ds[((size_t)b * NH + h) * NWIN + n] * g_pfo[base] + g_wfo[base] + x[idx];
    out[idx] = v;
}

// ---------------------------------------------------------------------------
// Launch
// ---------------------------------------------------------------------------
extern "C" void kernel_launch(void* const* d_in, const int* in_sizes, int n_in,
                              void* d_out, int out_size) {
    const float* x       = (const float*)d_in[0];
    const float* pn_g    = (const float*)d_in[1];
    const float* pn_b    = (const float*)d_in[2];
    const float* Wqk_p   = (const float*)d_in[3];
    const float* Wv_p    = (const float*)d_in[4];
    const float* conv_pw = (const float*)d_in[5];
    const float* conv_pb = (const float*)d_in[6];
    const float* Wout_p  = (const float*)d_in[7];
    const float* pln_g   = (const float*)d_in[8];
    const float* pln_b   = (const float*)d_in[9];
    const float* Wqk_w   = (const float*)d_in[10];
    const float* wn_g    = (const float*)d_in[11];
    const float* wn_b    = (const float*)d_in[12];
    const float* Wv_w    = (const float*)d_in[13];
    const float* conv_ww = (const float*)d_in[14];
    const float* conv_wb = (const float*)d_in[15];
    const float* Wout_w  = (const float*)d_in[16];
    float* out = (float*)d_out;

    // --- patch branch ---
    kA_fl<<<NTOK_P, 256>>>(x, pn_g, pn_b);
    gemm_qkp<<<dim3((2*PD)/128, NTOK_P/128), 256>>>(Wqk_p);
    gemm_pv <<<dim3(PD/128,     NTOK_P/128), 256>>>(Wv_p);
    kB_pattn<<<BATCH*NWIN*NH, 256>>>(conv_pw, conv_pb);
    gemm_pfo<<<dim3(PD/128,     NTOK_P/128), 256>>>(Wout_p);

    // --- window branch ---
    kC_pl<<<NTOK_W, 256>>>(x, pln_g, pln_b);
    gemm_qkw<<<dim3((2*WIN_INNER)/128, NTOK_W/128), 256>>>(Wqk_w);
    kD_wscores<<<BATCH*NH, 256>>>();
    kE_lnxw<<<NTOK_W, 256>>>(x, wn_g, wn_b);
    gemm_wv <<<dim3(WIN_INNER/128, NTOK_W/128), 256>>>(Wv_w);
    kF_wattn<<<BATCH*NH, 256>>>(conv_ww, conv_wb);
    gemm_wfo<<<dim3(WD/128, NTOK_W/128), 256>>>(Wout_w);

    // --- combine + residual ---
    size_t total = (size_t)BATCH * CCH * SZ * SZ;
    kG_out<<<(unsigned)((total + 255) / 256), 256>>>(x, out);
}

// round 2
// speedup vs baseline: 1.9174x; 1.9174x over previous
#include <cuda_runtime.h>
#include <cuda_bf16.h>
#include <cstdint>

// ---------------------------------------------------------------------------
// Problem dims (compile-time)
// ---------------------------------------------------------------------------
#define BATCH 64
#define CCH   16
#define SZ    128
#define WS    32
#define PS    8
#define NH    8
#define WN    4
#define PPW   4
#define NWIN  16
#define NPAT  16
#define PD    1024
#define PDH   128
#define PLD   1024
#define WDH   128
#define WIN_INNER 1024
#define WD    16384
#define NTOK_P (BATCH*NWIN*NPAT)   // 16384
#define NTOK_W (BATCH*NWIN)        // 1024
#define ATT_SCALE 0.08838834764831845f

#define WV_SPLITK 8

// ---------------------------------------------------------------------------
// Scratch (device globals)
// ---------------------------------------------------------------------------
__device__ float g_fl  [(size_t)NTOK_P * PD];
__device__ float g_qkp [(size_t)NTOK_P * 2 * PD];
__device__ float g_pv  [(size_t)NTOK_P * PD];
__device__ float g_pf  [(size_t)NTOK_P * PD];
__device__ float g_pfo [(size_t)NTOK_P * PD];
__device__ float g_plln[(size_t)NTOK_W * PLD];
__device__ float g_qkw [(size_t)NTOK_W * 2 * WIN_INNER];
__device__ float g_nds [(size_t)BATCH * NH * NWIN * NWIN];
__device__ float g_ds  [(size_t)BATCH * NH * NWIN];
__device__ float g_lnxw[(size_t)NTOK_W * WD];
__device__ float g_wv  [(size_t)NTOK_W * WIN_INNER];
__device__ float g_wv_part[(size_t)WV_SPLITK * NTOK_W * WIN_INNER];
__device__ float g_wf  [(size_t)NTOK_W * WIN_INNER];
__device__ float g_wfo [(size_t)NTOK_W * WD];

// ---------------------------------------------------------------------------
// MMA helpers
// ---------------------------------------------------------------------------
__device__ __forceinline__ void ldsm4(uint32_t& r0, uint32_t& r1, uint32_t& r2,
                                      uint32_t& r3, const void* p) {
    uint32_t a = (uint32_t)__cvta_generic_to_shared(p);
    asm volatile("ldmatrix.sync.aligned.m8n8.x4.shared.b16 {%0,%1,%2,%3}, [%4];"
                 : "=r"(r0), "=r"(r1), "=r"(r2), "=r"(r3) : "r"(a));
}
__device__ __forceinline__ void ldsm4t(uint32_t& r0, uint32_t& r1, uint32_t& r2,
                                       uint32_t& r3, const void* p) {
    uint32_t a = (uint32_t)__cvta_generic_to_shared(p);
    asm volatile("ldmatrix.sync.aligned.m8n8.x4.trans.shared.b16 {%0,%1,%2,%3}, [%4];"
                 : "=r"(r0), "=r"(r1), "=r"(r2), "=r"(r3) : "r"(a));
}
__device__ __forceinline__ void mma_bf16(float* c, const uint32_t* a, uint32_t b0, uint32_t b1) {
    asm volatile(
        "mma.sync.aligned.m16n8k16.row.col.f32.bf16.bf16.f32 "
        "{%0,%1,%2,%3},{%4,%5,%6,%7},{%8,%9},{%0,%1,%2,%3};"
        : "+f"(c[0]), "+f"(c[1]), "+f"(c[2]), "+f"(c[3])
        : "r"(a[0]), "r"(a[1]), "r"(a[2]), "r"(a[3]), "r"(b0), "r"(b1));
}

// ---------------------------------------------------------------------------
// Split-bf16 tensor-core GEMM: C[M,N] = A[M,K] @ B[K,N] (row-major fp32).
// 128x128x32 tile, 256 threads, 8 warps (2x4), warp tile 64x32.
// fp32 -> (hi,lo) bf16 split; hi*hi + hi*lo + lo*hi (fp32 accum).
// SPLITK>1: blockIdx.z selects a K chunk of length KC, writes C + z*M*N.
// ---------------------------------------------------------------------------
template<int M, int N, int K, int KC>
__device__ __forceinline__ void gemm_mma_body(const float* __restrict__ A,
                                              const float* __restrict__ B,
                                              float* __restrict__ Cbase) {
    constexpr int BM = 128, BN = 128, BK = 32;
    constexpr int APAD = 8, BPAD = 8;
    __shared__ __nv_bfloat16 Ahi[BM][BK + APAD];
    __shared__ __nv_bfloat16 Alo[BM][BK + APAD];
    __shared__ __nv_bfloat16 Bhi[BK][BN + BPAD];
    __shared__ __nv_bfloat16 Blo[BK][BN + BPAD];

    const int tid  = threadIdx.x;
    const int lane = tid & 31;
    const int wid  = tid >> 5;
    const int wm   = wid & 1;          // 2 row groups (64 rows each)
    const int wn   = wid >> 1;         // 4 col groups (32 cols each)
    const size_t m0 = (size_t)blockIdx.y * BM;
    const size_t n0 = (size_t)blockIdx.x * BN;
    const int kc0 = blockIdx.z * KC;
    float* __restrict__ C = Cbase + (size_t)blockIdx.z * M * N;

    float acc[4][4][4];
    #pragma unroll
    for (int i = 0; i < 4; i++)
        #pragma unroll
        for (int j = 0; j < 4; j++)
            #pragma unroll
            for (int e = 0; e < 4; e++) acc[i][j][e] = 0.f;

    const int ar  = lane & 15;
    const int ac8 = (lane >> 4) << 3;

    for (int k0 = kc0; k0 < kc0 + KC; k0 += BK) {
        // stage A tile: 128x32 fp32 -> hi/lo bf16
        #pragma unroll
        for (int q = tid; q < (BM * BK) / 4; q += 256) {
            int row = q >> 3, col = (q & 7) << 2;
            float4 v = *(const float4*)(A + (m0 + row) * K + k0 + col);
            float f[4] = {v.x, v.y, v.z, v.w};
            #pragma unroll
            for (int e = 0; e < 4; e++) {
                __nv_bfloat16 h = __float2bfloat16(f[e]);
                Ahi[row][col + e] = h;
                Alo[row][col + e] = __float2bfloat16(f[e] - __bfloat162float(h));
            }
        }
        // stage B tile: 32x128
        #pragma unroll
        for (int q = tid; q < (BK * BN) / 4; q += 256) {
            int row = q >> 5, col = (q & 31) << 2;
            float4 v = *(const float4*)(B + (size_t)(k0 + row) * N + n0 + col);
            float f[4] = {v.x, v.y, v.z, v.w};
            #pragma unroll
            for (int e = 0; e < 4; e++) {
                __nv_bfloat16 h = __float2bfloat16(f[e]);
                Bhi[row][col + e] = h;
                Blo[row][col + e] = __float2bfloat16(f[e] - __bfloat162float(h));
            }
        }
        __syncthreads();

        #pragma unroll
        for (int kk = 0; kk < 2; kk++) {      // two k16 steps
            uint32_t ah[4][4], al[4][4], bh[2][4], bl[2][4];
            #pragma unroll
            for (int mi = 0; mi < 4; mi++) {
                ldsm4(ah[mi][0], ah[mi][1], ah[mi][2], ah[mi][3],
                      &Ahi[wm * 64 + mi * 16 + ar][kk * 16 + ac8]);
                ldsm4(al[mi][0], al[mi][1], al[mi][2], al[mi][3],
                      &Alo[wm * 64 + mi * 16 + ar][kk * 16 + ac8]);
            }
            #pragma unroll
            for (int ni = 0; ni < 2; ni++) {
                ldsm4t(bh[ni][0], bh[ni][1], bh[ni][2], bh[ni][3],
                       &Bhi[kk * 16 + ar][wn * 32 + ni * 16 + ac8]);
                ldsm4t(bl[ni][0], bl[ni][1], bl[ni][2], bl[ni][3],
                       &Blo[kk * 16 + ar][wn * 32 + ni * 16 + ac8]);
            }
            #pragma unroll
            for (int mi = 0; mi < 4; mi++)
                #pragma unroll
                for (int nj = 0; nj < 4; nj++) {
                    int ni = nj >> 1, pr = (nj & 1) << 1;
                    mma_bf16(acc[mi][nj], ah[mi], bh[ni][pr], bh[ni][pr + 1]);
                    mma_bf16(acc[mi][nj], ah[mi], bl[ni][pr], bl[ni][pr + 1]);
                    mma_bf16(acc[mi][nj], al[mi], bh[ni][pr], bh[ni][pr + 1]);
                }
        }
        __syncthreads();
    }

    const int gid = lane >> 2, tig = lane & 3;
    #pragma unroll
    for (int mi = 0; mi < 4; mi++) {
        size_t r0 = m0 + wm * 64 + mi * 16 + gid;
        #pragma unroll
        for (int nj = 0; nj < 4; nj++) {
            size_t cc = n0 + wn * 32 + nj * 8 + tig * 2;
            *(float2*)(C + r0 * N + cc)       = make_float2(acc[mi][nj][0], acc[mi][nj][1]);
            *(float2*)(C + (r0 + 8) * N + cc) = make_float2(acc[mi][nj][2], acc[mi][nj][3]);
        }
    }
}

__global__ void __launch_bounds__(256) mm_qkp(const float* __restrict__ W) {
    gemm_mma_body<NTOK_P, 2*PD, PD, PD>(g_fl, W, g_qkp);
}
__global__ void __launch_bounds__(256) mm_pv(const float* __restrict__ W) {
    gemm_mma_body<NTOK_P, PD, PD, PD>(g_fl, W, g_pv);
}
__global__ void __launch_bounds__(256) mm_pfo(const float* __restrict__ W) {
    gemm_mma_body<NTOK_P, PD, PD, PD>(g_pf, W, g_pfo);
}
__global__ void __launch_bounds__(256) mm_qkw(const float* __restrict__ W) {
    gemm_mma_body<NTOK_W, 2*WIN_INNER, PLD, PLD>(g_plln, W, g_qkw);
}
__global__ void __launch_bounds__(256) mm_wv(const float* __restrict__ W) {
    gemm_mma_body<NTOK_W, WIN_INNER, WD, WD / WV_SPLITK>(g_lnxw, W, g_wv_part);
}
__global__ void __launch_bounds__(256) mm_wfo(const float* __restrict__ W) {
    gemm_mma_body<NTOK_W, WD, WIN_INNER, WIN_INNER>(g_wf, W, g_wfo);
}

// split-K reduction for wv (deterministic)
__global__ void kR_wv() {
    size_t i = (size_t)blockIdx.x * blockDim.x + threadIdx.x;
    if (i >= (size_t)NTOK_W * WIN_INNER) return;
    float s = 0.f;
    #pragma unroll
    for (int z = 0; z < WV_SPLITK; z++)
        s += g_wv_part[(size_t)z * NTOK_W * WIN_INNER + i];
    g_wv[i] = s;
}

// ---------------------------------------------------------------------------
// Block reduce
// ---------------------------------------------------------------------------
__device__ __forceinline__ float blockReduceSum(float v, float* sh) {
    int lane = threadIdx.x & 31, wid = threadIdx.x >> 5;
    #pragma unroll
    for (int o = 16; o > 0; o >>= 1) v += __shfl_down_sync(0xffffffffu, v, o);
    if (lane == 0) sh[wid] = v;
    __syncthreads();
    int nw = blockDim.x >> 5;
    v = (threadIdx.x < (unsigned)nw) ? sh[threadIdx.x] : 0.f;
    if (wid == 0) {
        #pragma unroll
        for (int o = 16; o > 0; o >>= 1) v += __shfl_down_sync(0xffffffffu, v, o);
        if (lane == 0) sh[0] = v;
    }
    __syncthreads();
    float r = sh[0];
    __syncthreads();
    return r;
}

// ---------------------------------------------------------------------------
// kA: gather patch token + LayerNorm -> g_fl
// ---------------------------------------------------------------------------
__global__ void kA_fl(const float* __restrict__ x,
                      const float* __restrict__ gam, const float* __restrict__ bet) {
    int t = blockIdx.x;
    int b = t >> 8, w = (t >> 4) & 15, p = t & 15;
    int wy = w >> 2, wx = w & 3, py = p >> 2, px = p & 3;
    int i0 = wy * WS + py * PS, j0 = wx * WS + px * PS;
    __shared__ float red[32];
    float vals[4], s = 0.f, s2 = 0.f;
    #pragma unroll
    for (int r = 0; r < 4; r++) {
        int d = threadIdx.x + r * 256;
        int sidx = d >> 4, c = d & 15;
        int sy = sidx >> 3, sx = sidx & 7;
        float v = x[(((size_t)b * CCH + c) * SZ + (i0 + sy)) * SZ + (j0 + sx)];
        vals[r] = v; s += v; s2 += v * v;
    }
    s  = blockReduceSum(s,  red);
    s2 = blockReduceSum(s2, red);
    float m  = s  * (1.f / PD);
    float rs = rsqrtf(s2 * (1.f / PD) - m * m + 1e-5f);
    #pragma unroll
    for (int r = 0; r < 4; r++) {
        int d = threadIdx.x + r * 256;
        g_fl[(size_t)t * PD + d] = (vals[r] - m) * rs * gam[d] + bet[d];
    }
}

// ---------------------------------------------------------------------------
// kB: patch attention + LePE conv, per (b,win,head)
// ---------------------------------------------------------------------------
__global__ void kB_pattn(const float* __restrict__ cw, const float* __restrict__ cb) {
    int bid = blockIdx.x;
    int h = bid & 7;
    size_t tb = (size_t)(bid >> 3) * NPAT;
    __shared__ float qs[NPAT][129], ks[NPAT][129], S[NPAT][NPAT];
    int tid = threadIdx.x;
    #pragma unroll
    for (int r = 0; r < 8; r++) {
        int idx = tid + r * 256;
        int p = idx >> 7, d = idx & 127;
        qs[p][d] = g_qkp[(tb + p) * (2 * PD) + h * PDH + d];
        ks[p][d] = g_qkp[(tb + p) * (2 * PD) + PD + h * PDH + d];
    }
    __syncthreads();
    {
        int p = tid >> 4, v = tid & 15;
        float acc = 0.f;
        #pragma unroll 8
        for (int d = 0; d < PDH; d++) acc += qs[p][d] * ks[v][d];
        S[p][v] = acc * ATT_SCALE;
    }
    __syncthreads();
    if (tid < NPAT) {
        float mx = -1e30f;
        #pragma unroll
        for (int v = 0; v < NPAT; v++) mx = fmaxf(mx, S[tid][v]);
        float e[NPAT], sum = 0.f;
        #pragma unroll
        for (int v = 0; v < NPAT; v++) { e[v] = __expf(S[tid][v] - mx); sum += e[v]; }
        float inv = 1.f / sum;
        #pragma unroll
        for (int v = 0; v < NPAT; v++) S[tid][v] = e[v] * inv;
    }
    __syncthreads();
    #pragma unroll
    for (int r = 0; r < 8; r++) {
        int idx = tid + r * 256;
        int p = idx >> 7, d = idx & 127;
        ks[p][d] = g_pv[(tb + p) * PD + h * PDH + d];
    }
    __syncthreads();
    #pragma unroll
    for (int r = 0; r < 8; r++) {
        int idx = tid + r * 256;
        int p = idx >> 7, d = idx & 127;
        float acc = 0.f;
        #pragma unroll
        for (int v = 0; v < NPAT; v++) acc += S[p][v] * ks[v][d];
        int py = p >> 2, px = p & 3;
        #pragma unroll
        for (int ky = 0; ky < 3; ky++) {
            int yy = py + ky - 1;
            if (yy < 0 || yy > 3) continue;
            #pragma unroll
            for (int kx = 0; kx < 3; kx++) {
                int xx = px + kx - 1;
                if (xx < 0 || xx > 3) continue;
                acc += cw[d * 9 + ky * 3 + kx] * ks[yy * 4 + xx][d];
            }
        }
        acc += cb[d];
        g_pf[(tb + p) * PD + h * PDH + d] = acc;
    }
}

// ---------------------------------------------------------------------------
// kC: 4x4 average pool + gather + LayerNorm -> g_plln
// ---------------------------------------------------------------------------
__global__ void kC_pl(const float* __restrict__ x,
                      const float* __restrict__ gam, const float* __restrict__ bet) {
    int t = blockIdx.x;
    int b = t >> 4, w = t & 15, wy = w >> 2, wx = w & 3;
    __shared__ float red[32];
    float vals[4], s = 0.f, s2 = 0.f;
    #pragma unroll
    for (int r = 0; r < 4; r++) {
        int d = threadIdx.x + r * 256;
        int uy = (d >> 4) >> 3, ux = (d >> 4) & 7, c = d & 15;
        int i0 = wy * WS + uy * 4, j0 = wx * WS + ux * 4;
        const float* xb = x + (((size_t)b * CCH + c) * SZ + i0) * SZ + j0;
        float acc = 0.f;
        #pragma unroll
        for (int a = 0; a < 4; a++)
            #pragma unroll
            for (int e = 0; e < 4; e++) acc += xb[a * SZ + e];
        float v = acc * (1.f / 16.f);
        vals[r] = v; s += v; s2 += v * v;
    }
    s  = blockReduceSum(s,  red);
    s2 = blockReduceSum(s2, red);
    float m  = s  * (1.f / PLD);
    float rs = rsqrtf(s2 * (1.f / PLD) - m * m + 1e-5f);
    #pragma unroll
    for (int r = 0; r < 4; r++) {
        int d = threadIdx.x + r * 256;
        g_plln[(size_t)t * PLD + d] = (vals[r] - m) * rs * gam[d] + bet[d];
    }
}

// ---------------------------------------------------------------------------
// kD: window attention scores + diag/non-diag rescale
// ---------------------------------------------------------------------------
__global__ void kD_wscores() {
    int bid = blockIdx.x;
    int h = bid & 7, b = bid >> 3;
    __shared__ float qs[NWIN][129], ks[NWIN][129], S[NWIN][NWIN];
    int tid = threadIdx.x;
    #pragma unroll
    for (int r = 0; r < 8; r++) {
        int idx = tid + r * 256;
        int n = idx >> 7, d = idx & 127;
        qs[n][d] = g_qkw[((size_t)b * NWIN + n) * (2 * WIN_INNER) + h * WDH + d];
        ks[n][d] = g_qkw[((size_t)b * NWIN + n) * (2 * WIN_INNER) + WIN_INNER + h * WDH + d];
    }
    __syncthreads();
    int n = tid >> 4, m = tid & 15;
    {
        float acc = 0.f;
        #pragma unroll 8
        for (int d = 0; d < WDH; d++) acc += qs[n][d] * ks[m][d];
        S[n][m] = acc * ATT_SCALE;
    }
    __syncthreads();
    if (tid < NWIN) {
        float mx = -1e30f;
        #pragma unroll
        for (int v = 0; v < NWIN; v++) mx = fmaxf(mx, S[tid][v]);
        float e[NWIN], sum = 0.f;
        #pragma unroll
        for (int v = 0; v < NWIN; v++) { e[v] = __expf(S[tid][v] - mx); sum += e[v]; }
        float inv = 1.f / sum;
        #pragma unroll
        for (int v = 0; v < NWIN; v++) S[tid][v] = e[v] * inv;
    }
    __syncthreads();
    float dn = S[n][n];
    bool line = dn < 0.5f;
    if (m == 0) g_ds[((size_t)b * NH + h) * NWIN + n] = line ? 0.5f : dn;
    float val = (m == n) ? 0.f : S[n][m];
    if (line) val *= 0.5f / (1.f - dn);
    g_nds[(((size_t)b * NH + h) * NWIN + n) * NWIN + m] = val;
}

// ---------------------------------------------------------------------------
// kE: window-pixel gather + LayerNorm over WD -> g_lnxw
// ---------------------------------------------------------------------------
__global__ void kE_lnxw(const float* __restrict__ x,
                        const float* __restrict__ gam, const float* __restrict__ bet) {
    int t = blockIdx.x;
    int b = t >> 4, w = t & 15, wy = w >> 2, wx = w & 3;
    __shared__ float red[32];
    float s = 0.f, s2 = 0.f;
    for (int r = 0; r < 64; r++) {
        int d = threadIdx.x + r * 256;
        int sidx = d >> 4, c = d & 15;
        int sy = sidx >> 5, sx = sidx & 31;
        float v = x[(((size_t)b * CCH + c) * SZ + (wy * WS + sy)) * SZ + (wx * WS + sx)];
        s += v; s2 += v * v;
    }
    s  = blockReduceSum(s,  red);
    s2 = blockReduceSum(s2, red);
    float m  = s  * (1.f / WD);
    float rs = rsqrtf(s2 * (1.f / WD) - m * m + 1e-5f);
    for (int r = 0; r < 64; r++) {
        int d = threadIdx.x + r * 256;
        int sidx = d >> 4, c = d & 15;
        int sy = sidx >> 5, sx = sidx & 31;
        float v = x[(((size_t)b * CCH + c) * SZ + (wy * WS + sy)) * SZ + (wx * WS + sx)];
        g_lnxw[(size_t)t * WD + d] = (v - m) * rs * gam[d] + bet[d];
    }
}

// ---------------------------------------------------------------------------
// kF: window value mixing with nds + LePE conv -> g_wf
// ---------------------------------------------------------------------------
__global__ void kF_wattn(const float* __restrict__ cw, const float* __restrict__ cb) {
    int bid = blockIdx.x;
    int h = bid & 7, b = bid >> 3;
    __shared__ float vs[NWIN][129], P[NWIN][NWIN];
    int tid = threadIdx.x;
    #pragma unroll
    for (int r = 0; r < 8; r++) {
        int idx = tid + r * 256;
        int n = idx >> 7, d = idx & 127;
        vs[n][d] = g_wv[((size_t)b * NWIN + n) * WIN_INNER + h * WDH + d];
    }
    {
        int n = tid >> 4, m = tid & 15;
        P[n][m] = g_nds[(((size_t)b * NH + h) * NWIN + n) * NWIN + m];
    }
    __syncthreads();
    #pragma unroll
    for (int r = 0; r < 8; r++) {
        int idx = tid + r * 256;
        int n = idx >> 7, d = idx & 127;
        float acc = 0.f;
        #pragma unroll
        for (int m = 0; m < NWIN; m++) acc += P[n][m] * vs[m][d];
        int wyy = n >> 2, wxx = n & 3;
        #pragma unroll
        for (int ky = 0; ky < 3; ky++) {
            int yy = wyy + ky - 1;
            if (yy < 0 || yy > 3) continue;
            #pragma unroll
            for (int kx = 0; kx < 3; kx++) {
                int xx = wxx + kx - 1;
                if (xx < 0 || xx > 3) continue;
                acc += cw[d * 9 + ky * 3 + kx] * vs[yy * 4 + xx][d];
            }
        }
        acc += cb[d];
        g_wf[((size_t)b * NWIN + n) * WIN_INNER + h * WDH + d] = acc;
    }
}

// ---------------------------------------------------------------------------
// kG: out = ds*pfo + wfo (scatter) + residual
// ---------------------------------------------------------------------------
__global__ void kG_out(const float* __restrict__ x, float* __restrict__ out) {
    size_t idx = (size_t)blockIdx.x * blockDim.x + threadIdx.x;
    if (idx >= (size_t)BATCH * CCH * SZ * SZ) return;
    int j = idx & 127;
    int i = (idx >> 7) & 127;
    int c = (idx >> 14) & 15;
    int b = (int)(idx >> 18);
    int wy = i >> 5, sy = i & 31, wx = j >> 5, sx = j & 31;
    int n = wy * 4 + wx;
    int wd = ((sy << 5) + sx) * 16 + c;
    int h = wd >> 11;
    size_t base = ((size_t)b * NWIN + n) * WD + wd;
    float v = g_ds[((size_t)b * NH + h) * NWIN + n] * g_pfo[base] + g_wfo[base] + x[idx];
    out[idx] = v;
}

// ---------------------------------------------------------------------------
// Launch
// ---------------------------------------------------------------------------
extern "C" void kernel_launch(void* const* d_in, const int* in_sizes, int n_in,
                              void* d_out, int out_size) {
    const float* x       = (const float*)d_in[0];
    const float* pn_g    = (const float*)d_in[1];
    const float* pn_b    = (const float*)d_in[2];
    const float* Wqk_p   = (const float*)d_in[3];
    const float* Wv_p    = (const float*)d_in[4];
    const float* conv_pw = (const float*)d_in[5];
    const float* conv_pb = (const float*)d_in[6];
    const float* Wout_p  = (const float*)d_in[7];
    const float* pln_g   = (const float*)d_in[8];
    const float* pln_b   = (const float*)d_in[9];
    const float* Wqk_w   = (const float*)d_in[10];
    const float* wn_g    = (const float*)d_in[11];
    const float* wn_b    = (const float*)d_in[12];
    const float* Wv_w    = (const float*)d_in[13];
    const float* conv_ww = (const float*)d_in[14];
    const float* conv_wb = (const float*)d_in[15];
    const float* Wout_w  = (const float*)d_in[16];
    float* out = (float*)d_out;

    // --- patch branch ---
    kA_fl<<<NTOK_P, 256>>>(x, pn_g, pn_b);
    mm_qkp<<<dim3((2*PD)/128, NTOK_P/128), 256>>>(Wqk_p);
    mm_pv <<<dim3(PD/128,     NTOK_P/128), 256>>>(Wv_p);
    kB_pattn<<<BATCH*NWIN*NH, 256>>>(conv_pw, conv_pb);
    mm_pfo<<<dim3(PD/128,     NTOK_P/128), 256>>>(Wout_p);

    // --- window branch ---
    kC_pl<<<NTOK_W, 256>>>(x, pln_g, pln_b);
    mm_qkw<<<dim3((2*WIN_INNER)/128, NTOK_W/128), 256>>>(Wqk_w);
    kD_wscores<<<BATCH*NH, 256>>>();
    kE_lnxw<<<NTOK_W, 256>>>(x, wn_g, wn_b);
    mm_wv <<<dim3(WIN_INNER/128, NTOK_W/128, WV_SPLITK), 256>>>(Wv_w);
    kR_wv<<<(NTOK_W * WIN_INNER + 255) / 256, 256>>>();
    kF_wattn<<<BATCH*NH, 256>>>(conv_ww, conv_wb);
    mm_wfo<<<dim3(WD/128, NTOK_W/128), 256>>>(Wout_w);

    // --- combine + residual ---
    size_t total = (size_t)BATCH * CCH * SZ * SZ;
    kG_out<<<(unsigned)((total + 255) / 256), 256>>>(x, out);
}

// round 7
// speedup vs baseline: 3.4991x; 1.8249x over previous
#include <cuda_runtime.h>
#include <cuda_bf16.h>
#include <cstdint>

// ---------------------------------------------------------------------------
// Problem dims (compile-time)
// ---------------------------------------------------------------------------
#define BATCH 64
#define CCH   16
#define SZ    128
#define WS    32
#define PS    8
#define NH    8
#define WN    4
#define PPW   4
#define NWIN  16
#define NPAT  16
#define PD    1024
#define PDH   128
#define PLD   1024
#define WDH   128
#define WIN_INNER 1024
#define WD    16384
#define NTOK_P (BATCH*NWIN*NPAT)   // 16384
#define NTOK_W (BATCH*NWIN)        // 1024
#define ATT_SCALE 0.08838834764831845f

#define WV_SPLITK 8

// ---------------------------------------------------------------------------
// Scratch (device globals) — EXACT R2 set (known delta=0)
// ---------------------------------------------------------------------------
__device__ float g_fl  [(size_t)NTOK_P * PD];
__device__ float g_qkp [(size_t)NTOK_P * 2 * PD];
__device__ float g_pv  [(size_t)NTOK_P * PD];
__device__ float g_pf  [(size_t)NTOK_P * PD];
__device__ float g_pfo [(size_t)NTOK_P * PD];
__device__ float g_plln[(size_t)NTOK_W * PLD];
__device__ float g_qkw [(size_t)NTOK_W * 2 * WIN_INNER];
__device__ float g_nds [(size_t)BATCH * NH * NWIN * NWIN];
__device__ float g_ds  [(size_t)BATCH * NH * NWIN];
__device__ float g_lnxw[(size_t)NTOK_W * WD];
__device__ float g_wv  [(size_t)NTOK_W * WIN_INNER];
__device__ float g_wv_part[(size_t)WV_SPLITK * NTOK_W * WIN_INNER];
__device__ float g_wf  [(size_t)NTOK_W * WIN_INNER];
__device__ float g_wfo [(size_t)NTOK_W * WD];

// ---------------------------------------------------------------------------
// MMA helpers (same as R2)
// ---------------------------------------------------------------------------
__device__ __forceinline__ void ldsm4(uint32_t& r0, uint32_t& r1, uint32_t& r2,
                                      uint32_t& r3, const void* p) {
    uint32_t a = (uint32_t)__cvta_generic_to_shared(p);
    asm volatile("ldmatrix.sync.aligned.m8n8.x4.shared.b16 {%0,%1,%2,%3}, [%4];"
                 : "=r"(r0), "=r"(r1), "=r"(r2), "=r"(r3) : "r"(a));
}
__device__ __forceinline__ void ldsm4t(uint32_t& r0, uint32_t& r1, uint32_t& r2,
                                       uint32_t& r3, const void* p) {
    uint32_t a = (uint32_t)__cvta_generic_to_shared(p);
    asm volatile("ldmatrix.sync.aligned.m8n8.x4.trans.shared.b16 {%0,%1,%2,%3}, [%4];"
                 : "=r"(r0), "=r"(r1), "=r"(r2), "=r"(r3) : "r"(a));
}
__device__ __forceinline__ void mma_bf16(float* c, const uint32_t* a, uint32_t b0, uint32_t b1) {
    asm volatile(
        "mma.sync.aligned.m16n8k16.row.col.f32.bf16.bf16.f32 "
        "{%0,%1,%2,%3},{%4,%5,%6,%7},{%8,%9},{%0,%1,%2,%3};"
        : "+f"(c[0]), "+f"(c[1]), "+f"(c[2]), "+f"(c[3])
        : "r"(a[0]), "r"(a[1]), "r"(a[2]), "r"(a[3]), "r"(b0), "r"(b1));
}

// fp32x4 -> packed bf16 hi-pair + lo-pair (truncation split).
// hi = top 16 bits of fp32 (PRMT packs two at once);
// lo = rn_bf16(f - hi_as_float), |lo| < 2^-8 |f| so total err ~2^-17.
__device__ __forceinline__ void cvt4(float4 v, uint2& h, uint2& l) {
    uint32_t b0 = __float_as_uint(v.x), b1 = __float_as_uint(v.y);
    uint32_t b2 = __float_as_uint(v.z), b3 = __float_as_uint(v.w);
    h.x = __byte_perm(b0, b1, 0x7632);
    h.y = __byte_perm(b2, b3, 0x7632);
    float r0 = v.x - __uint_as_float(b0 & 0xFFFF0000u);
    float r1 = v.y - __uint_as_float(b1 & 0xFFFF0000u);
    float r2 = v.z - __uint_as_float(b2 & 0xFFFF0000u);
    float r3 = v.w - __uint_as_float(b3 & 0xFFFF0000u);
    __nv_bfloat162 p0 = __floats2bfloat162_rn(r0, r1);
    __nv_bfloat162 p1 = __floats2bfloat162_rn(r2, r3);
    l.x = *reinterpret_cast<uint32_t*>(&p0);
    l.y = *reinterpret_cast<uint32_t*>(&p1);
}

// ---------------------------------------------------------------------------
// Split-bf16 tensor-core GEMM: C[M,N] = A[M,K] @ B[K,N], fp32 in/out.
// R2's exact shell (static smem, W by parameter, same launches); internal
// upgrades only: PRMT truncation split, 64-bit packed STS, register-prefetch
// pipelining of the next K-tile's global loads.
// ---------------------------------------------------------------------------
template<int M, int N, int K, int KC>
__device__ __forceinline__ void gemm_mma_body(const float* __restrict__ A,
                                              const float* __restrict__ B,
                                              float* __restrict__ Cbase) {
    constexpr int BM = 128, BN = 128, BK = 32;
    constexpr int APAD = 8, BPAD = 8;
    __shared__ __nv_bfloat16 Ahi[BM][BK + APAD];
    __shared__ __nv_bfloat16 Alo[BM][BK + APAD];
    __shared__ __nv_bfloat16 Bhi[BK][BN + BPAD];
    __shared__ __nv_bfloat16 Blo[BK][BN + BPAD];

    const int tid  = threadIdx.x;
    const int lane = tid & 31;
    const int wid  = tid >> 5;
    const int wm   = wid & 1;          // 2 row groups (64 rows each)
    const int wn   = wid >> 1;         // 4 col groups (32 cols each)
    const size_t m0 = (size_t)blockIdx.y * BM;
    const size_t n0 = (size_t)blockIdx.x * BN;
    const int kc0 = blockIdx.z * KC;
    float* __restrict__ C = Cbase + (size_t)blockIdx.z * M * N;

    const float* Ab = A + m0 * K;
    const float* Bb = B + n0;

    float acc[4][4][4];
    #pragma unroll
    for (int i = 0; i < 4; i++)
        #pragma unroll
        for (int j = 0; j < 4; j++)
            #pragma unroll
            for (int e = 0; e < 4; e++) acc[i][j][e] = 0.f;

    const int ar  = lane & 15;
    const int ac8 = (lane >> 4) << 3;
    const int nIter = KC / BK;

    // prologue: prefetch first K-tile into registers
    float4 pa[4], pb[4];
    #pragma unroll
    for (int i = 0; i < 4; i++) {
        int q = tid + 256 * i;
        int row = q >> 3, col = (q & 7) << 2;
        pa[i] = *(const float4*)(Ab + (size_t)row * K + kc0 + col);
    }
    #pragma unroll
    for (int i = 0; i < 4; i++) {
        int q = tid + 256 * i;
        int row = q >> 5, col = (q & 31) << 2;
        pb[i] = *(const float4*)(Bb + (size_t)(kc0 + row) * N + col);
    }

    for (int it = 0; it < nIter; ++it) {
        // stage current tile: convert + packed 64-bit stores
        #pragma unroll
        for (int i = 0; i < 4; i++) {
            int q = tid + 256 * i;
            int row = q >> 3, col = (q & 7) << 2;
            uint2 h, l;
            cvt4(pa[i], h, l);
            *(uint2*)&Ahi[row][col] = h;
            *(uint2*)&Alo[row][col] = l;
        }
        #pragma unroll
        for (int i = 0; i < 4; i++) {
            int q = tid + 256 * i;
            int row = q >> 5, col = (q & 31) << 2;
            uint2 h, l;
            cvt4(pb[i], h, l);
            *(uint2*)&Bhi[row][col] = h;
            *(uint2*)&Blo[row][col] = l;
        }
        __syncthreads();

        // prefetch next tile (LDGs in flight during compute)
        if (it + 1 < nIter) {
            int k0n = kc0 + (it + 1) * BK;
            #pragma unroll
            for (int i = 0; i < 4; i++) {
                int q = tid + 256 * i;
                int row = q >> 3, col = (q & 7) << 2;
                pa[i] = *(const float4*)(Ab + (size_t)row * K + k0n + col);
            }
            #pragma unroll
            for (int i = 0; i < 4; i++) {
                int q = tid + 256 * i;
                int row = q >> 5, col = (q & 31) << 2;
                pb[i] = *(const float4*)(Bb + (size_t)(k0n + row) * N + col);
            }
        }

        // compute: 3-term split (hi*hi + hi*lo + lo*hi)
        #pragma unroll
        for (int kk = 0; kk < 2; kk++) {
            uint32_t af[4][4], bh[2][4], bl[2][4];
            #pragma unroll
            for (int mi = 0; mi < 4; mi++)
                ldsm4(af[mi][0], af[mi][1], af[mi][2], af[mi][3],
                      &Ahi[wm * 64 + mi * 16 + ar][kk * 16 + ac8]);
            #pragma unroll
            for (int ni = 0; ni < 2; ni++) {
                ldsm4t(bh[ni][0], bh[ni][1], bh[ni][2], bh[ni][3],
                       &Bhi[kk * 16 + ar][wn * 32 + ni * 16 + ac8]);
                ldsm4t(bl[ni][0], bl[ni][1], bl[ni][2], bl[ni][3],
                       &Blo[kk * 16 + ar][wn * 32 + ni * 16 + ac8]);
            }
            #pragma unroll
            for (int mi = 0; mi < 4; mi++)
                #pragma unroll
                for (int nj = 0; nj < 4; nj++) {
                    int ni = nj >> 1, pr = (nj & 1) << 1;
                    mma_bf16(acc[mi][nj], af[mi], bh[ni][pr], bh[ni][pr + 1]);
                    mma_bf16(acc[mi][nj], af[mi], bl[ni][pr], bl[ni][pr + 1]);
                }
            // reload A fragments from lo plane; lo*hi term
            #pragma unroll
            for (int mi = 0; mi < 4; mi++)
                ldsm4(af[mi][0], af[mi][1], af[mi][2], af[mi][3],
                      &Alo[wm * 64 + mi * 16 + ar][kk * 16 + ac8]);
            #pragma unroll
            for (int mi = 0; mi < 4; mi++)
                #pragma unroll
                for (int nj = 0; nj < 4; nj++) {
                    int ni = nj >> 1, pr = (nj & 1) << 1;
                    mma_bf16(acc[mi][nj], af[mi], bh[ni][pr], bh[ni][pr + 1]);
                }
        }
        __syncthreads();
    }

    const int gid = lane >> 2, tig = lane & 3;
    #pragma unroll
    for (int mi = 0; mi < 4; mi++) {
        size_t r0 = m0 + wm * 64 + mi * 16 + gid;
        #pragma unroll
        for (int nj = 0; nj < 4; nj++) {
            size_t cc = n0 + wn * 32 + nj * 8 + tig * 2;
            *(float2*)(C + r0 * N + cc)       = make_float2(acc[mi][nj][0], acc[mi][nj][1]);
            *(float2*)(C + (r0 + 8) * N + cc) = make_float2(acc[mi][nj][2], acc[mi][nj][3]);
        }
    }
}

__global__ void __launch_bounds__(256) mm_qkp(const float* __restrict__ W) {
    gemm_mma_body<NTOK_P, 2*PD, PD, PD>(g_fl, W, g_qkp);
}
__global__ void __launch_bounds__(256) mm_pv(const float* __restrict__ W) {
    gemm_mma_body<NTOK_P, PD, PD, PD>(g_fl, W, g_pv);
}
__global__ void __launch_bounds__(256) mm_pfo(const float* __restrict__ W) {
    gemm_mma_body<NTOK_P, PD, PD, PD>(g_pf, W, g_pfo);
}
__global__ void __launch_bounds__(256) mm_qkw(const float* __restrict__ W) {
    gemm_mma_body<NTOK_W, 2*WIN_INNER, PLD, PLD>(g_plln, W, g_qkw);
}
__global__ void __launch_bounds__(256) mm_wv(const float* __restrict__ W) {
    gemm_mma_body<NTOK_W, WIN_INNER, WD, WD / WV_SPLITK>(g_lnxw, W, g_wv_part);
}
__global__ void __launch_bounds__(256) mm_wfo(const float* __restrict__ W) {
    gemm_mma_body<NTOK_W, WD, WIN_INNER, WIN_INNER>(g_wf, W, g_wfo);
}

// split-K reduction for wv (deterministic)
__global__ void kR_wv() {
    size_t i = (size_t)blockIdx.x * blockDim.x + threadIdx.x;
    if (i >= (size_t)NTOK_W * WIN_INNER) return;
    float s = 0.f;
    #pragma unroll
    for (int z = 0; z < WV_SPLITK; z++)
        s += g_wv_part[(size_t)z * NTOK_W * WIN_INNER + i];
    g_wv[i] = s;
}

// ---------------------------------------------------------------------------
// Block reduce
// ---------------------------------------------------------------------------
__device__ __forceinline__ float blockReduceSum(float v, float* sh) {
    int lane = threadIdx.x & 31, wid = threadIdx.x >> 5;
    #pragma unroll
    for (int o = 16; o > 0; o >>= 1) v += __shfl_down_sync(0xffffffffu, v, o);
    if (lane == 0) sh[wid] = v;
    __syncthreads();
    int nw = blockDim.x >> 5;
    v = (threadIdx.x < (unsigned)nw) ? sh[threadIdx.x] : 0.f;
    if (wid == 0) {
        #pragma unroll
        for (int o = 16; o > 0; o >>= 1) v += __shfl_down_sync(0xffffffffu, v, o);
        if (lane == 0) sh[0] = v;
    }
    __syncthreads();
    float r = sh[0];
    __syncthreads();
    return r;
}

// ---------------------------------------------------------------------------
// kA: gather patch token + LayerNorm -> g_fl
// ---------------------------------------------------------------------------
__global__ void kA_fl(const float* __restrict__ x,
                      const float* __restrict__ gam, const float* __restrict__ bet) {
    int t = blockIdx.x;
    int b = t >> 8, w = (t >> 4) & 15, p = t & 15;
    int wy = w >> 2, wx = w & 3, py = p >> 2, px = p & 3;
    int i0 = wy * WS + py * PS, j0 = wx * WS + px * PS;
    __shared__ float red[32];
    float vals[4], s = 0.f, s2 = 0.f;
    #pragma unroll
    for (int r = 0; r < 4; r++) {
        int d = threadIdx.x + r * 256;
        int sidx = d >> 4, c = d & 15;
        int sy = sidx >> 3, sx = sidx & 7;
        float v = x[(((size_t)b * CCH + c) * SZ + (i0 + sy)) * SZ + (j0 + sx)];
        vals[r] = v; s += v; s2 += v * v;
    }
    s  = blockReduceSum(s,  red);
    s2 = blockReduceSum(s2, red);
    float m  = s  * (1.f / PD);
    float rs = rsqrtf(s2 * (1.f / PD) - m * m + 1e-5f);
    #pragma unroll
    for (int r = 0; r < 4; r++) {
        int d = threadIdx.x + r * 256;
        g_fl[(size_t)t * PD + d] = (vals[r] - m) * rs * gam[d] + bet[d];
    }
}

// ---------------------------------------------------------------------------
// kB: patch attention + LePE conv, per (b,win,head)
// ---------------------------------------------------------------------------
__global__ void kB_pattn(const float* __restrict__ cw, const float* __restrict__ cb) {
    int bid = blockIdx.x;
    int h = bid & 7;
    size_t tb = (size_t)(bid >> 3) * NPAT;
    __shared__ float qs[NPAT][129], ks[NPAT][129], S[NPAT][NPAT];
    int tid = threadIdx.x;
    #pragma unroll
    for (int r = 0; r < 8; r++) {
        int idx = tid + r * 256;
        int p = idx >> 7, d = idx & 127;
        qs[p][d] = g_qkp[(tb + p) * (2 * PD) + h * PDH + d];
        ks[p][d] = g_qkp[(tb + p) * (2 * PD) + PD + h * PDH + d];
    }
    __syncthreads();
    {
        int p = tid >> 4, v = tid & 15;
        float acc = 0.f;
        #pragma unroll 8
        for (int d = 0; d < PDH; d++) acc += qs[p][d] * ks[v][d];
        S[p][v] = acc * ATT_SCALE;
    }
    __syncthreads();
    if (tid < NPAT) {
        float mx = -1e30f;
        #pragma unroll
        for (int v = 0; v < NPAT; v++) mx = fmaxf(mx, S[tid][v]);
        float e[NPAT], sum = 0.f;
        #pragma unroll
        for (int v = 0; v < NPAT; v++) { e[v] = __expf(S[tid][v] - mx); sum += e[v]; }
        float inv = 1.f / sum;
        #pragma unroll
        for (int v = 0; v < NPAT; v++) S[tid][v] = e[v] * inv;
    }
    __syncthreads();
    #pragma unroll
    for (int r = 0; r < 8; r++) {
        int idx = tid + r * 256;
        int p = idx >> 7, d = idx & 127;
        ks[p][d] = g_pv[(tb + p) * PD + h * PDH + d];
    }
    __syncthreads();
    #pragma unroll
    for (int r = 0; r < 8; r++) {
        int idx = tid + r * 256;
        int p = idx >> 7, d = idx & 127;
        float acc = 0.f;
        #pragma unroll
        for (int v = 0; v < NPAT; v++) acc += S[p][v] * ks[v][d];
        int py = p >> 2, px = p & 3;
        #pragma unroll
        for (int ky = 0; ky < 3; ky++) {
            int yy = py + ky - 1;
            if (yy < 0 || yy > 3) continue;
            #pragma unroll
            for (int kx = 0; kx < 3; kx++) {
                int xx = px + kx - 1;
                if (xx < 0 || xx > 3) continue;
                acc += cw[d * 9 + ky * 3 + kx] * ks[yy * 4 + xx][d];
            }
        }
        acc += cb[d];
        g_pf[(tb + p) * PD + h * PDH + d] = acc;
    }
}

// ---------------------------------------------------------------------------
// kC: 4x4 average pool + gather + LayerNorm -> g_plln
// ---------------------------------------------------------------------------
__global__ void kC_pl(const float* __restrict__ x,
                      const float* __restrict__ gam, const float* __restrict__ bet) {
    int t = blockIdx.x;
    int b = t >> 4, w = t & 15, wy = w >> 2, wx = w & 3;
    __shared__ float red[32];
    float vals[4], s = 0.f, s2 = 0.f;
    #pragma unroll
    for (int r = 0; r < 4; r++) {
        int d = threadIdx.x + r * 256;
        int uy = (d >> 4) >> 3, ux = (d >> 4) & 7, c = d & 15;
        int i0 = wy * WS + uy * 4, j0 = wx * WS + ux * 4;
        const float* xb = x + (((size_t)b * CCH + c) * SZ + i0) * SZ + j0;
        float acc = 0.f;
        #pragma unroll
        for (int a = 0; a < 4; a++)
            #pragma unroll
            for (int e = 0; e < 4; e++) acc += xb[a * SZ + e];
        float v = acc * (1.f / 16.f);
        vals[r] = v; s += v; s2 += v * v;
    }
    s  = blockReduceSum(s,  red);
    s2 = blockReduceSum(s2, red);
    float m  = s  * (1.f / PLD);
    float rs = rsqrtf(s2 * (1.f / PLD) - m * m + 1e-5f);
    #pragma unroll
    for (int r = 0; r < 4; r++) {
        int d = threadIdx.x + r * 256;
        g_plln[(size_t)t * PLD + d] = (vals[r] - m) * rs * gam[d] + bet[d];
    }
}

// ---------------------------------------------------------------------------
// kD: window attention scores + diag/non-diag rescale
// ---------------------------------------------------------------------------
__global__ void kD_wscores() {
    int bid = blockIdx.x;
    int h = bid & 7, b = bid >> 3;
    __shared__ float qs[NWIN][129], ks[NWIN][129], S[NWIN][NWIN];
    int tid = threadIdx.x;
    #pragma unroll
    for (int r = 0; r < 8; r++) {
        int idx = tid + r * 256;
        int n = idx >> 7, d = idx & 127;
        qs[n][d] = g_qkw[((size_t)b * NWIN + n) * (2 * WIN_INNER) + h * WDH + d];
        ks[n][d] = g_qkw[((size_t)b * NWIN + n) * (2 * WIN_INNER) + WIN_INNER + h * WDH + d];
    }
    __syncthreads();
    int n = tid >> 4, m = tid & 15;
    {
        float acc = 0.f;
        #pragma unroll 8
        for (int d = 0; d < WDH; d++) acc += qs[n][d] * ks[m][d];
        S[n][m] = acc * ATT_SCALE;
    }
    __syncthreads();
    if (tid < NWIN) {
        float mx = -1e30f;
        #pragma unroll
        for (int v = 0; v < NWIN; v++) mx = fmaxf(mx, S[tid][v]);
        float e[NWIN], sum = 0.f;
        #pragma unroll
        for (int v = 0; v < NWIN; v++) { e[v] = __expf(S[tid][v] - mx); sum += e[v]; }
        float inv = 1.f / sum;
        #pragma unroll
        for (int v = 0; v < NWIN; v++) S[tid][v] = e[v] * inv;
    }
    __syncthreads();
    float dn = S[n][n];
    bool line = dn < 0.5f;
    if (m == 0) g_ds[((size_t)b * NH + h) * NWIN + n] = line ? 0.5f : dn;
    float val = (m == n) ? 0.f : S[n][m];
    if (line) val *= 0.5f / (1.f - dn);
    g_nds[(((size_t)b * NH + h) * NWIN + n) * NWIN + m] = val;
}

// ---------------------------------------------------------------------------
// kE: window-pixel gather + LayerNorm over WD -> g_lnxw
// ---------------------------------------------------------------------------
__global__ void kE_lnxw(const float* __restrict__ x,
                        const float* __restrict__ gam, const float* __restrict__ bet) {
    int t = blockIdx.x;
    int b = t >> 4, w = t & 15, wy = w >> 2, wx = w & 3;
    __shared__ float red[32];
    float s = 0.f, s2 = 0.f;
    for (int r = 0; r < 64; r++) {
        int d = threadIdx.x + r * 256;
        int sidx = d >> 4, c = d & 15;
        int sy = sidx >> 5, sx = sidx & 31;
        float v = x[(((size_t)b * CCH + c) * SZ + (wy * WS + sy)) * SZ + (wx * WS + sx)];
        s += v; s2 += v * v;
    }
    s  = blockReduceSum(s,  red);
    s2 = blockReduceSum(s2, red);
    float m  = s  * (1.f / WD);
    float rs = rsqrtf(s2 * (1.f / WD) - m * m + 1e-5f);
    for (int r = 0; r < 64; r++) {
        int d = threadIdx.x + r * 256;
        int sidx = d >> 4, c = d & 15;
        int sy = sidx >> 5, sx = sidx & 31;
        float v = x[(((size_t)b * CCH + c) * SZ + (wy * WS + sy)) * SZ + (wx * WS + sx)];
        g_lnxw[(size_t)t * WD + d] = (v - m) * rs * gam[d] + bet[d];
    }
}

// ---------------------------------------------------------------------------
// kF: window value mixing with nds + LePE conv -> g_wf
// ---------------------------------------------------------------------------
__global__ void kF_wattn(const float* __restrict__ cw, const float* __restrict__ cb) {
    int bid = blockIdx.x;
    int h = bid & 7, b = bid >> 3;
    __shared__ float vs[NWIN][129], P[NWIN][NWIN];
    int tid = threadIdx.x;
    #pragma unroll
    for (int r = 0; r < 8; r++) {
        int idx = tid + r * 256;
        int n = idx >> 7, d = idx & 127;
        vs[n][d] = g_wv[((size_t)b * NWIN + n) * WIN_INNER + h * WDH + d];
    }
    {
        int n = tid >> 4, m = tid & 15;
        P[n][m] = g_nds[(((size_t)b * NH + h) * NWIN + n) * NWIN + m];
    }
    __syncthreads();
    #pragma unroll
    for (int r = 0; r < 8; r++) {
        int idx = tid + r * 256;
        int n = idx >> 7, d = idx & 127;
        float acc = 0.f;
        #pragma unroll
        for (int m = 0; m < NWIN; m++) acc += P[n][m] * vs[m][d];
        int wyy = n >> 2, wxx = n & 3;
        #pragma unroll
        for (int ky = 0; ky < 3; ky++) {
            int yy = wyy + ky - 1;
            if (yy < 0 || yy > 3) continue;
            #pragma unroll
            for (int kx = 0; kx < 3; kx++) {
                int xx = wxx + kx - 1;
                if (xx < 0 || xx > 3) continue;
                acc += cw[d * 9 + ky * 3 + kx] * vs[yy * 4 + xx][d];
            }
        }
        acc += cb[d];
        g_wf[((size_t)b * NWIN + n) * WIN_INNER + h * WDH + d] = acc;
    }
}

// ---------------------------------------------------------------------------
// kG: out = ds*pfo + wfo (scatter) + residual
// ---------------------------------------------------------------------------
__global__ void kG_out(const float* __restrict__ x, float* __restrict__ out) {
    size_t idx = (size_t)blockIdx.x * blockDim.x + threadIdx.x;
    if (idx >= (size_t)BATCH * CCH * SZ * SZ) return;
    int j = idx & 127;
    int i = (idx >> 7) & 127;
    int c = (idx >> 14) & 15;
    int b = (int)(idx >> 18);
    int wy = i >> 5, sy = i & 31, wx = j >> 5, sx = j & 31;
    int n = wy * 4 + wx;
    int wd = ((sy << 5) + sx) * 16 + c;
    int h = wd >> 11;
    size_t base = ((size_t)b * NWIN + n) * WD + wd;
    float v = g_ds[((size_t)b * NH + h) * NWIN + n] * g_pfo[base] + g_wfo[base] + x[idx];
    out[idx] = v;
}

// ---------------------------------------------------------------------------
// Launch
// ---------------------------------------------------------------------------
extern "C" void kernel_launch(void* const* d_in, const int* in_sizes, int n_in,
                              void* d_out, int out_size) {
    const float* x       = (const float*)d_in[0];
    const float* pn_g    = (const float*)d_in[1];
    const float* pn_b    = (const float*)d_in[2];
    const float* Wqk_p   = (const float*)d_in[3];
    const float* Wv_p    = (const float*)d_in[4];
    const float* conv_pw = (const float*)d_in[5];
    const float* conv_pb = (const float*)d_in[6];
    const float* Wout_p  = (const float*)d_in[7];
    const float* pln_g   = (const float*)d_in[8];
    const float* pln_b   = (const float*)d_in[9];
    const float* Wqk_w   = (const float*)d_in[10];
    const float* wn_g    = (const float*)d_in[11];
    const float* wn_b    = (const float*)d_in[12];
    const float* Wv_w    = (const float*)d_in[13];
    const float* conv_ww = (const float*)d_in[14];
    const float* conv_wb = (const float*)d_in[15];
    const float* Wout_w  = (const float*)d_in[16];
    float* out = (float*)d_out;

    // --- patch branch ---
    kA_fl<<<NTOK_P, 256>>>(x, pn_g, pn_b);
    mm_qkp<<<dim3((2*PD)/128, NTOK_P/128), 256>>>(Wqk_p);
    mm_pv <<<dim3(PD/128,     NTOK_P/128), 256>>>(Wv_p);
    kB_pattn<<<BATCH*NWIN*NH, 256>>>(conv_pw, conv_pb);
    mm_pfo<<<dim3(PD/128,     NTOK_P/128), 256>>>(Wout_p);

    // --- window branch ---
    kC_pl<<<NTOK_W, 256>>>(x, pln_g, pln_b);
    mm_qkw<<<dim3((2*WIN_INNER)/128, NTOK_W/128), 256>>>(Wqk_w);
    kD_wscores<<<BATCH*NH, 256>>>();
    kE_lnxw<<<NTOK_W, 256>>>(x, wn_g, wn_b);
    mm_wv <<<dim3(WIN_INNER/128, NTOK_W/128, WV_SPLITK), 256>>>(Wv_w);
    kR_wv<<<(NTOK_W * WIN_INNER + 255) / 256, 256>>>();
    kF_wattn<<<BATCH*NH, 256>>>(conv_ww, conv_wb);
    mm_wfo<<<dim3(WD/128, NTOK_W/128), 256>>>(Wout_w);

    // --- combine + residual ---
    size_t total = (size_t)BATCH * CCH * SZ * SZ;
    kG_out<<<(unsigned)((total + 255) / 256), 256>>>(x, out);
}

// round 8
// speedup vs baseline: 3.6748x; 1.0502x over previous
#include <cuda_runtime.h>
#include <cuda_bf16.h>
#include <cstdint>

// ---------------------------------------------------------------------------
// Problem dims (compile-time)
// ---------------------------------------------------------------------------
#define BATCH 64
#define CCH   16
#define SZ    128
#define WS    32
#define PS    8
#define NH    8
#define WN    4
#define PPW   4
#define NWIN  16
#define NPAT  16
#define PD    1024
#define PDH   128
#define PLD   1024
#define WDH   128
#define WIN_INNER 1024
#define WD    16384
#define NTOK_P (BATCH*NWIN*NPAT)   // 16384
#define NTOK_W (BATCH*NWIN)        // 1024
#define ATT_SCALE 0.08838834764831845f

#define WV_SPLITK 8

// ---------------------------------------------------------------------------
// Scratch (device globals) — EXACT R2/R7 set (known delta=0)
// ---------------------------------------------------------------------------
__device__ float g_fl  [(size_t)NTOK_P * PD];
__device__ float g_qkp [(size_t)NTOK_P * 2 * PD];
__device__ float g_pv  [(size_t)NTOK_P * PD];
__device__ float g_pf  [(size_t)NTOK_P * PD];
__device__ float g_pfo [(size_t)NTOK_P * PD];
__device__ float g_plln[(size_t)NTOK_W * PLD];
__device__ float g_qkw [(size_t)NTOK_W * 2 * WIN_INNER];
__device__ float g_nds [(size_t)BATCH * NH * NWIN * NWIN];
__device__ float g_ds  [(size_t)BATCH * NH * NWIN];
__device__ float g_lnxw[(size_t)NTOK_W * WD];
__device__ float g_wv  [(size_t)NTOK_W * WIN_INNER];
__device__ float g_wv_part[(size_t)WV_SPLITK * NTOK_W * WIN_INNER];
__device__ float g_wf  [(size_t)NTOK_W * WIN_INNER];
__device__ float g_wfo [(size_t)NTOK_W * WD];

// ---------------------------------------------------------------------------
// MMA helpers
// ---------------------------------------------------------------------------
__device__ __forceinline__ void ldsm4(uint32_t& r0, uint32_t& r1, uint32_t& r2,
                                      uint32_t& r3, const void* p) {
    uint32_t a = (uint32_t)__cvta_generic_to_shared(p);
    asm volatile("ldmatrix.sync.aligned.m8n8.x4.shared.b16 {%0,%1,%2,%3}, [%4];"
                 : "=r"(r0), "=r"(r1), "=r"(r2), "=r"(r3) : "r"(a));
}
__device__ __forceinline__ void ldsm4t(uint32_t& r0, uint32_t& r1, uint32_t& r2,
                                       uint32_t& r3, const void* p) {
    uint32_t a = (uint32_t)__cvta_generic_to_shared(p);
    asm volatile("ldmatrix.sync.aligned.m8n8.x4.trans.shared.b16 {%0,%1,%2,%3}, [%4];"
                 : "=r"(r0), "=r"(r1), "=r"(r2), "=r"(r3) : "r"(a));
}
__device__ __forceinline__ void mma_bf16(float* c, const uint32_t* a, uint32_t b0, uint32_t b1) {
    asm volatile(
        "mma.sync.aligned.m16n8k16.row.col.f32.bf16.bf16.f32 "
        "{%0,%1,%2,%3},{%4,%5,%6,%7},{%8,%9},{%0,%1,%2,%3};"
        : "+f"(c[0]), "+f"(c[1]), "+f"(c[2]), "+f"(c[3])
        : "r"(a[0]), "r"(a[1]), "r"(a[2]), "r"(a[3]), "r"(b0), "r"(b1));
}

// fp32x4 -> packed bf16 hi-pair + lo-pair (truncation split).
__device__ __forceinline__ void cvt4(float4 v, uint2& h, uint2& l) {
    uint32_t b0 = __float_as_uint(v.x), b1 = __float_as_uint(v.y);
    uint32_t b2 = __float_as_uint(v.z), b3 = __float_as_uint(v.w);
    h.x = __byte_perm(b0, b1, 0x7632);
    h.y = __byte_perm(b2, b3, 0x7632);
    float r0 = v.x - __uint_as_float(b0 & 0xFFFF0000u);
    float r1 = v.y - __uint_as_float(b1 & 0xFFFF0000u);
    float r2 = v.z - __uint_as_float(b2 & 0xFFFF0000u);
    float r3 = v.w - __uint_as_float(b3 & 0xFFFF0000u);
    __nv_bfloat162 p0 = __floats2bfloat162_rn(r0, r1);
    __nv_bfloat162 p1 = __floats2bfloat162_rn(r2, r3);
    l.x = *reinterpret_cast<uint32_t*>(&p0);
    l.y = *reinterpret_cast<uint32_t*>(&p1);
}

// ---------------------------------------------------------------------------
// Split-bf16 tensor-core GEMM (R7-proven)
// ---------------------------------------------------------------------------
template<int M, int N, int K, int KC>
__device__ __forceinline__ void gemm_mma_body(const float* __restrict__ A,
                                              const float* __restrict__ B,
                                              float* __restrict__ Cbase) {
    constexpr int BM = 128, BN = 128, BK = 32;
    constexpr int APAD = 8, BPAD = 8;
    __shared__ __nv_bfloat16 Ahi[BM][BK + APAD];
    __shared__ __nv_bfloat16 Alo[BM][BK + APAD];
    __shared__ __nv_bfloat16 Bhi[BK][BN + BPAD];
    __shared__ __nv_bfloat16 Blo[BK][BN + BPAD];

    const int tid  = threadIdx.x;
    const int lane = tid & 31;
    const int wid  = tid >> 5;
    const int wm   = wid & 1;
    const int wn   = wid >> 1;
    const size_t m0 = (size_t)blockIdx.y * BM;
    const size_t n0 = (size_t)blockIdx.x * BN;
    const int kc0 = blockIdx.z * KC;
    float* __restrict__ C = Cbase + (size_t)blockIdx.z * M * N;

    const float* Ab = A + m0 * K;
    const float* Bb = B + n0;

    float acc[4][4][4];
    #pragma unroll
    for (int i = 0; i < 4; i++)
        #pragma unroll
        for (int j = 0; j < 4; j++)
            #pragma unroll
            for (int e = 0; e < 4; e++) acc[i][j][e] = 0.f;

    const int ar  = lane & 15;
    const int ac8 = (lane >> 4) << 3;
    const int nIter = KC / BK;

    float4 pa[4], pb[4];
    #pragma unroll
    for (int i = 0; i < 4; i++) {
        int q = tid + 256 * i;
        int row = q >> 3, col = (q & 7) << 2;
        pa[i] = *(const float4*)(Ab + (size_t)row * K + kc0 + col);
    }
    #pragma unroll
    for (int i = 0; i < 4; i++) {
        int q = tid + 256 * i;
        int row = q >> 5, col = (q & 31) << 2;
        pb[i] = *(const float4*)(Bb + (size_t)(kc0 + row) * N + col);
    }

    for (int it = 0; it < nIter; ++it) {
        #pragma unroll
        for (int i = 0; i < 4; i++) {
            int q = tid + 256 * i;
            int row = q >> 3, col = (q & 7) << 2;
            uint2 h, l;
            cvt4(pa[i], h, l);
            *(uint2*)&Ahi[row][col] = h;
            *(uint2*)&Alo[row][col] = l;
        }
        #pragma unroll
        for (int i = 0; i < 4; i++) {
            int q = tid + 256 * i;
            int row = q >> 5, col = (q & 31) << 2;
            uint2 h, l;
            cvt4(pb[i], h, l);
            *(uint2*)&Bhi[row][col] = h;
            *(uint2*)&Blo[row][col] = l;
        }
        __syncthreads();

        if (it + 1 < nIter) {
            int k0n = kc0 + (it + 1) * BK;
            #pragma unroll
            for (int i = 0; i < 4; i++) {
                int q = tid + 256 * i;
                int row = q >> 3, col = (q & 7) << 2;
                pa[i] = *(const float4*)(Ab + (size_t)row * K + k0n + col);
            }
            #pragma unroll
            for (int i = 0; i < 4; i++) {
                int q = tid + 256 * i;
                int row = q >> 5, col = (q & 31) << 2;
                pb[i] = *(const float4*)(Bb + (size_t)(k0n + row) * N + col);
            }
        }

        #pragma unroll
        for (int kk = 0; kk < 2; kk++) {
            uint32_t af[4][4], bh[2][4], bl[2][4];
            #pragma unroll
            for (int mi = 0; mi < 4; mi++)
                ldsm4(af[mi][0], af[mi][1], af[mi][2], af[mi][3],
                      &Ahi[wm * 64 + mi * 16 + ar][kk * 16 + ac8]);
            #pragma unroll
            for (int ni = 0; ni < 2; ni++) {
                ldsm4t(bh[ni][0], bh[ni][1], bh[ni][2], bh[ni][3],
                       &Bhi[kk * 16 + ar][wn * 32 + ni * 16 + ac8]);
                ldsm4t(bl[ni][0], bl[ni][1], bl[ni][2], bl[ni][3],
                       &Blo[kk * 16 + ar][wn * 32 + ni * 16 + ac8]);
            }
            #pragma unroll
            for (int mi = 0; mi < 4; mi++)
                #pragma unroll
                for (int nj = 0; nj < 4; nj++) {
                    int ni = nj >> 1, pr = (nj & 1) << 1;
                    mma_bf16(acc[mi][nj], af[mi], bh[ni][pr], bh[ni][pr + 1]);
                    mma_bf16(acc[mi][nj], af[mi], bl[ni][pr], bl[ni][pr + 1]);
                }
            #pragma unroll
            for (int mi = 0; mi < 4; mi++)
                ldsm4(af[mi][0], af[mi][1], af[mi][2], af[mi][3],
                      &Alo[wm * 64 + mi * 16 + ar][kk * 16 + ac8]);
            #pragma unroll
            for (int mi = 0; mi < 4; mi++)
                #pragma unroll
                for (int nj = 0; nj < 4; nj++) {
                    int ni = nj >> 1, pr = (nj & 1) << 1;
                    mma_bf16(acc[mi][nj], af[mi], bh[ni][pr], bh[ni][pr + 1]);
                }
        }
        __syncthreads();
    }

    const int gid = lane >> 2, tig = lane & 3;
    #pragma unroll
    for (int mi = 0; mi < 4; mi++) {
        size_t r0 = m0 + wm * 64 + mi * 16 + gid;
        #pragma unroll
        for (int nj = 0; nj < 4; nj++) {
            size_t cc = n0 + wn * 32 + nj * 8 + tig * 2;
            *(float2*)(C + r0 * N + cc)       = make_float2(acc[mi][nj][0], acc[mi][nj][1]);
            *(float2*)(C + (r0 + 8) * N + cc) = make_float2(acc[mi][nj][2], acc[mi][nj][3]);
        }
    }
}

__global__ void __launch_bounds__(256) mm_qkp(const float* __restrict__ W) {
    gemm_mma_body<NTOK_P, 2*PD, PD, PD>(g_fl, W, g_qkp);
}
__global__ void __launch_bounds__(256) mm_pv(const float* __restrict__ W) {
    gemm_mma_body<NTOK_P, PD, PD, PD>(g_fl, W, g_pv);
}
__global__ void __launch_bounds__(256) mm_pfo(const float* __restrict__ W) {
    gemm_mma_body<NTOK_P, PD, PD, PD>(g_pf, W, g_pfo);
}
__global__ void __launch_bounds__(256) mm_qkw(const float* __restrict__ W) {
    gemm_mma_body<NTOK_W, 2*WIN_INNER, PLD, PLD>(g_plln, W, g_qkw);
}
__global__ void __launch_bounds__(256) mm_wv(const float* __restrict__ W) {
    gemm_mma_body<NTOK_W, WIN_INNER, WD, WD / WV_SPLITK>(g_lnxw, W, g_wv_part);
}
__global__ void __launch_bounds__(256) mm_wfo(const float* __restrict__ W) {
    gemm_mma_body<NTOK_W, WD, WIN_INNER, WIN_INNER>(g_wf, W, g_wfo);
}

// split-K reduction for wv (deterministic)
__global__ void kR_wv() {
    size_t i = (size_t)blockIdx.x * blockDim.x + threadIdx.x;
    if (i >= (size_t)NTOK_W * WIN_INNER) return;
    float s = 0.f;
    #pragma unroll
    for (int z = 0; z < WV_SPLITK; z++)
        s += g_wv_part[(size_t)z * NTOK_W * WIN_INNER + i];
    g_wv[i] = s;
}

// ---------------------------------------------------------------------------
// Block reduce
// ---------------------------------------------------------------------------
__device__ __forceinline__ float blockReduceSum(float v, float* sh) {
    int lane = threadIdx.x & 31, wid = threadIdx.x >> 5;
    #pragma unroll
    for (int o = 16; o > 0; o >>= 1) v += __shfl_down_sync(0xffffffffu, v, o);
    if (lane == 0) sh[wid] = v;
    __syncthreads();
    int nw = blockDim.x >> 5;
    v = (threadIdx.x < (unsigned)nw) ? sh[threadIdx.x] : 0.f;
    if (wid == 0) {
        #pragma unroll
        for (int o = 16; o > 0; o >>= 1) v += __shfl_down_sync(0xffffffffu, v, o);
        if (lane == 0) sh[0] = v;
    }
    __syncthreads();
    float r = sh[0];
    __syncthreads();
    return r;
}

// ---------------------------------------------------------------------------
// kA: gather patch token + LayerNorm -> g_fl
// ---------------------------------------------------------------------------
__global__ void kA_fl(const float* __restrict__ x,
                      const float* __restrict__ gam, const float* __restrict__ bet) {
    int t = blockIdx.x;
    int b = t >> 8, w = (t >> 4) & 15, p = t & 15;
    int wy = w >> 2, wx = w & 3, py = p >> 2, px = p & 3;
    int i0 = wy * WS + py * PS, j0 = wx * WS + px * PS;
    __shared__ float red[32];
    float vals[4], s = 0.f, s2 = 0.f;
    #pragma unroll
    for (int r = 0; r < 4; r++) {
        int d = threadIdx.x + r * 256;
        int sidx = d >> 4, c = d & 15;
        int sy = sidx >> 3, sx = sidx & 7;
        float v = x[(((size_t)b * CCH + c) * SZ + (i0 + sy)) * SZ + (j0 + sx)];
        vals[r] = v; s += v; s2 += v * v;
    }
    s  = blockReduceSum(s,  red);
    s2 = blockReduceSum(s2, red);
    float m  = s  * (1.f / PD);
    float rs = rsqrtf(s2 * (1.f / PD) - m * m + 1e-5f);
    #pragma unroll
    for (int r = 0; r < 4; r++) {
        int d = threadIdx.x + r * 256;
        g_fl[(size_t)t * PD + d] = (vals[r] - m) * rs * gam[d] + bet[d];
    }
}

// ---------------------------------------------------------------------------
// kB: patch attention + LePE conv, per (b,win,head)
// ---------------------------------------------------------------------------
__global__ void kB_pattn(const float* __restrict__ cw, const float* __restrict__ cb) {
    int bid = blockIdx.x;
    int h = bid & 7;
    size_t tb = (size_t)(bid >> 3) * NPAT;
    __shared__ float qs[NPAT][129], ks[NPAT][129], S[NPAT][NPAT];
    int tid = threadIdx.x;
    #pragma unroll
    for (int r = 0; r < 8; r++) {
        int idx = tid + r * 256;
        int p = idx >> 7, d = idx & 127;
        qs[p][d] = g_qkp[(tb + p) * (2 * PD) + h * PDH + d];
        ks[p][d] = g_qkp[(tb + p) * (2 * PD) + PD + h * PDH + d];
    }
    __syncthreads();
    {
        int p = tid >> 4, v = tid & 15;
        float acc = 0.f;
        #pragma unroll 8
        for (int d = 0; d < PDH; d++) acc += qs[p][d] * ks[v][d];
        S[p][v] = acc * ATT_SCALE;
    }
    __syncthreads();
    if (tid < NPAT) {
        float mx = -1e30f;
        #pragma unroll
        for (int v = 0; v < NPAT; v++) mx = fmaxf(mx, S[tid][v]);
        float e[NPAT], sum = 0.f;
        #pragma unroll
        for (int v = 0; v < NPAT; v++) { e[v] = __expf(S[tid][v] - mx); sum += e[v]; }
        float inv = 1.f / sum;
        #pragma unroll
        for (int v = 0; v < NPAT; v++) S[tid][v] = e[v] * inv;
    }
    __syncthreads();
    #pragma unroll
    for (int r = 0; r < 8; r++) {
        int idx = tid + r * 256;
        int p = idx >> 7, d = idx & 127;
        ks[p][d] = g_pv[(tb + p) * PD + h * PDH + d];
    }
    __syncthreads();
    #pragma unroll
    for (int r = 0; r < 8; r++) {
        int idx = tid + r * 256;
        int p = idx >> 7, d = idx & 127;
        float acc = 0.f;
        #pragma unroll
        for (int v = 0; v < NPAT; v++) acc += S[p][v] * ks[v][d];
        int py = p >> 2, px = p & 3;
        #pragma unroll
        for (int ky = 0; ky < 3; ky++) {
            int yy = py + ky - 1;
            if (yy < 0 || yy > 3) continue;
            #pragma unroll
            for (int kx = 0; kx < 3; kx++) {
                int xx = px + kx - 1;
                if (xx < 0 || xx > 3) continue;
                acc += cw[d * 9 + ky * 3 + kx] * ks[yy * 4 + xx][d];
            }
        }
        acc += cb[d];
        g_pf[(tb + p) * PD + h * PDH + d] = acc;
    }
}

// ---------------------------------------------------------------------------
// kC: 4x4 average pool + gather + LayerNorm -> g_plln
// ---------------------------------------------------------------------------
__global__ void kC_pl(const float* __restrict__ x,
                      const float* __restrict__ gam, const float* __restrict__ bet) {
    int t = blockIdx.x;
    int b = t >> 4, w = t & 15, wy = w >> 2, wx = w & 3;
    __shared__ float red[32];
    float vals[4], s = 0.f, s2 = 0.f;
    #pragma unroll
    for (int r = 0; r < 4; r++) {
        int d = threadIdx.x + r * 256;
        int uy = (d >> 4) >> 3, ux = (d >> 4) & 7, c = d & 15;
        int i0 = wy * WS + uy * 4, j0 = wx * WS + ux * 4;
        const float* xb = x + (((size_t)b * CCH + c) * SZ + i0) * SZ + j0;
        float acc = 0.f;
        #pragma unroll
        for (int a = 0; a < 4; a++)
            #pragma unroll
            for (int e = 0; e < 4; e++) acc += xb[a * SZ + e];
        float v = acc * (1.f / 16.f);
        vals[r] = v; s += v; s2 += v * v;
    }
    s  = blockReduceSum(s,  red);
    s2 = blockReduceSum(s2, red);
    float m  = s  * (1.f / PLD);
    float rs = rsqrtf(s2 * (1.f / PLD) - m * m + 1e-5f);
    #pragma unroll
    for (int r = 0; r < 4; r++) {
        int d = threadIdx.x + r * 256;
        g_plln[(size_t)t * PLD + d] = (vals[r] - m) * rs * gam[d] + bet[d];
    }
}

// ---------------------------------------------------------------------------
// kD: window attention scores + diag/non-diag rescale
// ---------------------------------------------------------------------------
__global__ void kD_wscores() {
    int bid = blockIdx.x;
    int h = bid & 7, b = bid >> 3;
    __shared__ float qs[NWIN][129], ks[NWIN][129], S[NWIN][NWIN];
    int tid = threadIdx.x;
    #pragma unroll
    for (int r = 0; r < 8; r++) {
        int idx = tid + r * 256;
        int n = idx >> 7, d = idx & 127;
        qs[n][d] = g_qkw[((size_t)b * NWIN + n) * (2 * WIN_INNER) + h * WDH + d];
        ks[n][d] = g_qkw[((size_t)b * NWIN + n) * (2 * WIN_INNER) + WIN_INNER + h * WDH + d];
    }
    __syncthreads();
    int n = tid >> 4, m = tid & 15;
    {
        float acc = 0.f;
        #pragma unroll 8
        for (int d = 0; d < WDH; d++) acc += qs[n][d] * ks[m][d];
        S[n][m] = acc * ATT_SCALE;
    }
    __syncthreads();
    if (tid < NWIN) {
        float mx = -1e30f;
        #pragma unroll
        for (int v = 0; v < NWIN; v++) mx = fmaxf(mx, S[tid][v]);
        float e[NWIN], sum = 0.f;
        #pragma unroll
        for (int v = 0; v < NWIN; v++) { e[v] = __expf(S[tid][v] - mx); sum += e[v]; }
        float inv = 1.f / sum;
        #pragma unroll
        for (int v = 0; v < NWIN; v++) S[tid][v] = e[v] * inv;
    }
    __syncthreads();
    float dn = S[n][n];
    bool line = dn < 0.5f;
    if (m == 0) g_ds[((size_t)b * NH + h) * NWIN + n] = line ? 0.5f : dn;
    float val = (m == n) ? 0.f : S[n][m];
    if (line) val *= 0.5f / (1.f - dn);
    g_nds[(((size_t)b * NH + h) * NWIN + n) * NWIN + m] = val;
}

// ---------------------------------------------------------------------------
// kE: window-pixel gather + LayerNorm over WD -> g_lnxw
// ---------------------------------------------------------------------------
__global__ void kE_lnxw(const float* __restrict__ x,
                        const float* __restrict__ gam, const float* __restrict__ bet) {
    int t = blockIdx.x;
    int b = t >> 4, w = t & 15, wy = w >> 2, wx = w & 3;
    __shared__ float red[32];
    float s = 0.f, s2 = 0.f;
    for (int r = 0; r < 64; r++) {
        int d = threadIdx.x + r * 256;
        int sidx = d >> 4, c = d & 15;
        int sy = sidx >> 5, sx = sidx & 31;
        float v = x[(((size_t)b * CCH + c) * SZ + (wy * WS + sy)) * SZ + (wx * WS + sx)];
        s += v; s2 += v * v;
    }
    s  = blockReduceSum(s,  red);
    s2 = blockReduceSum(s2, red);
    float m  = s  * (1.f / WD);
    float rs = rsqrtf(s2 * (1.f / WD) - m * m + 1e-5f);
    for (int r = 0; r < 64; r++) {
        int d = threadIdx.x + r * 256;
        int sidx = d >> 4, c = d & 15;
        int sy = sidx >> 5, sx = sidx & 31;
        float v = x[(((size_t)b * CCH + c) * SZ + (wy * WS + sy)) * SZ + (wx * WS + sx)];
        g_lnxw[(size_t)t * WD + d] = (v - m) * rs * gam[d] + bet[d];
    }
}

// ---------------------------------------------------------------------------
// kF: window value mixing with nds + LePE conv -> g_wf
// ---------------------------------------------------------------------------
__global__ void kF_wattn(const float* __restrict__ cw, const float* __restrict__ cb) {
    int bid = blockIdx.x;
    int h = bid & 7, b = bid >> 3;
    __shared__ float vs[NWIN][129], P[NWIN][NWIN];
    int tid = threadIdx.x;
    #pragma unroll
    for (int r = 0; r < 8; r++) {
        int idx = tid + r * 256;
        int n = idx >> 7, d = idx & 127;
        vs[n][d] = g_wv[((size_t)b * NWIN + n) * WIN_INNER + h * WDH + d];
    }
    {
        int n = tid >> 4, m = tid & 15;
        P[n][m] = g_nds[(((size_t)b * NH + h) * NWIN + n) * NWIN + m];
    }
    __syncthreads();
    #pragma unroll
    for (int r = 0; r < 8; r++) {
        int idx = tid + r * 256;
        int n = idx >> 7, d = idx & 127;
        float acc = 0.f;
        #pragma unroll
        for (int m = 0; m < NWIN; m++) acc += P[n][m] * vs[m][d];
        int wyy = n >> 2, wxx = n & 3;
        #pragma unroll
        for (int ky = 0; ky < 3; ky++) {
            int yy = wyy + ky - 1;
            if (yy < 0 || yy > 3) continue;
            #pragma unroll
            for (int kx = 0; kx < 3; kx++) {
                int xx = wxx + kx - 1;
                if (xx < 0 || xx > 3) continue;
                acc += cw[d * 9 + ky * 3 + kx] * vs[yy * 4 + xx][d];
            }
        }
        acc += cb[d];
        g_wf[((size_t)b * NWIN + n) * WIN_INNER + h * WDH + d] = acc;
    }
}

// ---------------------------------------------------------------------------
// kG: out = ds*pfo + wfo (scatter) + residual
// ---------------------------------------------------------------------------
__global__ void kG_out(const float* __restrict__ x, float* __restrict__ out) {
    size_t idx = (size_t)blockIdx.x * blockDim.x + threadIdx.x;
    if (idx >= (size_t)BATCH * CCH * SZ * SZ) return;
    int j = idx & 127;
    int i = (idx >> 7) & 127;
    int c = (idx >> 14) & 15;
    int b = (int)(idx >> 18);
    int wy = i >> 5, sy = i & 31, wx = j >> 5, sx = j & 31;
    int n = wy * 4 + wx;
    int wd = ((sy << 5) + sx) * 16 + c;
    int h = wd >> 11;
    size_t base = ((size_t)b * NWIN + n) * WD + wd;
    float v = g_ds[((size_t)b * NH + h) * NWIN + n] * g_pfo[base] + g_wfo[base] + x[idx];
    out[idx] = v;
}

// ---------------------------------------------------------------------------
// Launch: fork window branch onto a second stream; join before kG.
// ---------------------------------------------------------------------------
extern "C" void kernel_launch(void* const* d_in, const int* in_sizes, int n_in,
                              void* d_out, int out_size) {
    const float* x       = (const float*)d_in[0];
    const float* pn_g    = (const float*)d_in[1];
    const float* pn_b    = (const float*)d_in[2];
    const float* Wqk_p   = (const float*)d_in[3];
    const float* Wv_p    = (const float*)d_in[4];
    const float* conv_pw = (const float*)d_in[5];
    const float* conv_pb = (const float*)d_in[6];
    const float* Wout_p  = (const float*)d_in[7];
    const float* pln_g   = (const float*)d_in[8];
    const float* pln_b   = (const float*)d_in[9];
    const float* Wqk_w   = (const float*)d_in[10];
    const float* wn_g    = (const float*)d_in[11];
    const float* wn_b    = (const float*)d_in[12];
    const float* Wv_w    = (const float*)d_in[13];
    const float* conv_ww = (const float*)d_in[14];
    const float* conv_wb = (const float*)d_in[15];
    const float* Wout_w  = (const float*)d_in[16];
    float* out = (float*)d_out;

    // Fresh stream/events per call; NOT destroyed (destroying during graph
    // capture would invalidate the capture; kernel_launch runs only a few
    // times so the host-object leak is negligible).
    cudaStream_t s2;
    cudaStreamCreateWithFlags(&s2, cudaStreamNonBlocking);
    cudaEvent_t evFork, evJoin;
    cudaEventCreateWithFlags(&evFork, cudaEventDisableTiming);
    cudaEventCreateWithFlags(&evJoin, cudaEventDisableTiming);

    // fork
    cudaEventRecord(evFork, 0);
    cudaStreamWaitEvent(s2, evFork, 0);

    // --- window branch (stream s2) ---
    kC_pl<<<NTOK_W, 256, 0, s2>>>(x, pln_g, pln_b);
    mm_qkw<<<dim3((2*WIN_INNER)/128, NTOK_W/128), 256, 0, s2>>>(Wqk_w);
    kD_wscores<<<BATCH*NH, 256, 0, s2>>>();
    kE_lnxw<<<NTOK_W, 256, 0, s2>>>(x, wn_g, wn_b);
    mm_wv <<<dim3(WIN_INNER/128, NTOK_W/128, WV_SPLITK), 256, 0, s2>>>(Wv_w);
    kR_wv<<<(NTOK_W * WIN_INNER + 255) / 256, 256, 0, s2>>>();
    kF_wattn<<<BATCH*NH, 256, 0, s2>>>(conv_ww, conv_wb);
    mm_wfo<<<dim3(WD/128, NTOK_W/128), 256, 0, s2>>>(Wout_w);
    cudaEventRecord(evJoin, s2);

    // --- patch branch (default stream) ---
    kA_fl<<<NTOK_P, 256>>>(x, pn_g, pn_b);
    mm_qkp<<<dim3((2*PD)/128, NTOK_P/128), 256>>>(Wqk_p);
    mm_pv <<<dim3(PD/128,     NTOK_P/128), 256>>>(Wv_p);
    kB_pattn<<<BATCH*NWIN*NH, 256>>>(conv_pw, conv_pb);
    mm_pfo<<<dim3(PD/128,     NTOK_P/128), 256>>>(Wout_p);

    // join
    cudaStreamWaitEvent(0, evJoin, 0);

    // --- combine + residual ---
    size_t total = (size_t)BATCH * CCH * SZ * SZ;
    kG_out<<<(unsigned)((total + 255) / 256), 256>>>(x, out);
}

// round 9
// speedup vs baseline: 4.5282x; 1.2322x over previous
#include <cuda_runtime.h>
#include <cuda_fp16.h>
#include <cstdint>

// ---------------------------------------------------------------------------
// Problem dims (compile-time)
// ---------------------------------------------------------------------------
#define BATCH 64
#define CCH   16
#define SZ    128
#define WS    32
#define PS    8
#define NH    8
#define WN    4
#define PPW   4
#define NWIN  16
#define NPAT  16
#define PD    1024
#define PDH   128
#define PLD   1024
#define WDH   128
#define WIN_INNER 1024
#define WD    16384
#define NTOK_P (BATCH*NWIN*NPAT)   // 16384
#define NTOK_W (BATCH*NWIN)        // 1024
#define ATT_SCALE 0.08838834764831845f

#define WV_SPLITK 8

// ---------------------------------------------------------------------------
// Scratch (device globals) — EXACT R2/R7 set (known delta=0)
// ---------------------------------------------------------------------------
__device__ float g_fl  [(size_t)NTOK_P * PD];
__device__ float g_qkp [(size_t)NTOK_P * 2 * PD];
__device__ float g_pv  [(size_t)NTOK_P * PD];
__device__ float g_pf  [(size_t)NTOK_P * PD];
__device__ float g_pfo [(size_t)NTOK_P * PD];
__device__ float g_plln[(size_t)NTOK_W * PLD];
__device__ float g_qkw [(size_t)NTOK_W * 2 * WIN_INNER];
__device__ float g_nds [(size_t)BATCH * NH * NWIN * NWIN];
__device__ float g_ds  [(size_t)BATCH * NH * NWIN];
__device__ float g_lnxw[(size_t)NTOK_W * WD];
__device__ float g_wv  [(size_t)NTOK_W * WIN_INNER];
__device__ float g_wv_part[(size_t)WV_SPLITK * NTOK_W * WIN_INNER];
__device__ float g_wf  [(size_t)NTOK_W * WIN_INNER];
__device__ float g_wfo [(size_t)NTOK_W * WD];

// ---------------------------------------------------------------------------
// MMA helpers
// ---------------------------------------------------------------------------
__device__ __forceinline__ void ldsm4(uint32_t& r0, uint32_t& r1, uint32_t& r2,
                                      uint32_t& r3, const void* p) {
    uint32_t a = (uint32_t)__cvta_generic_to_shared(p);
    asm volatile("ldmatrix.sync.aligned.m8n8.x4.shared.b16 {%0,%1,%2,%3}, [%4];"
                 : "=r"(r0), "=r"(r1), "=r"(r2), "=r"(r3) : "r"(a));
}
__device__ __forceinline__ void ldsm4t(uint32_t& r0, uint32_t& r1, uint32_t& r2,
                                       uint32_t& r3, const void* p) {
    uint32_t a = (uint32_t)__cvta_generic_to_shared(p);
    asm volatile("ldmatrix.sync.aligned.m8n8.x4.trans.shared.b16 {%0,%1,%2,%3}, [%4];"
                 : "=r"(r0), "=r"(r1), "=r"(r2), "=r"(r3) : "r"(a));
}
__device__ __forceinline__ void mma_f16(float* c, const uint32_t* a, uint32_t b0, uint32_t b1) {
    asm volatile(
        "mma.sync.aligned.m16n8k16.row.col.f32.f16.f16.f32 "
        "{%0,%1,%2,%3},{%4,%5,%6,%7},{%8,%9},{%0,%1,%2,%3};"
        : "+f"(c[0]), "+f"(c[1]), "+f"(c[2]), "+f"(c[3])
        : "r"(a[0]), "r"(a[1]), "r"(a[2]), "r"(a[3]), "r"(b0), "r"(b1));
}

// fp32x4 -> fp16 hi-pair + lo-pair (round-to-nearest split; residual ~2^-22)
__device__ __forceinline__ void cvt4A(float4 v, uint2& h, uint2& l) {
    __half2 h01 = __floats2half2_rn(v.x, v.y);
    __half2 h23 = __floats2half2_rn(v.z, v.w);
    float2 f01 = __half22float2(h01);
    float2 f23 = __half22float2(h23);
    __half2 l01 = __floats2half2_rn(v.x - f01.x, v.y - f01.y);
    __half2 l23 = __floats2half2_rn(v.z - f23.x, v.w - f23.y);
    h.x = *reinterpret_cast<uint32_t*>(&h01);
    h.y = *reinterpret_cast<uint32_t*>(&h23);
    l.x = *reinterpret_cast<uint32_t*>(&l01);
    l.y = *reinterpret_cast<uint32_t*>(&l23);
}
// fp32x4 -> single fp16 pair (weights)
__device__ __forceinline__ void cvt4B(float4 v, uint2& h) {
    __half2 h01 = __floats2half2_rn(v.x, v.y);
    __half2 h23 = __floats2half2_rn(v.z, v.w);
    h.x = *reinterpret_cast<uint32_t*>(&h01);
    h.y = *reinterpret_cast<uint32_t*>(&h23);
}

// ---------------------------------------------------------------------------
// Split-fp16 tensor-core GEMM (2-term): C = (Ahi + Alo) @ fp16(B).
// R7-proven shell: static smem, fp32 operands from gmem, register prefetch.
// 128x128x32 block tile, 256 threads, warp tile 64x32.
// ---------------------------------------------------------------------------
template<int M, int N, int K, int KC>
__device__ __forceinline__ void gemm_mma_body(const float* __restrict__ A,
                                              const float* __restrict__ B,
                                              float* __restrict__ Cbase) {
    constexpr int BM = 128, BN = 128, BK = 32;
    constexpr int APAD = 8, BPAD = 8;
    __shared__ __half Ahi[BM][BK + APAD];
    __shared__ __half Alo[BM][BK + APAD];
    __shared__ __half Bh [BK][BN + BPAD];

    const int tid  = threadIdx.x;
    const int lane = tid & 31;
    const int wid  = tid >> 5;
    const int wm   = wid & 1;
    const int wn   = wid >> 1;
    const size_t m0 = (size_t)blockIdx.y * BM;
    const size_t n0 = (size_t)blockIdx.x * BN;
    const int kc0 = blockIdx.z * KC;
    float* __restrict__ C = Cbase + (size_t)blockIdx.z * M * N;

    const float* Ab = A + m0 * K;
    const float* Bb = B + n0;

    float acc[4][4][4];
    #pragma unroll
    for (int i = 0; i < 4; i++)
        #pragma unroll
        for (int j = 0; j < 4; j++)
            #pragma unroll
            for (int e = 0; e < 4; e++) acc[i][j][e] = 0.f;

    const int ar  = lane & 15;
    const int ac8 = (lane >> 4) << 3;
    const int nIter = KC / BK;

    // prologue: prefetch first K-tile into registers
    float4 pa[4], pb[4];
    #pragma unroll
    for (int i = 0; i < 4; i++) {
        int q = tid + 256 * i;
        int row = q >> 3, col = (q & 7) << 2;
        pa[i] = *(const float4*)(Ab + (size_t)row * K + kc0 + col);
    }
    #pragma unroll
    for (int i = 0; i < 4; i++) {
        int q = tid + 256 * i;
        int row = q >> 5, col = (q & 31) << 2;
        pb[i] = *(const float4*)(Bb + (size_t)(kc0 + row) * N + col);
    }

    for (int it = 0; it < nIter; ++it) {
        // stage current tile
        #pragma unroll
        for (int i = 0; i < 4; i++) {
            int q = tid + 256 * i;
            int row = q >> 3, col = (q & 7) << 2;
            uint2 h, l;
            cvt4A(pa[i], h, l);
            *(uint2*)&Ahi[row][col] = h;
            *(uint2*)&Alo[row][col] = l;
        }
        #pragma unroll
        for (int i = 0; i < 4; i++) {
            int q = tid + 256 * i;
            int row = q >> 5, col = (q & 31) << 2;
            uint2 h;
            cvt4B(pb[i], h);
            *(uint2*)&Bh[row][col] = h;
        }
        __syncthreads();

        // prefetch next tile (LDGs in flight during compute)
        if (it + 1 < nIter) {
            int k0n = kc0 + (it + 1) * BK;
            #pragma unroll
            for (int i = 0; i < 4; i++) {
                int q = tid + 256 * i;
                int row = q >> 3, col = (q & 7) << 2;
                pa[i] = *(const float4*)(Ab + (size_t)row * K + k0n + col);
            }
            #pragma unroll
            for (int i = 0; i < 4; i++) {
                int q = tid + 256 * i;
                int row = q >> 5, col = (q & 31) << 2;
                pb[i] = *(const float4*)(Bb + (size_t)(k0n + row) * N + col);
            }
        }

        // compute: 2-term (hi*B + lo*B)
        #pragma unroll
        for (int kk = 0; kk < 2; kk++) {
            uint32_t af[4][4], bf[2][4];
            #pragma unroll
            for (int mi = 0; mi < 4; mi++)
                ldsm4(af[mi][0], af[mi][1], af[mi][2], af[mi][3],
                      &Ahi[wm * 64 + mi * 16 + ar][kk * 16 + ac8]);
            #pragma unroll
            for (int ni = 0; ni < 2; ni++)
                ldsm4t(bf[ni][0], bf[ni][1], bf[ni][2], bf[ni][3],
                       &Bh[kk * 16 + ar][wn * 32 + ni * 16 + ac8]);
            #pragma unroll
            for (int mi = 0; mi < 4; mi++)
                #pragma unroll
                for (int nj = 0; nj < 4; nj++) {
                    int ni = nj >> 1, pr = (nj & 1) << 1;
                    mma_f16(acc[mi][nj], af[mi], bf[ni][pr], bf[ni][pr + 1]);
                }
            // reload A frags from lo plane
            #pragma unroll
            for (int mi = 0; mi < 4; mi++)
                ldsm4(af[mi][0], af[mi][1], af[mi][2], af[mi][3],
                      &Alo[wm * 64 + mi * 16 + ar][kk * 16 + ac8]);
            #pragma unroll
            for (int mi = 0; mi < 4; mi++)
                #pragma unroll
                for (int nj = 0; nj < 4; nj++) {
                    int ni = nj >> 1, pr = (nj & 1) << 1;
                    mma_f16(acc[mi][nj], af[mi], bf[ni][pr], bf[ni][pr + 1]);
                }
        }
        __syncthreads();
    }

    const int gid = lane >> 2, tig = lane & 3;
    #pragma unroll
    for (int mi = 0; mi < 4; mi++) {
        size_t r0 = m0 + wm * 64 + mi * 16 + gid;
        #pragma unroll
        for (int nj = 0; nj < 4; nj++) {
            size_t cc = n0 + wn * 32 + nj * 8 + tig * 2;
            *(float2*)(C + r0 * N + cc)       = make_float2(acc[mi][nj][0], acc[mi][nj][1]);
            *(float2*)(C + (r0 + 8) * N + cc) = make_float2(acc[mi][nj][2], acc[mi][nj][3]);
        }
    }
}

__global__ void __launch_bounds__(256) mm_qkp(const float* __restrict__ W) {
    gemm_mma_body<NTOK_P, 2*PD, PD, PD>(g_fl, W, g_qkp);
}
__global__ void __launch_bounds__(256) mm_pv(const float* __restrict__ W) {
    gemm_mma_body<NTOK_P, PD, PD, PD>(g_fl, W, g_pv);
}
__global__ void __launch_bounds__(256) mm_pfo(const float* __restrict__ W) {
    gemm_mma_body<NTOK_P, PD, PD, PD>(g_pf, W, g_pfo);
}
__global__ void __launch_bounds__(256) mm_qkw(const float* __restrict__ W) {
    gemm_mma_body<NTOK_W, 2*WIN_INNER, PLD, PLD>(g_plln, W, g_qkw);
}
__global__ void __launch_bounds__(256) mm_wv(const float* __restrict__ W) {
    gemm_mma_body<NTOK_W, WIN_INNER, WD, WD / WV_SPLITK>(g_lnxw, W, g_wv_part);
}
__global__ void __launch_bounds__(256) mm_wfo(const float* __restrict__ W) {
    gemm_mma_body<NTOK_W, WD, WIN_INNER, WIN_INNER>(g_wf, W, g_wfo);
}

// split-K reduction for wv (deterministic)
__global__ void kR_wv() {
    size_t i = (size_t)blockIdx.x * blockDim.x + threadIdx.x;
    if (i >= (size_t)NTOK_W * WIN_INNER) return;
    float s = 0.f;
    #pragma unroll
    for (int z = 0; z < WV_SPLITK; z++)
        s += g_wv_part[(size_t)z * NTOK_W * WIN_INNER + i];
    g_wv[i] = s;
}

// ---------------------------------------------------------------------------
// Block reduce
// ---------------------------------------------------------------------------
__device__ __forceinline__ float blockReduceSum(float v, float* sh) {
    int lane = threadIdx.x & 31, wid = threadIdx.x >> 5;
    #pragma unroll
    for (int o = 16; o > 0; o >>= 1) v += __shfl_down_sync(0xffffffffu, v, o);
    if (lane == 0) sh[wid] = v;
    __syncthreads();
    int nw = blockDim.x >> 5;
    v = (threadIdx.x < (unsigned)nw) ? sh[threadIdx.x] : 0.f;
    if (wid == 0) {
        #pragma unroll
        for (int o = 16; o > 0; o >>= 1) v += __shfl_down_sync(0xffffffffu, v, o);
        if (lane == 0) sh[0] = v;
    }
    __syncthreads();
    float r = sh[0];
    __syncthreads();
    return r;
}

// ---------------------------------------------------------------------------
// kA: gather patch token + LayerNorm -> g_fl
// ---------------------------------------------------------------------------
__global__ void kA_fl(const float* __restrict__ x,
                      const float* __restrict__ gam, const float* __restrict__ bet) {
    int t = blockIdx.x;
    int b = t >> 8, w = (t >> 4) & 15, p = t & 15;
    int wy = w >> 2, wx = w & 3, py = p >> 2, px = p & 3;
    int i0 = wy * WS + py * PS, j0 = wx * WS + px * PS;
    __shared__ float red[32];
    float vals[4], s = 0.f, s2 = 0.f;
    #pragma unroll
    for (int r = 0; r < 4; r++) {
        int d = threadIdx.x + r * 256;
        int sidx = d >> 4, c = d & 15;
        int sy = sidx >> 3, sx = sidx & 7;
        float v = x[(((size_t)b * CCH + c) * SZ + (i0 + sy)) * SZ + (j0 + sx)];
        vals[r] = v; s += v; s2 += v * v;
    }
    s  = blockReduceSum(s,  red);
    s2 = blockReduceSum(s2, red);
    float m  = s  * (1.f / PD);
    float rs = rsqrtf(s2 * (1.f / PD) - m * m + 1e-5f);
    #pragma unroll
    for (int r = 0; r < 4; r++) {
        int d = threadIdx.x + r * 256;
        g_fl[(size_t)t * PD + d] = (vals[r] - m) * rs * gam[d] + bet[d];
    }
}

// ---------------------------------------------------------------------------
// kB: patch attention + LePE conv, per (b,win,head)
// ---------------------------------------------------------------------------
__global__ void kB_pattn(const float* __restrict__ cw, const float* __restrict__ cb) {
    int bid = blockIdx.x;
    int h = bid & 7;
    size_t tb = (size_t)(bid >> 3) * NPAT;
    __shared__ float qs[NPAT][129], ks[NPAT][129], S[NPAT][NPAT];
    int tid = threadIdx.x;
    #pragma unroll
    for (int r = 0; r < 8; r++) {
        int idx = tid + r * 256;
        int p = idx >> 7, d = idx & 127;
        qs[p][d] = g_qkp[(tb + p) * (2 * PD) + h * PDH + d];
        ks[p][d] = g_qkp[(tb + p) * (2 * PD) + PD + h * PDH + d];
    }
    __syncthreads();
    {
        int p = tid >> 4, v = tid & 15;
        float acc = 0.f;
        #pragma unroll 8
        for (int d = 0; d < PDH; d++) acc += qs[p][d] * ks[v][d];
        S[p][v] = acc * ATT_SCALE;
    }
    __syncthreads();
    if (tid < NPAT) {
        float mx = -1e30f;
        #pragma unroll
        for (int v = 0; v < NPAT; v++) mx = fmaxf(mx, S[tid][v]);
        float e[NPAT], sum = 0.f;
        #pragma unroll
        for (int v = 0; v < NPAT; v++) { e[v] = __expf(S[tid][v] - mx); sum += e[v]; }
        float inv = 1.f / sum;
        #pragma unroll
        for (int v = 0; v < NPAT; v++) S[tid][v] = e[v] * inv;
    }
    __syncthreads();
    #pragma unroll
    for (int r = 0; r < 8; r++) {
        int idx = tid + r * 256;
        int p = idx >> 7, d = idx & 127;
        ks[p][d] = g_pv[(tb + p) * PD + h * PDH + d];
    }
    __syncthreads();
    #pragma unroll
    for (int r = 0; r < 8; r++) {
        int idx = tid + r * 256;
        int p = idx >> 7, d = idx & 127;
        float acc = 0.f;
        #pragma unroll
        for (int v = 0; v < NPAT; v++) acc += S[p][v] * ks[v][d];
        int py = p >> 2, px = p & 3;
        #pragma unroll
        for (int ky = 0; ky < 3; ky++) {
            int yy = py + ky - 1;
            if (yy < 0 || yy > 3) continue;
            #pragma unroll
            for (int kx = 0; kx < 3; kx++) {
                int xx = px + kx - 1;
                if (xx < 0 || xx > 3) continue;
                acc += cw[d * 9 + ky * 3 + kx] * ks[yy * 4 + xx][d];
            }
        }
        acc += cb[d];
        g_pf[(tb + p) * PD + h * PDH + d] = acc;
    }
}

// ---------------------------------------------------------------------------
// kC: 4x4 average pool + gather + LayerNorm -> g_plln
// ---------------------------------------------------------------------------
__global__ void kC_pl(const float* __restrict__ x,
                      const float* __restrict__ gam, const float* __restrict__ bet) {
    int t = blockIdx.x;
    int b = t >> 4, w = t & 15, wy = w >> 2, wx = w & 3;
    __shared__ float red[32];
    float vals[4], s = 0.f, s2 = 0.f;
    #pragma unroll
    for (int r = 0; r < 4; r++) {
        int d = threadIdx.x + r * 256;
        int uy = (d >> 4) >> 3, ux = (d >> 4) & 7, c = d & 15;
        int i0 = wy * WS + uy * 4, j0 = wx * WS + ux * 4;
        const float* xb = x + (((size_t)b * CCH + c) * SZ + i0) * SZ + j0;
        float acc = 0.f;
        #pragma unroll
        for (int a = 0; a < 4; a++)
            #pragma unroll
            for (int e = 0; e < 4; e++) acc += xb[a * SZ + e];
        float v = acc * (1.f / 16.f);
        vals[r] = v; s += v; s2 += v * v;
    }
    s  = blockReduceSum(s,  red);
    s2 = blockReduceSum(s2, red);
    float m  = s  * (1.f / PLD);
    float rs = rsqrtf(s2 * (1.f / PLD) - m * m + 1e-5f);
    #pragma unroll
    for (int r = 0; r < 4; r++) {
        int d = threadIdx.x + r * 256;
        g_plln[(size_t)t * PLD + d] = (vals[r] - m) * rs * gam[d] + bet[d];
    }
}

// ---------------------------------------------------------------------------
// kD: window attention scores + diag/non-diag rescale
// ---------------------------------------------------------------------------
__global__ void kD_wscores() {
    int bid = blockIdx.x;
    int h = bid & 7, b = bid >> 3;
    __shared__ float qs[NWIN][129], ks[NWIN][129], S[NWIN][NWIN];
    int tid = threadIdx.x;
    #pragma unroll
    for (int r = 0; r < 8; r++) {
        int idx = tid + r * 256;
        int n = idx >> 7, d = idx & 127;
        qs[n][d] = g_qkw[((size_t)b * NWIN + n) * (2 * WIN_INNER) + h * WDH + d];
        ks[n][d] = g_qkw[((size_t)b * NWIN + n) * (2 * WIN_INNER) + WIN_INNER + h * WDH + d];
    }
    __syncthreads();
    int n = tid >> 4, m = tid & 15;
    {
        float acc = 0.f;
        #pragma unroll 8
        for (int d = 0; d < WDH; d++) acc += qs[n][d] * ks[m][d];
        S[n][m] = acc * ATT_SCALE;
    }
    __syncthreads();
    if (tid < NWIN) {
        float mx = -1e30f;
        #pragma unroll
        for (int v = 0; v < NWIN; v++) mx = fmaxf(mx, S[tid][v]);
        float e[NWIN], sum = 0.f;
        #pragma unroll
        for (int v = 0; v < NWIN; v++) { e[v] = __expf(S[tid][v] - mx); sum += e[v]; }
        float inv = 1.f / sum;
        #pragma unroll
        for (int v = 0; v < NWIN; v++) S[tid][v] = e[v] * inv;
    }
    __syncthreads();
    float dn = S[n][n];
    bool line = dn < 0.5f;
    if (m == 0) g_ds[((size_t)b * NH + h) * NWIN + n] = line ? 0.5f : dn;
    float val = (m == n) ? 0.f : S[n][m];
    if (line) val *= 0.5f / (1.f - dn);
    g_nds[(((size_t)b * NH + h) * NWIN + n) * NWIN + m] = val;
}

// ---------------------------------------------------------------------------
// kE: window-pixel gather + LayerNorm over WD -> g_lnxw
// ---------------------------------------------------------------------------
__global__ void kE_lnxw(const float* __restrict__ x,
                        const float* __restrict__ gam, const float* __restrict__ bet) {
    int t = blockIdx.x;
    int b = t >> 4, w = t & 15, wy = w >> 2, wx = w & 3;
    __shared__ float red[32];
    float s = 0.f, s2 = 0.f;
    for (int r = 0; r < 64; r++) {
        int d = threadIdx.x + r * 256;
        int sidx = d >> 4, c = d & 15;
        int sy = sidx >> 5, sx = sidx & 31;
        float v = x[(((size_t)b * CCH + c) * SZ + (wy * WS + sy)) * SZ + (wx * WS + sx)];
        s += v; s2 += v * v;
    }
    s  = blockReduceSum(s,  red);
    s2 = blockReduceSum(s2, red);
    float m  = s  * (1.f / WD);
    float rs = rsqrtf(s2 * (1.f / WD) - m * m + 1e-5f);
    for (int r = 0; r < 64; r++) {
        int d = threadIdx.x + r * 256;
        int sidx = d >> 4, c = d & 15;
        int sy = sidx >> 5, sx = sidx & 31;
        float v = x[(((size_t)b * CCH + c) * SZ + (wy * WS + sy)) * SZ + (wx * WS + sx)];
        g_lnxw[(size_t)t * WD + d] = (v - m) * rs * gam[d] + bet[d];
    }
}

// ---------------------------------------------------------------------------
// kF: window value mixing with nds + LePE conv -> g_wf
// ---------------------------------------------------------------------------
__global__ void kF_wattn(const float* __restrict__ cw, const float* __restrict__ cb) {
    int bid = blockIdx.x;
    int h = bid & 7, b = bid >> 3;
    __shared__ float vs[NWIN][129], P[NWIN][NWIN];
    int tid = threadIdx.x;
    #pragma unroll
    for (int r = 0; r < 8; r++) {
        int idx = tid + r * 256;
        int n = idx >> 7, d = idx & 127;
        vs[n][d] = g_wv[((size_t)b * NWIN + n) * WIN_INNER + h * WDH + d];
    }
    {
        int n = tid >> 4, m = tid & 15;
        P[n][m] = g_nds[(((size_t)b * NH + h) * NWIN + n) * NWIN + m];
    }
    __syncthreads();
    #pragma unroll
    for (int r = 0; r < 8; r++) {
        int idx = tid + r * 256;
        int n = idx >> 7, d = idx & 127;
        float acc = 0.f;
        #pragma unroll
        for (int m = 0; m < NWIN; m++) acc += P[n][m] * vs[m][d];
        int wyy = n >> 2, wxx = n & 3;
        #pragma unroll
        for (int ky = 0; ky < 3; ky++) {
            int yy = wyy + ky - 1;
            if (yy < 0 || yy > 3) continue;
            #pragma unroll
            for (int kx = 0; kx < 3; kx++) {
                int xx = wxx + kx - 1;
                if (xx < 0 || xx > 3) continue;
                acc += cw[d * 9 + ky * 3 + kx] * vs[yy * 4 + xx][d];
            }
        }
        acc += cb[d];
        g_wf[((size_t)b * NWIN + n) * WIN_INNER + h * WDH + d] = acc;
    }
}

// ---------------------------------------------------------------------------
// kG: out = ds*pfo + wfo (scatter) + residual
// ---------------------------------------------------------------------------
__global__ void kG_out(const float* __restrict__ x, float* __restrict__ out) {
    size_t idx = (size_t)blockIdx.x * blockDim.x + threadIdx.x;
    if (idx >= (size_t)BATCH * CCH * SZ * SZ) return;
    int j = idx & 127;
    int i = (idx >> 7) & 127;
    int c = (idx >> 14) & 15;
    int b = (int)(idx >> 18);
    int wy = i >> 5, sy = i & 31, wx = j >> 5, sx = j & 31;
    int n = wy * 4 + wx;
    int wd = ((sy << 5) + sx) * 16 + c;
    int h = wd >> 11;
    size_t base = ((size_t)b * NWIN + n) * WD + wd;
    float v = g_ds[((size_t)b * NH + h) * NWIN + n] * g_pfo[base] + g_wfo[base] + x[idx];
    out[idx] = v;
}

// ---------------------------------------------------------------------------
// Launch: fork window branch onto a second stream; join before kG.
// ---------------------------------------------------------------------------
extern "C" void kernel_launch(void* const* d_in, const int* in_sizes, int n_in,
                              void* d_out, int out_size) {
    const float* x       = (const float*)d_in[0];
    const float* pn_g    = (const float*)d_in[1];
    const float* pn_b    = (const float*)d_in[2];
    const float* Wqk_p   = (const float*)d_in[3];
    const float* Wv_p    = (const float*)d_in[4];
    const float* conv_pw = (const float*)d_in[5];
    const float* conv_pb = (const float*)d_in[6];
    const float* Wout_p  = (const float*)d_in[7];
    const float* pln_g   = (const float*)d_in[8];
    const float* pln_b   = (const float*)d_in[9];
    const float* Wqk_w   = (const float*)d_in[10];
    const float* wn_g    = (const float*)d_in[11];
    const float* wn_b    = (const float*)d_in[12];
    const float* Wv_w    = (const float*)d_in[13];
    const float* conv_ww = (const float*)d_in[14];
    const float* conv_wb = (const float*)d_in[15];
    const float* Wout_w  = (const float*)d_in[16];
    float* out = (float*)d_out;

    // Fresh stream/events per call; NOT destroyed (destroy during graph
    // capture would invalidate the capture; call count is tiny).
    cudaStream_t s2;
    cudaStreamCreateWithFlags(&s2, cudaStreamNonBlocking);
    cudaEvent_t evFork, evJoin;
    cudaEventCreateWithFlags(&evFork, cudaEventDisableTiming);
    cudaEventCreateWithFlags(&evJoin, cudaEventDisableTiming);

    // fork
    cudaEventRecord(evFork, 0);
    cudaStreamWaitEvent(s2, evFork, 0);

    // --- window branch (stream s2) ---
    kC_pl<<<NTOK_W, 256, 0, s2>>>(x, pln_g, pln_b);
    mm_qkw<<<dim3((2*WIN_INNER)/128, NTOK_W/128), 256, 0, s2>>>(Wqk_w);
    kD_wscores<<<BATCH*NH, 256, 0, s2>>>();
    kE_lnxw<<<NTOK_W, 256, 0, s2>>>(x, wn_g, wn_b);
    mm_wv <<<dim3(WIN_INNER/128, NTOK_W/128, WV_SPLITK), 256, 0, s2>>>(Wv_w);
    kR_wv<<<(NTOK_W * WIN_INNER + 255) / 256, 256, 0, s2>>>();
    kF_wattn<<<BATCH*NH, 256, 0, s2>>>(conv_ww, conv_wb);
    mm_wfo<<<dim3(WD/128, NTOK_W/128), 256, 0, s2>>>(Wout_w);
    cudaEventRecord(evJoin, s2);

    // --- patch branch (default stream) ---
    kA_fl<<<NTOK_P, 256>>>(x, pn_g, pn_b);
    mm_qkp<<<dim3((2*PD)/128, NTOK_P/128), 256>>>(Wqk_p);
    mm_pv <<<dim3(PD/128,     NTOK_P/128), 256>>>(Wv_p);
    kB_pattn<<<BATCH*NWIN*NH, 256>>>(conv_pw, conv_pb);
    mm_pfo<<<dim3(PD/128,     NTOK_P/128), 256>>>(Wout_p);

    // join
    cudaStreamWaitEvent(0, evJoin, 0);

    // --- combine + residual ---
    size_t total = (size_t)BATCH * CCH * SZ * SZ;
    kG_out<<<(unsigned)((total + 255) / 256), 256>>>(x, out);
}

// round 11
// speedup vs baseline: 5.0531x; 1.1159x over previous
#include <cuda_runtime.h>
#include <cuda_fp16.h>
#include <cstdint>

// ---------------------------------------------------------------------------
// Problem dims (compile-time)
// ---------------------------------------------------------------------------
#define BATCH 64
#define CCH   16
#define SZ    128
#define WS    32
#define PS    8
#define NH    8
#define WN    4
#define PPW   4
#define NWIN  16
#define NPAT  16
#define PD    1024
#define PDH   128
#define PLD   1024
#define WDH   128
#define WIN_INNER 1024
#define WD    16384
#define NTOK_P (BATCH*NWIN*NPAT)   // 16384
#define NTOK_W (BATCH*NWIN)        // 1024
#define ATT_SCALE 0.08838834764831845f

#define WV_SPLITK 8

// ---------------------------------------------------------------------------
// Scratch (device globals) — EXACT R2/R7 set (known delta=0)
// ---------------------------------------------------------------------------
__device__ float g_fl  [(size_t)NTOK_P * PD];
__device__ float g_qkp [(size_t)NTOK_P * 2 * PD];
__device__ float g_pv  [(size_t)NTOK_P * PD];
__device__ float g_pf  [(size_t)NTOK_P * PD];
__device__ float g_pfo [(size_t)NTOK_P * PD];
__device__ float g_plln[(size_t)NTOK_W * PLD];
__device__ float g_qkw [(size_t)NTOK_W * 2 * WIN_INNER];
__device__ float g_nds [(size_t)BATCH * NH * NWIN * NWIN];
__device__ float g_ds  [(size_t)BATCH * NH * NWIN];
__device__ float g_lnxw[(size_t)NTOK_W * WD];
__device__ float g_wv  [(size_t)NTOK_W * WIN_INNER];
__device__ float g_wv_part[(size_t)WV_SPLITK * NTOK_W * WIN_INNER];
__device__ float g_wf  [(size_t)NTOK_W * WIN_INNER];
__device__ float g_wfo [(size_t)NTOK_W * WD];

// ---------------------------------------------------------------------------
// MMA helpers
// ---------------------------------------------------------------------------
__device__ __forceinline__ void ldsm4(uint32_t& r0, uint32_t& r1, uint32_t& r2,
                                      uint32_t& r3, const void* p) {
    uint32_t a = (uint32_t)__cvta_generic_to_shared(p);
    asm volatile("ldmatrix.sync.aligned.m8n8.x4.shared.b16 {%0,%1,%2,%3}, [%4];"
                 : "=r"(r0), "=r"(r1), "=r"(r2), "=r"(r3) : "r"(a));
}
__device__ __forceinline__ void ldsm4t(uint32_t& r0, uint32_t& r1, uint32_t& r2,
                                       uint32_t& r3, const void* p) {
    uint32_t a = (uint32_t)__cvta_generic_to_shared(p);
    asm volatile("ldmatrix.sync.aligned.m8n8.x4.trans.shared.b16 {%0,%1,%2,%3}, [%4];"
                 : "=r"(r0), "=r"(r1), "=r"(r2), "=r"(r3) : "r"(a));
}
__device__ __forceinline__ void mma_f16(float* c, const uint32_t* a, uint32_t b0, uint32_t b1) {
    asm volatile(
        "mma.sync.aligned.m16n8k16.row.col.f32.f16.f16.f32 "
        "{%0,%1,%2,%3},{%4,%5,%6,%7},{%8,%9},{%0,%1,%2,%3};"
        : "+f"(c[0]), "+f"(c[1]), "+f"(c[2]), "+f"(c[3])
        : "r"(a[0]), "r"(a[1]), "r"(a[2]), "r"(a[3]), "r"(b0), "r"(b1));
}

// fp32x4 -> single fp16 pair (RN)
__device__ __forceinline__ void cvt4(float4 v, uint2& h) {
    __half2 h01 = __floats2half2_rn(v.x, v.y);
    __half2 h23 = __floats2half2_rn(v.z, v.w);
    h.x = *reinterpret_cast<uint32_t*>(&h01);
    h.y = *reinterpret_cast<uint32_t*>(&h23);
}

// ---------------------------------------------------------------------------
// fp16 tensor-core GEMM (single-term): C = fp16(A) @ fp16(B), fp32 accum.
// R7/R9-proven shell: static smem, register prefetch, 128x128x32 tile,
// 256 threads, warp tile 64x32.
// ---------------------------------------------------------------------------
template<int M, int N, int K, int KC>
__device__ __forceinline__ void gemm_mma_body(const float* __restrict__ A,
                                              const float* __restrict__ B,
                                              float* __restrict__ Cbase) {
    constexpr int BM = 128, BN = 128, BK = 32;
    constexpr int APAD = 8, BPAD = 8;
    __shared__ __half Ah[BM][BK + APAD];
    __shared__ __half Bh[BK][BN + BPAD];

    const int tid  = threadIdx.x;
    const int lane = tid & 31;
    const int wid  = tid >> 5;
    const int wm   = wid & 1;
    const int wn   = wid >> 1;
    const size_t m0 = (size_t)blockIdx.y * BM;
    const size_t n0 = (size_t)blockIdx.x * BN;
    const int kc0 = blockIdx.z * KC;
    float* __restrict__ C = Cbase + (size_t)blockIdx.z * M * N;

    const float* Ab = A + m0 * K;
    const float* Bb = B + n0;

    float acc[4][4][4];
    #pragma unroll
    for (int i = 0; i < 4; i++)
        #pragma unroll
        for (int j = 0; j < 4; j++)
            #pragma unroll
            for (int e = 0; e < 4; e++) acc[i][j][e] = 0.f;

    const int ar  = lane & 15;
    const int ac8 = (lane >> 4) << 3;
    const int nIter = KC / BK;

    // prologue: prefetch first K-tile into registers
    float4 pa[4], pb[4];
    #pragma unroll
    for (int i = 0; i < 4; i++) {
        int q = tid + 256 * i;
        int row = q >> 3, col = (q & 7) << 2;
        pa[i] = *(const float4*)(Ab + (size_t)row * K + kc0 + col);
    }
    #pragma unroll
    for (int i = 0; i < 4; i++) {
        int q = tid + 256 * i;
        int row = q >> 5, col = (q & 31) << 2;
        pb[i] = *(const float4*)(Bb + (size_t)(kc0 + row) * N + col);
    }

    for (int it = 0; it < nIter; ++it) {
        // stage current tile
        #pragma unroll
        for (int i = 0; i < 4; i++) {
            int q = tid + 256 * i;
            int row = q >> 3, col = (q & 7) << 2;
            uint2 h;
            cvt4(pa[i], h);
            *(uint2*)&Ah[row][col] = h;
        }
        #pragma unroll
        for (int i = 0; i < 4; i++) {
            int q = tid + 256 * i;
            int row = q >> 5, col = (q & 31) << 2;
            uint2 h;
            cvt4(pb[i], h);
            *(uint2*)&Bh[row][col] = h;
        }
        __syncthreads();

        // prefetch next tile (LDGs in flight during compute)
        if (it + 1 < nIter) {
            int k0n = kc0 + (it + 1) * BK;
            #pragma unroll
            for (int i = 0; i < 4; i++) {
                int q = tid + 256 * i;
                int row = q >> 3, col = (q & 7) << 2;
                pa[i] = *(const float4*)(Ab + (size_t)row * K + k0n + col);
            }
            #pragma unroll
            for (int i = 0; i < 4; i++) {
                int q = tid + 256 * i;
                int row = q >> 5, col = (q & 31) << 2;
                pb[i] = *(const float4*)(Bb + (size_t)(k0n + row) * N + col);
            }
        }

        // compute
        #pragma unroll
        for (int kk = 0; kk < 2; kk++) {
            uint32_t af[4][4], bf[2][4];
            #pragma unroll
            for (int mi = 0; mi < 4; mi++)
                ldsm4(af[mi][0], af[mi][1], af[mi][2], af[mi][3],
                      &Ah[wm * 64 + mi * 16 + ar][kk * 16 + ac8]);
            #pragma unroll
            for (int ni = 0; ni < 2; ni++)
                ldsm4t(bf[ni][0], bf[ni][1], bf[ni][2], bf[ni][3],
                       &Bh[kk * 16 + ar][wn * 32 + ni * 16 + ac8]);
            #pragma unroll
            for (int mi = 0; mi < 4; mi++)
                #pragma unroll
                for (int nj = 0; nj < 4; nj++) {
                    int ni = nj >> 1, pr = (nj & 1) << 1;
                    mma_f16(acc[mi][nj], af[mi], bf[ni][pr], bf[ni][pr + 1]);
                }
        }
        __syncthreads();
    }

    const int gid = lane >> 2, tig = lane & 3;
    #pragma unroll
    for (int mi = 0; mi < 4; mi++) {
        size_t r0 = m0 + wm * 64 + mi * 16 + gid;
        #pragma unroll
        for (int nj = 0; nj < 4; nj++) {
            size_t cc = n0 + wn * 32 + nj * 8 + tig * 2;
            *(float2*)(C + r0 * N + cc)       = make_float2(acc[mi][nj][0], acc[mi][nj][1]);
            *(float2*)(C + (r0 + 8) * N + cc) = make_float2(acc[mi][nj][2], acc[mi][nj][3]);
        }
    }
}

__global__ void __launch_bounds__(256) mm_qkp(const float* __restrict__ W) {
    gemm_mma_body<NTOK_P, 2*PD, PD, PD>(g_fl, W, g_qkp);
}
__global__ void __launch_bounds__(256) mm_pv(const float* __restrict__ W) {
    gemm_mma_body<NTOK_P, PD, PD, PD>(g_fl, W, g_pv);
}
__global__ void __launch_bounds__(256) mm_pfo(const float* __restrict__ W) {
    gemm_mma_body<NTOK_P, PD, PD, PD>(g_pf, W, g_pfo);
}
__global__ void __launch_bounds__(256) mm_qkw(const float* __restrict__ W) {
    gemm_mma_body<NTOK_W, 2*WIN_INNER, PLD, PLD>(g_plln, W, g_qkw);
}
__global__ void __launch_bounds__(256) mm_wv(const float* __restrict__ W) {
    gemm_mma_body<NTOK_W, WIN_INNER, WD, WD / WV_SPLITK>(g_lnxw, W, g_wv_part);
}
__global__ void __launch_bounds__(256) mm_wfo(const float* __restrict__ W) {
    gemm_mma_body<NTOK_W, WD, WIN_INNER, WIN_INNER>(g_wf, W, g_wfo);
}

// split-K reduction for wv (deterministic)
__global__ void kR_wv() {
    size_t i = (size_t)blockIdx.x * blockDim.x + threadIdx.x;
    if (i >= (size_t)NTOK_W * WIN_INNER) return;
    float s = 0.f;
    #pragma unroll
    for (int z = 0; z < WV_SPLITK; z++)
        s += g_wv_part[(size_t)z * NTOK_W * WIN_INNER + i];
    g_wv[i] = s;
}

// ---------------------------------------------------------------------------
// Block reduce
// ---------------------------------------------------------------------------
__device__ __forceinline__ float blockReduceSum(float v, float* sh) {
    int lane = threadIdx.x & 31, wid = threadIdx.x >> 5;
    #pragma unroll
    for (int o = 16; o > 0; o >>= 1) v += __shfl_down_sync(0xffffffffu, v, o);
    if (lane == 0) sh[wid] = v;
    __syncthreads();
    int nw = blockDim.x >> 5;
    v = (threadIdx.x < (unsigned)nw) ? sh[threadIdx.x] : 0.f;
    if (wid == 0) {
        #pragma unroll
        for (int o = 16; o > 0; o >>= 1) v += __shfl_down_sync(0xffffffffu, v, o);
        if (lane == 0) sh[0] = v;
    }
    __syncthreads();
    float r = sh[0];
    __syncthreads();
    return r;
}

// ---------------------------------------------------------------------------
// kA: gather patch token + LayerNorm -> g_fl
// ---------------------------------------------------------------------------
__global__ void kA_fl(const float* __restrict__ x,
                      const float* __restrict__ gam, const float* __restrict__ bet) {
    int t = blockIdx.x;
    int b = t >> 8, w = (t >> 4) & 15, p = t & 15;
    int wy = w >> 2, wx = w & 3, py = p >> 2, px = p & 3;
    int i0 = wy * WS + py * PS, j0 = wx * WS + px * PS;
    __shared__ float red[32];
    float vals[4], s = 0.f, s2 = 0.f;
    #pragma unroll
    for (int r = 0; r < 4; r++) {
        int d = threadIdx.x + r * 256;
        int sidx = d >> 4, c = d & 15;
        int sy = sidx >> 3, sx = sidx & 7;
        float v = x[(((size_t)b * CCH + c) * SZ + (i0 + sy)) * SZ + (j0 + sx)];
        vals[r] = v; s += v; s2 += v * v;
    }
    s  = blockReduceSum(s,  red);
    s2 = blockReduceSum(s2, red);
    float m  = s  * (1.f / PD);
    float rs = rsqrtf(s2 * (1.f / PD) - m * m + 1e-5f);
    #pragma unroll
    for (int r = 0; r < 4; r++) {
        int d = threadIdx.x + r * 256;
        g_fl[(size_t)t * PD + d] = (vals[r] - m) * rs * gam[d] + bet[d];
    }
}

// ---------------------------------------------------------------------------
// kB: patch attention + LePE conv, per (b,win,head)
// ---------------------------------------------------------------------------
__global__ void kB_pattn(const float* __restrict__ cw, const float* __restrict__ cb) {
    int bid = blockIdx.x;
    int h = bid & 7;
    size_t tb = (size_t)(bid >> 3) * NPAT;
    __shared__ float qs[NPAT][129], ks[NPAT][129], S[NPAT][NPAT];
    int tid = threadIdx.x;
    #pragma unroll
    for (int r = 0; r < 8; r++) {
        int idx = tid + r * 256;
        int p = idx >> 7, d = idx & 127;
        qs[p][d] = g_qkp[(tb + p) * (2 * PD) + h * PDH + d];
        ks[p][d] = g_qkp[(tb + p) * (2 * PD) + PD + h * PDH + d];
    }
    __syncthreads();
    {
        int p = tid >> 4, v = tid & 15;
        float acc = 0.f;
        #pragma unroll 8
        for (int d = 0; d < PDH; d++) acc += qs[p][d] * ks[v][d];
        S[p][v] = acc * ATT_SCALE;
    }
    __syncthreads();
    if (tid < NPAT) {
        float mx = -1e30f;
        #pragma unroll
        for (int v = 0; v < NPAT; v++) mx = fmaxf(mx, S[tid][v]);
        float e[NPAT], sum = 0.f;
        #pragma unroll
        for (int v = 0; v < NPAT; v++) { e[v] = __expf(S[tid][v] - mx); sum += e[v]; }
        float inv = 1.f / sum;
        #pragma unroll
        for (int v = 0; v < NPAT; v++) S[tid][v] = e[v] * inv;
    }
    __syncthreads();
    #pragma unroll
    for (int r = 0; r < 8; r++) {
        int idx = tid + r * 256;
        int p = idx >> 7, d = idx & 127;
        ks[p][d] = g_pv[(tb + p) * PD + h * PDH + d];
    }
    __syncthreads();
    #pragma unroll
    for (int r = 0; r < 8; r++) {
        int idx = tid + r * 256;
        int p = idx >> 7, d = idx & 127;
        float acc = 0.f;
        #pragma unroll
        for (int v = 0; v < NPAT; v++) acc += S[p][v] * ks[v][d];
        int py = p >> 2, px = p & 3;
        #pragma unroll
        for (int ky = 0; ky < 3; ky++) {
            int yy = py + ky - 1;
            if (yy < 0 || yy > 3) continue;
            #pragma unroll
            for (int kx = 0; kx < 3; kx++) {
                int xx = px + kx - 1;
                if (xx < 0 || xx > 3) continue;
                acc += cw[d * 9 + ky * 3 + kx] * ks[yy * 4 + xx][d];
            }
        }
        acc += cb[d];
        g_pf[(tb + p) * PD + h * PDH + d] = acc;
    }
}

// ---------------------------------------------------------------------------
// kC: 4x4 average pool + gather + LayerNorm -> g_plln
// ---------------------------------------------------------------------------
__global__ void kC_pl(const float* __restrict__ x,
                      const float* __restrict__ gam, const float* __restrict__ bet) {
    int t = blockIdx.x;
    int b = t >> 4, w = t & 15, wy = w >> 2, wx = w & 3;
    __shared__ float red[32];
    float vals[4], s = 0.f, s2 = 0.f;
    #pragma unroll
    for (int r = 0; r < 4; r++) {
        int d = threadIdx.x + r * 256;
        int uy = (d >> 4) >> 3, ux = (d >> 4) & 7, c = d & 15;
        int i0 = wy * WS + uy * 4, j0 = wx * WS + ux * 4;
        const float* xb = x + (((size_t)b * CCH + c) * SZ + i0) * SZ + j0;
        float acc = 0.f;
        #pragma unroll
        for (int a = 0; a < 4; a++)
            #pragma unroll
            for (int e = 0; e < 4; e++) acc += xb[a * SZ + e];
        float v = acc * (1.f / 16.f);
        vals[r] = v; s += v; s2 += v * v;
    }
    s  = blockReduceSum(s,  red);
    s2 = blockReduceSum(s2, red);
    float m  = s  * (1.f / PLD);
    float rs = rsqrtf(s2 * (1.f / PLD) - m * m + 1e-5f);
    #pragma unroll
    for (int r = 0; r < 4; r++) {
        int d = threadIdx.x + r * 256;
        g_plln[(size_t)t * PLD + d] = (vals[r] - m) * rs * gam[d] + bet[d];
    }
}

// ---------------------------------------------------------------------------
// kD: window attention scores + diag/non-diag rescale
// ---------------------------------------------------------------------------
__global__ void kD_wscores() {
    int bid = blockIdx.x;
    int h = bid & 7, b = bid >> 3;
    __shared__ float qs[NWIN][129], ks[NWIN][129], S[NWIN][NWIN];
    int tid = threadIdx.x;
    #pragma unroll
    for (int r = 0; r < 8; r++) {
        int idx = tid + r * 256;
        int n = idx >> 7, d = idx & 127;
        qs[n][d] = g_qkw[((size_t)b * NWIN + n) * (2 * WIN_INNER) + h * WDH + d];
        ks[n][d] = g_qkw[((size_t)b * NWIN + n) * (2 * WIN_INNER) + WIN_INNER + h * WDH + d];
    }
    __syncthreads();
    int n = tid >> 4, m = tid & 15;
    {
        float acc = 0.f;
        #pragma unroll 8
        for (int d = 0; d < WDH; d++) acc += qs[n][d] * ks[m][d];
        S[n][m] = acc * ATT_SCALE;
    }
    __syncthreads();
    if (tid < NWIN) {
        float mx = -1e30f;
        #pragma unroll
        for (int v = 0; v < NWIN; v++) mx = fmaxf(mx, S[tid][v]);
        float e[NWIN], sum = 0.f;
        #pragma unroll
        for (int v = 0; v < NWIN; v++) { e[v] = __expf(S[tid][v] - mx); sum += e[v]; }
        float inv = 1.f / sum;
        #pragma unroll
        for (int v = 0; v < NWIN; v++) S[tid][v] = e[v] * inv;
    }
    __syncthreads();
    float dn = S[n][n];
    bool line = dn < 0.5f;
    if (m == 0) g_ds[((size_t)b * NH + h) * NWIN + n] = line ? 0.5f : dn;
    float val = (m == n) ? 0.f : S[n][m];
    if (line) val *= 0.5f / (1.f - dn);
    g_nds[(((size_t)b * NH + h) * NWIN + n) * NWIN + m] = val;
}

// ---------------------------------------------------------------------------
// kE: window-pixel gather + LayerNorm over WD -> g_lnxw
// ---------------------------------------------------------------------------
__global__ void kE_lnxw(const float* __restrict__ x,
                        const float* __restrict__ gam, const float* __restrict__ bet) {
    int t = blockIdx.x;
    int b = t >> 4, w = t & 15, wy = w >> 2, wx = w & 3;
    __shared__ float red[32];
    float s = 0.f, s2 = 0.f;
    for (int r = 0; r < 64; r++) {
        int d = threadIdx.x + r * 256;
        int sidx = d >> 4, c = d & 15;
        int sy = sidx >> 5, sx = sidx & 31;
        float v = x[(((size_t)b * CCH + c) * SZ + (wy * WS + sy)) * SZ + (wx * WS + sx)];
        s += v; s2 += v * v;
    }
    s  = blockReduceSum(s,  red);
    s2 = blockReduceSum(s2, red);
    float m  = s  * (1.f / WD);
    float rs = rsqrtf(s2 * (1.f / WD) - m * m + 1e-5f);
    for (int r = 0; r < 64; r++) {
        int d = threadIdx.x + r * 256;
        int sidx = d >> 4, c = d & 15;
        int sy = sidx >> 5, sx = sidx & 31;
        float v = x[(((size_t)b * CCH + c) * SZ + (wy * WS + sy)) * SZ + (wx * WS + sx)];
        g_lnxw[(size_t)t * WD + d] = (v - m) * rs * gam[d] + bet[d];
    }
}

// ---------------------------------------------------------------------------
// kF: window value mixing with nds + LePE conv -> g_wf
// ---------------------------------------------------------------------------
__global__ void kF_wattn(const float* __restrict__ cw, const float* __restrict__ cb) {
    int bid = blockIdx.x;
    int h = bid & 7, b = bid >> 3;
    __shared__ float vs[NWIN][129], P[NWIN][NWIN];
    int tid = threadIdx.x;
    #pragma unroll
    for (int r = 0; r < 8; r++) {
        int idx = tid + r * 256;
        int n = idx >> 7, d = idx & 127;
        vs[n][d] = g_wv[((size_t)b * NWIN + n) * WIN_INNER + h * WDH + d];
    }
    {
        int n = tid >> 4, m = tid & 15;
        P[n][m] = g_nds[(((size_t)b * NH + h) * NWIN + n) * NWIN + m];
    }
    __syncthreads();
    #pragma unroll
    for (int r = 0; r < 8; r++) {
        int idx = tid + r * 256;
        int n = idx >> 7, d = idx & 127;
        float acc = 0.f;
        #pragma unroll
        for (int m = 0; m < NWIN; m++) acc += P[n][m] * vs[m][d];
        int wyy = n >> 2, wxx = n & 3;
        #pragma unroll
        for (int ky = 0; ky < 3; ky++) {
            int yy = wyy + ky - 1;
            if (yy < 0 || yy > 3) continue;
            #pragma unroll
            for (int kx = 0; kx < 3; kx++) {
                int xx = wxx + kx - 1;
                if (xx < 0 || xx > 3) continue;
                acc += cw[d * 9 + ky * 3 + kx] * vs[yy * 4 + xx][d];
            }
        }
        acc += cb[d];
        g_wf[((size_t)b * NWIN + n) * WIN_INNER + h * WDH + d] = acc;
    }
}

// ---------------------------------------------------------------------------
// kG: out = ds*pfo + wfo (scatter) + residual
// ---------------------------------------------------------------------------
__global__ void kG_out(const float* __restrict__ x, float* __restrict__ out) {
    size_t idx = (size_t)blockIdx.x * blockDim.x + threadIdx.x;
    if (idx >= (size_t)BATCH * CCH * SZ * SZ) return;
    int j = idx & 127;
    int i = (idx >> 7) & 127;
    int c = (idx >> 14) & 15;
    int b = (int)(idx >> 18);
    int wy = i >> 5, sy = i & 31, wx = j >> 5, sx = j & 31;
    int n = wy * 4 + wx;
    int wd = ((sy << 5) + sx) * 16 + c;
    int h = wd >> 11;
    size_t base = ((size_t)b * NWIN + n) * WD + wd;
    float v = g_ds[((size_t)b * NH + h) * NWIN + n] * g_pfo[base] + g_wfo[base] + x[idx];
    out[idx] = v;
}

// ---------------------------------------------------------------------------
// Launch: fork window branch onto a second stream; join before kG.
// ---------------------------------------------------------------------------
extern "C" void kernel_launch(void* const* d_in, const int* in_sizes, int n_in,
                              void* d_out, int out_size) {
    const float* x       = (const float*)d_in[0];
    const float* pn_g    = (const float*)d_in[1];
    const float* pn_b    = (const float*)d_in[2];
    const float* Wqk_p   = (const float*)d_in[3];
    const float* Wv_p    = (const float*)d_in[4];
    const float* conv_pw = (const float*)d_in[5];
    const float* conv_pb = (const float*)d_in[6];
    const float* Wout_p  = (const float*)d_in[7];
    const float* pln_g   = (const float*)d_in[8];
    const float* pln_b   = (const float*)d_in[9];
    const float* Wqk_w   = (const float*)d_in[10];
    const float* wn_g    = (const float*)d_in[11];
    const float* wn_b    = (const float*)d_in[12];
    const float* Wv_w    = (const float*)d_in[13];
    const float* conv_ww = (const float*)d_in[14];
    const float* conv_wb = (const float*)d_in[15];
    const float* Wout_w  = (const float*)d_in[16];
    float* out = (float*)d_out;

    // Fresh stream/events per call; NOT destroyed (destroy during graph
    // capture would invalidate the capture; call count is tiny).
    cudaStream_t s2;
    cudaStreamCreateWithFlags(&s2, cudaStreamNonBlocking);
    cudaEvent_t evFork, evJoin;
    cudaEventCreateWithFlags(&evFork, cudaEventDisableTiming);
    cudaEventCreateWithFlags(&evJoin, cudaEventDisableTiming);

    // fork
    cudaEventRecord(evFork, 0);
    cudaStreamWaitEvent(s2, evFork, 0);

    // --- window branch (stream s2) ---
    kC_pl<<<NTOK_W, 256, 0, s2>>>(x, pln_g, pln_b);
    mm_qkw<<<dim3((2*WIN_INNER)/128, NTOK_W/128), 256, 0, s2>>>(Wqk_w);
    kD_wscores<<<BATCH*NH, 256, 0, s2>>>();
    kE_lnxw<<<NTOK_W, 256, 0, s2>>>(x, wn_g, wn_b);
    mm_wv <<<dim3(WIN_INNER/128, NTOK_W/128, WV_SPLITK), 256, 0, s2>>>(Wv_w);
    kR_wv<<<(NTOK_W * WIN_INNER + 255) / 256, 256, 0, s2>>>();
    kF_wattn<<<BATCH*NH, 256, 0, s2>>>(conv_ww, conv_wb);
    mm_wfo<<<dim3(WD/128, NTOK_W/128), 256, 0, s2>>>(Wout_w);
    cudaEventRecord(evJoin, s2);

    // --- patch branch (default stream) ---
    kA_fl<<<NTOK_P, 256>>>(x, pn_g, pn_b);
    mm_qkp<<<dim3((2*PD)/128, NTOK_P/128), 256>>>(Wqk_p);
    mm_pv <<<dim3(PD/128,     NTOK_P/128), 256>>>(Wv_p);
    kB_pattn<<<BATCH*NWIN*NH, 256>>>(conv_pw, conv_pb);
    mm_pfo<<<dim3(PD/128,     NTOK_P/128), 256>>>(Wout_p);

    // join
    cudaStreamWaitEvent(0, evJoin, 0);

    // --- combine + residual ---
    size_t total = (size_t)BATCH * CCH * SZ * SZ;
    kG_out<<<(unsigned)((total + 255) / 256), 256>>>(x, out);
}

// round 12
// speedup vs baseline: 5.4621x; 1.0809x over previous
#include <cuda_runtime.h>
#include <cuda_fp16.h>
#include <cstdint>

// ---------------------------------------------------------------------------
// Problem dims (compile-time)
// ---------------------------------------------------------------------------
#define BATCH 64
#define CCH   16
#define SZ    128
#define WS    32
#define PS    8
#define NH    8
#define WN    4
#define PPW   4
#define NWIN  16
#define NPAT  16
#define PD    1024
#define PDH   128
#define PLD   1024
#define WDH   128
#define WIN_INNER 1024
#define WD    16384
#define NTOK_P (BATCH*NWIN*NPAT)   // 16384
#define NTOK_W (BATCH*NWIN)        // 1024
#define ATT_SCALE 0.08838834764831845f

#define WV_SPLITK 8

// ---------------------------------------------------------------------------
// Scratch (device globals) — EXACT R2/R7 set (known delta=0).
// NOTE: g_fl, g_pf, g_plln, g_lnxw, g_wf are *declared* fp32 but now hold
// fp16 values (written via (__half*) casts by their producers; consumed only
// by the GEMMs). Same buffers, half the bytes used — no new allocations.
// ---------------------------------------------------------------------------
__device__ float g_fl  [(size_t)NTOK_P * PD];
__device__ float g_qkp [(size_t)NTOK_P * 2 * PD];
__device__ float g_pv  [(size_t)NTOK_P * PD];
__device__ float g_pf  [(size_t)NTOK_P * PD];
__device__ float g_pfo [(size_t)NTOK_P * PD];
__device__ float g_plln[(size_t)NTOK_W * PLD];
__device__ float g_qkw [(size_t)NTOK_W * 2 * WIN_INNER];
__device__ float g_nds [(size_t)BATCH * NH * NWIN * NWIN];
__device__ float g_ds  [(size_t)BATCH * NH * NWIN];
__device__ float g_lnxw[(size_t)NTOK_W * WD];
__device__ float g_wv  [(size_t)NTOK_W * WIN_INNER];
__device__ float g_wv_part[(size_t)WV_SPLITK * NTOK_W * WIN_INNER];
__device__ float g_wf  [(size_t)NTOK_W * WIN_INNER];
__device__ float g_wfo [(size_t)NTOK_W * WD];

// ---------------------------------------------------------------------------
// MMA helpers
// ---------------------------------------------------------------------------
__device__ __forceinline__ void ldsm4(uint32_t& r0, uint32_t& r1, uint32_t& r2,
                                      uint32_t& r3, const void* p) {
    uint32_t a = (uint32_t)__cvta_generic_to_shared(p);
    asm volatile("ldmatrix.sync.aligned.m8n8.x4.shared.b16 {%0,%1,%2,%3}, [%4];"
                 : "=r"(r0), "=r"(r1), "=r"(r2), "=r"(r3) : "r"(a));
}
__device__ __forceinline__ void ldsm4t(uint32_t& r0, uint32_t& r1, uint32_t& r2,
                                       uint32_t& r3, const void* p) {
    uint32_t a = (uint32_t)__cvta_generic_to_shared(p);
    asm volatile("ldmatrix.sync.aligned.m8n8.x4.trans.shared.b16 {%0,%1,%2,%3}, [%4];"
                 : "=r"(r0), "=r"(r1), "=r"(r2), "=r"(r3) : "r"(a));
}
__device__ __forceinline__ void mma_f16(float* c, const uint32_t* a, uint32_t b0, uint32_t b1) {
    asm volatile(
        "mma.sync.aligned.m16n8k16.row.col.f32.f16.f16.f32 "
        "{%0,%1,%2,%3},{%4,%5,%6,%7},{%8,%9},{%0,%1,%2,%3};"
        : "+f"(c[0]), "+f"(c[1]), "+f"(c[2]), "+f"(c[3])
        : "r"(a[0]), "r"(a[1]), "r"(a[2]), "r"(a[3]), "r"(b0), "r"(b1));
}

// fp32x4 -> single fp16 pair (RN) — for B (weights)
__device__ __forceinline__ void cvt4(float4 v, uint2& h) {
    __half2 h01 = __floats2half2_rn(v.x, v.y);
    __half2 h23 = __floats2half2_rn(v.z, v.w);
    h.x = *reinterpret_cast<uint32_t*>(&h01);
    h.y = *reinterpret_cast<uint32_t*>(&h23);
}

// ---------------------------------------------------------------------------
// fp16 tensor-core GEMM: C = A(fp16) @ fp16(B), fp32 accum.
// A arrives as fp16 (producer-rounded); B is fp32 with inline cvt.
// Double-buffered smem: stage(s) -> sync -> prefetch(next) -> MMA(s).
// 128x128x32 tile, 256 threads, warp tile 64x32.
// ---------------------------------------------------------------------------
template<int M, int N, int K, int KC>
__device__ __forceinline__ void gemm_mma_body(const __half* __restrict__ A,
                                              const float* __restrict__ B,
                                              float* __restrict__ Cbase) {
    constexpr int BM = 128, BN = 128, BK = 32;
    constexpr int APAD = 8, BPAD = 8;
    __shared__ __half Ah[2][BM][BK + APAD];   // 2 * 10240 B
    __shared__ __half Bh[2][BK][BN + BPAD];   // 2 * 8704 B

    const int tid  = threadIdx.x;
    const int lane = tid & 31;
    const int wid  = tid >> 5;
    const int wm   = wid & 1;
    const int wn   = wid >> 1;
    const size_t m0 = (size_t)blockIdx.y * BM;
    const size_t n0 = (size_t)blockIdx.x * BN;
    const int kc0 = blockIdx.z * KC;
    float* __restrict__ C = Cbase + (size_t)blockIdx.z * M * N;

    const __half* Abp = A + m0 * K;
    const float*  Bbp = B + n0;

    float acc[4][4][4];
    #pragma unroll
    for (int i = 0; i < 4; i++)
        #pragma unroll
        for (int j = 0; j < 4; j++)
            #pragma unroll
            for (int e = 0; e < 4; e++) acc[i][j][e] = 0.f;

    const int ar  = lane & 15;
    const int ac8 = (lane >> 4) << 3;
    const int nIter = KC / BK;

    // A load mapping: 128 rows x 32 halves = 512 x 16B; 2 chunks/thread
    const int a_row = tid >> 1;            // q>>2 with q=tid+256i -> rows interleave
    // (use generic q-derived mapping below instead)

    // register prefetch buffers
    uint4  pa[2];
    float4 pb[4];

    // prologue: load tile 0 into regs
    #pragma unroll
    for (int i = 0; i < 2; i++) {
        int q = tid + 256 * i;
        int row = q >> 2, c8 = (q & 3) * 8;
        pa[i] = *(const uint4*)(Abp + (size_t)row * K + kc0 + c8);
    }
    #pragma unroll
    for (int i = 0; i < 4; i++) {
        int q = tid + 256 * i;
        int row = q >> 5, col = (q & 31) << 2;
        pb[i] = *(const float4*)(Bbp + (size_t)(kc0 + row) * N + col);
    }

    for (int it = 0; it < nIter; ++it) {
        const int s = it & 1;
        // stage current tile into buffer s
        #pragma unroll
        for (int i = 0; i < 2; i++) {
            int q = tid + 256 * i;
            int row = q >> 2, c8 = (q & 3) * 8;
            *(uint4*)&Ah[s][row][c8] = pa[i];
        }
        #pragma unroll
        for (int i = 0; i < 4; i++) {
            int q = tid + 256 * i;
            int row = q >> 5, col = (q & 31) << 2;
            uint2 h;
            cvt4(pb[i], h);
            *(uint2*)&Bh[s][row][col] = h;
        }
        __syncthreads();

        // prefetch next tile into regs (LDGs in flight during MMA)
        if (it + 1 < nIter) {
            int k0n = kc0 + (it + 1) * BK;
            #pragma unroll
            for (int i = 0; i < 2; i++) {
                int q = tid + 256 * i;
                int row = q >> 2, c8 = (q & 3) * 8;
                pa[i] = *(const uint4*)(Abp + (size_t)row * K + k0n + c8);
            }
            #pragma unroll
            for (int i = 0; i < 4; i++) {
                int q = tid + 256 * i;
                int row = q >> 5, col = (q & 31) << 2;
                pb[i] = *(const float4*)(Bbp + (size_t)(k0n + row) * N + col);
            }
        }

        // compute on buffer s (next iteration stages buffer s^1 — no tail sync)
        #pragma unroll
        for (int kk = 0; kk < 2; kk++) {
            uint32_t af[4][4], bf[2][4];
            #pragma unroll
            for (int mi = 0; mi < 4; mi++)
                ldsm4(af[mi][0], af[mi][1], af[mi][2], af[mi][3],
                      &Ah[s][wm * 64 + mi * 16 + ar][kk * 16 + ac8]);
            #pragma unroll
            for (int ni = 0; ni < 2; ni++)
                ldsm4t(bf[ni][0], bf[ni][1], bf[ni][2], bf[ni][3],
                       &Bh[s][kk * 16 + ar][wn * 32 + ni * 16 + ac8]);
            #pragma unroll
            for (int mi = 0; mi < 4; mi++)
                #pragma unroll
                for (int nj = 0; nj < 4; nj++) {
                    int ni = nj >> 1, pr = (nj & 1) << 1;
                    mma_f16(acc[mi][nj], af[mi], bf[ni][pr], bf[ni][pr + 1]);
                }
        }
    }

    const int gid = lane >> 2, tig = lane & 3;
    #pragma unroll
    for (int mi = 0; mi < 4; mi++) {
        size_t r0 = m0 + wm * 64 + mi * 16 + gid;
        #pragma unroll
        for (int nj = 0; nj < 4; nj++) {
            size_t cc = n0 + wn * 32 + nj * 8 + tig * 2;
            *(float2*)(C + r0 * N + cc)       = make_float2(acc[mi][nj][0], acc[mi][nj][1]);
            *(float2*)(C + (r0 + 8) * N + cc) = make_float2(acc[mi][nj][2], acc[mi][nj][3]);
        }
    }
}

__global__ void __launch_bounds__(256) mm_qkp(const float* __restrict__ W) {
    gemm_mma_body<NTOK_P, 2*PD, PD, PD>((const __half*)g_fl, W, g_qkp);
}
__global__ void __launch_bounds__(256) mm_pv(const float* __restrict__ W) {
    gemm_mma_body<NTOK_P, PD, PD, PD>((const __half*)g_fl, W, g_pv);
}
__global__ void __launch_bounds__(256) mm_pfo(const float* __restrict__ W) {
    gemm_mma_body<NTOK_P, PD, PD, PD>((const __half*)g_pf, W, g_pfo);
}
__global__ void __launch_bounds__(256) mm_qkw(const float* __restrict__ W) {
    gemm_mma_body<NTOK_W, 2*WIN_INNER, PLD, PLD>((const __half*)g_plln, W, g_qkw);
}
__global__ void __launch_bounds__(256) mm_wv(const float* __restrict__ W) {
    gemm_mma_body<NTOK_W, WIN_INNER, WD, WD / WV_SPLITK>((const __half*)g_lnxw, W, g_wv_part);
}
__global__ void __launch_bounds__(256) mm_wfo(const float* __restrict__ W) {
    gemm_mma_body<NTOK_W, WD, WIN_INNER, WIN_INNER>((const __half*)g_wf, W, g_wfo);
}

// split-K reduction for wv (deterministic)
__global__ void kR_wv() {
    size_t i = (size_t)blockIdx.x * blockDim.x + threadIdx.x;
    if (i >= (size_t)NTOK_W * WIN_INNER) return;
    float s = 0.f;
    #pragma unroll
    for (int z = 0; z < WV_SPLITK; z++)
        s += g_wv_part[(size_t)z * NTOK_W * WIN_INNER + i];
    g_wv[i] = s;
}

// ---------------------------------------------------------------------------
// Block reduce
// ---------------------------------------------------------------------------
__device__ __forceinline__ float blockReduceSum(float v, float* sh) {
    int lane = threadIdx.x & 31, wid = threadIdx.x >> 5;
    #pragma unroll
    for (int o = 16; o > 0; o >>= 1) v += __shfl_down_sync(0xffffffffu, v, o);
    if (lane == 0) sh[wid] = v;
    __syncthreads();
    int nw = blockDim.x >> 5;
    v = (threadIdx.x < (unsigned)nw) ? sh[threadIdx.x] : 0.f;
    if (wid == 0) {
        #pragma unroll
        for (int o = 16; o > 0; o >>= 1) v += __shfl_down_sync(0xffffffffu, v, o);
        if (lane == 0) sh[0] = v;
    }
    __syncthreads();
    float r = sh[0];
    __syncthreads();
    return r;
}

// ---------------------------------------------------------------------------
// kA: gather patch token + LayerNorm -> g_fl (fp16 in-place)
// ---------------------------------------------------------------------------
__global__ void kA_fl(const float* __restrict__ x,
                      const float* __restrict__ gam, const float* __restrict__ bet) {
    int t = blockIdx.x;
    int b = t >> 8, w = (t >> 4) & 15, p = t & 15;
    int wy = w >> 2, wx = w & 3, py = p >> 2, px = p & 3;
    int i0 = wy * WS + py * PS, j0 = wx * WS + px * PS;
    __shared__ float red[32];
    float vals[4], s = 0.f, s2 = 0.f;
    #pragma unroll
    for (int r = 0; r < 4; r++) {
        int d = threadIdx.x + r * 256;
        int sidx = d >> 4, c = d & 15;
        int sy = sidx >> 3, sx = sidx & 7;
        float v = x[(((size_t)b * CCH + c) * SZ + (i0 + sy)) * SZ + (j0 + sx)];
        vals[r] = v; s += v; s2 += v * v;
    }
    s  = blockReduceSum(s,  red);
    s2 = blockReduceSum(s2, red);
    float m  = s  * (1.f / PD);
    float rs = rsqrtf(s2 * (1.f / PD) - m * m + 1e-5f);
    __half* out = (__half*)g_fl;
    #pragma unroll
    for (int r = 0; r < 4; r++) {
        int d = threadIdx.x + r * 256;
        float v = (vals[r] - m) * rs * gam[d] + bet[d];
        out[(size_t)t * PD + d] = __float2half_rn(v);
    }
}

// ---------------------------------------------------------------------------
// kB: patch attention + LePE conv -> g_pf (fp16 in-place)
// ---------------------------------------------------------------------------
__global__ void kB_pattn(const float* __restrict__ cw, const float* __restrict__ cb) {
    int bid = blockIdx.x;
    int h = bid & 7;
    size_t tb = (size_t)(bid >> 3) * NPAT;
    __shared__ float qs[NPAT][129], ks[NPAT][129], S[NPAT][NPAT];
    int tid = threadIdx.x;
    #pragma unroll
    for (int r = 0; r < 8; r++) {
        int idx = tid + r * 256;
        int p = idx >> 7, d = idx & 127;
        qs[p][d] = g_qkp[(tb + p) * (2 * PD) + h * PDH + d];
        ks[p][d] = g_qkp[(tb + p) * (2 * PD) + PD + h * PDH + d];
    }
    __syncthreads();
    {
        int p = tid >> 4, v = tid & 15;
        float acc = 0.f;
        #pragma unroll 8
        for (int d = 0; d < PDH; d++) acc += qs[p][d] * ks[v][d];
        S[p][v] = acc * ATT_SCALE;
    }
    __syncthreads();
    if (tid < NPAT) {
        float mx = -1e30f;
        #pragma unroll
        for (int v = 0; v < NPAT; v++) mx = fmaxf(mx, S[tid][v]);
        float e[NPAT], sum = 0.f;
        #pragma unroll
        for (int v = 0; v < NPAT; v++) { e[v] = __expf(S[tid][v] - mx); sum += e[v]; }
        float inv = 1.f / sum;
        #pragma unroll
        for (int v = 0; v < NPAT; v++) S[tid][v] = e[v] * inv;
    }
    __syncthreads();
    #pragma unroll
    for (int r = 0; r < 8; r++) {
        int idx = tid + r * 256;
        int p = idx >> 7, d = idx & 127;
        ks[p][d] = g_pv[(tb + p) * PD + h * PDH + d];
    }
    __syncthreads();
    __half* out = (__half*)g_pf;
    #pragma unroll
    for (int r = 0; r < 8; r++) {
        int idx = tid + r * 256;
        int p = idx >> 7, d = idx & 127;
        float acc = 0.f;
        #pragma unroll
        for (int v = 0; v < NPAT; v++) acc += S[p][v] * ks[v][d];
        int py = p >> 2, px = p & 3;
        #pragma unroll
        for (int ky = 0; ky < 3; ky++) {
            int yy = py + ky - 1;
            if (yy < 0 || yy > 3) continue;
            #pragma unroll
            for (int kx = 0; kx < 3; kx++) {
                int xx = px + kx - 1;
                if (xx < 0 || xx > 3) continue;
                acc += cw[d * 9 + ky * 3 + kx] * ks[yy * 4 + xx][d];
            }
        }
        acc += cb[d];
        out[(tb + p) * PD + h * PDH + d] = __float2half_rn(acc);
    }
}

// ---------------------------------------------------------------------------
// kC: 4x4 average pool + gather + LayerNorm -> g_plln (fp16 in-place)
// ---------------------------------------------------------------------------
__global__ void kC_pl(const float* __restrict__ x,
                      const float* __restrict__ gam, const float* __restrict__ bet) {
    int t = blockIdx.x;
    int b = t >> 4, w = t & 15, wy = w >> 2, wx = w & 3;
    __shared__ float red[32];
    float vals[4], s = 0.f, s2 = 0.f;
    #pragma unroll
    for (int r = 0; r < 4; r++) {
        int d = threadIdx.x + r * 256;
        int uy = (d >> 4) >> 3, ux = (d >> 4) & 7, c = d & 15;
        int i0 = wy * WS + uy * 4, j0 = wx * WS + ux * 4;
        const float* xb = x + (((size_t)b * CCH + c) * SZ + i0) * SZ + j0;
        float acc = 0.f;
        #pragma unroll
        for (int a = 0; a < 4; a++)
            #pragma unroll
            for (int e = 0; e < 4; e++) acc += xb[a * SZ + e];
        float v = acc * (1.f / 16.f);
        vals[r] = v; s += v; s2 += v * v;
    }
    s  = blockReduceSum(s,  red);
    s2 = blockReduceSum(s2, red);
    float m  = s  * (1.f / PLD);
    float rs = rsqrtf(s2 * (1.f / PLD) - m * m + 1e-5f);
    __half* out = (__half*)g_plln;
    #pragma unroll
    for (int r = 0; r < 4; r++) {
        int d = threadIdx.x + r * 256;
        float v = (vals[r] - m) * rs * gam[d] + bet[d];
        out[(size_t)t * PLD + d] = __float2half_rn(v);
    }
}

// ---------------------------------------------------------------------------
// kD: window attention scores + diag/non-diag rescale
// ---------------------------------------------------------------------------
__global__ void kD_wscores() {
    int bid = blockIdx.x;
    int h = bid & 7, b = bid >> 3;
    __shared__ float qs[NWIN][129], ks[NWIN][129], S[NWIN][NWIN];
    int tid = threadIdx.x;
    #pragma unroll
    for (int r = 0; r < 8; r++) {
        int idx = tid + r * 256;
        int n = idx >> 7, d = idx & 127;
        qs[n][d] = g_qkw[((size_t)b * NWIN + n) * (2 * WIN_INNER) + h * WDH + d];
        ks[n][d] = g_qkw[((size_t)b * NWIN + n) * (2 * WIN_INNER) + WIN_INNER + h * WDH + d];
    }
    __syncthreads();
    int n = tid >> 4, m = tid & 15;
    {
        float acc = 0.f;
        #pragma unroll 8
        for (int d = 0; d < WDH; d++) acc += qs[n][d] * ks[m][d];
        S[n][m] = acc * ATT_SCALE;
    }
    __syncthreads();
    if (tid < NWIN) {
        float mx = -1e30f;
        #pragma unroll
        for (int v = 0; v < NWIN; v++) mx = fmaxf(mx, S[tid][v]);
        float e[NWIN], sum = 0.f;
        #pragma unroll
        for (int v = 0; v < NWIN; v++) { e[v] = __expf(S[tid][v] - mx); sum += e[v]; }
        float inv = 1.f / sum;
        #pragma unroll
        for (int v = 0; v < NWIN; v++) S[tid][v] = e[v] * inv;
    }
    __syncthreads();
    float dn = S[n][n];
    bool line = dn < 0.5f;
    if (m == 0) g_ds[((size_t)b * NH + h) * NWIN + n] = line ? 0.5f : dn;
    float val = (m == n) ? 0.f : S[n][m];
    if (line) val *= 0.5f / (1.f - dn);
    g_nds[(((size_t)b * NH + h) * NWIN + n) * NWIN + m] = val;
}

// ---------------------------------------------------------------------------
// kE: window-pixel gather + LayerNorm over WD -> g_lnxw (fp16 in-place)
// ---------------------------------------------------------------------------
__global__ void kE_lnxw(const float* __restrict__ x,
                        const float* __restrict__ gam, const float* __restrict__ bet) {
    int t = blockIdx.x;
    int b = t >> 4, w = t & 15, wy = w >> 2, wx = w & 3;
    __shared__ float red[32];
    float s = 0.f, s2 = 0.f;
    for (int r = 0; r < 64; r++) {
        int d = threadIdx.x + r * 256;
        int sidx = d >> 4, c = d & 15;
        int sy = sidx >> 5, sx = sidx & 31;
        float v = x[(((size_t)b * CCH + c) * SZ + (wy * WS + sy)) * SZ + (wx * WS + sx)];
        s += v; s2 += v * v;
    }
    s  = blockReduceSum(s,  red);
    s2 = blockReduceSum(s2, red);
    float m  = s  * (1.f / WD);
    float rs = rsqrtf(s2 * (1.f / WD) - m * m + 1e-5f);
    __half* out = (__half*)g_lnxw;
    for (int r = 0; r < 64; r++) {
        int d = threadIdx.x + r * 256;
        int sidx = d >> 4, c = d & 15;
        int sy = sidx >> 5, sx = sidx & 31;
        float v = x[(((size_t)b * CCH + c) * SZ + (wy * WS + sy)) * SZ + (wx * WS + sx)];
        float o = (v - m) * rs * gam[d] + bet[d];
        out[(size_t)t * WD + d] = __float2half_rn(o);
    }
}

// ---------------------------------------------------------------------------
// kF: window value mixing with nds + LePE conv -> g_wf (fp16 in-place)
// ---------------------------------------------------------------------------
__global__ void kF_wattn(const float* __restrict__ cw, const float* __restrict__ cb) {
    int bid = blockIdx.x;
    int h = bid & 7, b = bid >> 3;
    __shared__ float vs[NWIN][129], P[NWIN][NWIN];
    int tid = threadIdx.x;
    #pragma unroll
    for (int r = 0; r < 8; r++) {
        int idx = tid + r * 256;
        int n = idx >> 7, d = idx & 127;
        vs[n][d] = g_wv[((size_t)b * NWIN + n) * WIN_INNER + h * WDH + d];
    }
    {
        int n = tid >> 4, m = tid & 15;
        P[n][m] = g_nds[(((size_t)b * NH + h) * NWIN + n) * NWIN + m];
    }
    __syncthreads();
    __half* out = (__half*)g_wf;
    #pragma unroll
    for (int r = 0; r < 8; r++) {
        int idx = tid + r * 256;
        int n = idx >> 7, d = idx & 127;
        float acc = 0.f;
        #pragma unroll
        for (int m = 0; m < NWIN; m++) acc += P[n][m] * vs[m][d];
        int wyy = n >> 2, wxx = n & 3;
        #pragma unroll
        for (int ky = 0; ky < 3; ky++) {
            int yy = wyy + ky - 1;
            if (yy < 0 || yy > 3) continue;
            #pragma unroll
            for (int kx = 0; kx < 3; kx++) {
                int xx = wxx + kx - 1;
                if (xx < 0 || xx > 3) continue;
                acc += cw[d * 9 + ky * 3 + kx] * vs[yy * 4 + xx][d];
            }
        }
        acc += cb[d];
        out[((size_t)b * NWIN + n) * WIN_INNER + h * WDH + d] = __float2half_rn(acc);
    }
}

// ---------------------------------------------------------------------------
// kG: out = ds*pfo + wfo (scatter) + residual
// ---------------------------------------------------------------------------
__global__ void kG_out(const float* __restrict__ x, float* __restrict__ out) {
    size_t idx = (size_t)blockIdx.x * blockDim.x + threadIdx.x;
    if (idx >= (size_t)BATCH * CCH * SZ * SZ) return;
    int j = idx & 127;
    int i = (idx >> 7) & 127;
    int c = (idx >> 14) & 15;
    int b = (int)(idx >> 18);
    int wy = i >> 5, sy = i & 31, wx = j >> 5, sx = j & 31;
    int n = wy * 4 + wx;
    int wd = ((sy << 5) + sx) * 16 + c;
    int h = wd >> 11;
    size_t base = ((size_t)b * NWIN + n) * WD + wd;
    float v = g_ds[((size_t)b * NH + h) * NWIN + n] * g_pfo[base] + g_wfo[base] + x[idx];
    out[idx] = v;
}

// ---------------------------------------------------------------------------
// Launch: fork window branch onto a second stream; join before kG.
// ---------------------------------------------------------------------------
extern "C" void kernel_launch(void* const* d_in, const int* in_sizes, int n_in,
                              void* d_out, int out_size) {
    const float* x       = (const float*)d_in[0];
    const float* pn_g    = (const float*)d_in[1];
    const float* pn_b    = (const float*)d_in[2];
    const float* Wqk_p   = (const float*)d_in[3];
    const float* Wv_p    = (const float*)d_in[4];
    const float* conv_pw = (const float*)d_in[5];
    const float* conv_pb = (const float*)d_in[6];
    const float* Wout_p  = (const float*)d_in[7];
    const float* pln_g   = (const float*)d_in[8];
    const float* pln_b   = (const float*)d_in[9];
    const float* Wqk_w   = (const float*)d_in[10];
    const float* wn_g    = (const float*)d_in[11];
    const float* wn_b    = (const float*)d_in[12];
    const float* Wv_w    = (const float*)d_in[13];
    const float* conv_ww = (const float*)d_in[14];
    const float* conv_wb = (const float*)d_in[15];
    const float* Wout_w  = (const float*)d_in[16];
    float* out = (float*)d_out;

    // Fresh stream/events per call; NOT destroyed (destroy during graph
    // capture would invalidate the capture; call count is tiny).
    cudaStream_t s2;
    cudaStreamCreateWithFlags(&s2, cudaStreamNonBlocking);
    cudaEvent_t evFork, evJoin;
    cudaEventCreateWithFlags(&evFork, cudaEventDisableTiming);
    cudaEventCreateWithFlags(&evJoin, cudaEventDisableTiming);

    // fork
    cudaEventRecord(evFork, 0);
    cudaStreamWaitEvent(s2, evFork, 0);

    // --- window branch (stream s2) ---
    kC_pl<<<NTOK_W, 256, 0, s2>>>(x, pln_g, pln_b);
    mm_qkw<<<dim3((2*WIN_INNER)/128, NTOK_W/128), 256, 0, s2>>>(Wqk_w);
    kD_wscores<<<BATCH*NH, 256, 0, s2>>>();
    kE_lnxw<<<NTOK_W, 256, 0, s2>>>(x, wn_g, wn_b);
    mm_wv <<<dim3(WIN_INNER/128, NTOK_W/128, WV_SPLITK), 256, 0, s2>>>(Wv_w);
    kR_wv<<<(NTOK_W * WIN_INNER + 255) / 256, 256, 0, s2>>>();
    kF_wattn<<<BATCH*NH, 256, 0, s2>>>(conv_ww, conv_wb);
    mm_wfo<<<dim3(WD/128, NTOK_W/128), 256, 0, s2>>>(Wout_w);
    cudaEventRecord(evJoin, s2);

    // --- patch branch (default stream) ---
    kA_fl<<<NTOK_P, 256>>>(x, pn_g, pn_b);
    mm_qkp<<<dim3((2*PD)/128, NTOK_P/128), 256>>>(Wqk_p);
    mm_pv <<<dim3(PD/128,     NTOK_P/128), 256>>>(Wv_p);
    kB_pattn<<<BATCH*NWIN*NH, 256>>>(conv_pw, conv_pb);
    mm_pfo<<<dim3(PD/128,     NTOK_P/128), 256>>>(Wout_p);

    // join
    cudaStreamWaitEvent(0, evJoin, 0);

    // --- combine + residual ---
    size_t total = (size_t)BATCH * CCH * SZ * SZ;
    kG_out<<<(unsigned)((total + 255) / 256), 256>>>(x, out);
}

// round 13
// speedup vs baseline: 5.8195x; 1.0654x over previous
#include <cuda_runtime.h>
#include <cuda_fp16.h>
#include <cstdint>

// ---------------------------------------------------------------------------
// Problem dims (compile-time)
// ---------------------------------------------------------------------------
#define BATCH 64
#define CCH   16
#define SZ    128
#define WS    32
#define PS    8
#define NH    8
#define WN    4
#define PPW   4
#define NWIN  16
#define NPAT  16
#define PD    1024
#define PDH   128
#define PLD   1024
#define WDH   128
#define WIN_INNER 1024
#define WD    16384
#define NTOK_P (BATCH*NWIN*NPAT)   // 16384
#define NTOK_W (BATCH*NWIN)        // 1024
#define ATT_SCALE 0.08838834764831845f

#define WV_SPLITK 8

// ---------------------------------------------------------------------------
// Scratch (device globals) — EXACT R2/R7 set (known delta=0).
// Buffers declared fp32; several now hold fp16 (written via (__half*) casts):
//   fp16: g_fl, g_pf, g_plln, g_lnxw, g_wf (GEMM A-operands)
//   fp16: g_qkp, g_pv, g_qkw, g_pfo, g_wfo (GEMM outputs)
//   fp32: g_wv_part, g_wv, g_nds, g_ds
// ---------------------------------------------------------------------------
__device__ float g_fl  [(size_t)NTOK_P * PD];
__device__ float g_qkp [(size_t)NTOK_P * 2 * PD];
__device__ float g_pv  [(size_t)NTOK_P * PD];
__device__ float g_pf  [(size_t)NTOK_P * PD];
__device__ float g_pfo [(size_t)NTOK_P * PD];
__device__ float g_plln[(size_t)NTOK_W * PLD];
__device__ float g_qkw [(size_t)NTOK_W * 2 * WIN_INNER];
__device__ float g_nds [(size_t)BATCH * NH * NWIN * NWIN];
__device__ float g_ds  [(size_t)BATCH * NH * NWIN];
__device__ float g_lnxw[(size_t)NTOK_W * WD];
__device__ float g_wv  [(size_t)NTOK_W * WIN_INNER];
__device__ float g_wv_part[(size_t)WV_SPLITK * NTOK_W * WIN_INNER];
__device__ float g_wf  [(size_t)NTOK_W * WIN_INNER];
__device__ float g_wfo [(size_t)NTOK_W * WD];

// ---------------------------------------------------------------------------
// MMA helpers
// ---------------------------------------------------------------------------
__device__ __forceinline__ void ldsm4(uint32_t& r0, uint32_t& r1, uint32_t& r2,
                                      uint32_t& r3, const void* p) {
    uint32_t a = (uint32_t)__cvta_generic_to_shared(p);
    asm volatile("ldmatrix.sync.aligned.m8n8.x4.shared.b16 {%0,%1,%2,%3}, [%4];"
                 : "=r"(r0), "=r"(r1), "=r"(r2), "=r"(r3) : "r"(a));
}
__device__ __forceinline__ void ldsm4t(uint32_t& r0, uint32_t& r1, uint32_t& r2,
                                       uint32_t& r3, const void* p) {
    uint32_t a = (uint32_t)__cvta_generic_to_shared(p);
    asm volatile("ldmatrix.sync.aligned.m8n8.x4.trans.shared.b16 {%0,%1,%2,%3}, [%4];"
                 : "=r"(r0), "=r"(r1), "=r"(r2), "=r"(r3) : "r"(a));
}
__device__ __forceinline__ void mma_f16(float* c, const uint32_t* a, uint32_t b0, uint32_t b1) {
    asm volatile(
        "mma.sync.aligned.m16n8k16.row.col.f32.f16.f16.f32 "
        "{%0,%1,%2,%3},{%4,%5,%6,%7},{%8,%9},{%0,%1,%2,%3};"
        : "+f"(c[0]), "+f"(c[1]), "+f"(c[2]), "+f"(c[3])
        : "r"(a[0]), "r"(a[1]), "r"(a[2]), "r"(a[3]), "r"(b0), "r"(b1));
}

// fp32x4 -> single fp16 pair (RN) — for B (weights)
__device__ __forceinline__ void cvt4(float4 v, uint2& h) {
    __half2 h01 = __floats2half2_rn(v.x, v.y);
    __half2 h23 = __floats2half2_rn(v.z, v.w);
    h.x = *reinterpret_cast<uint32_t*>(&h01);
    h.y = *reinterpret_cast<uint32_t*>(&h23);
}

// epilogue store helpers (fp32 or fp16 C)
__device__ __forceinline__ void store2(float* C, size_t off, float a, float b) {
    *(float2*)(C + off) = make_float2(a, b);
}
__device__ __forceinline__ void store2(__half* C, size_t off, float a, float b) {
    *(__half2*)(C + off) = __floats2half2_rn(a, b);
}

// ---------------------------------------------------------------------------
// fp16 tensor-core GEMM: C = A(fp16) @ fp16(B), fp32 accum, OutT output.
// Double-buffered smem; register prefetch. 128x128x32, 256 thr, warp 64x32.
// ---------------------------------------------------------------------------
template<int M, int N, int K, int KC, typename OutT>
__device__ __forceinline__ void gemm_mma_body(const __half* __restrict__ A,
                                              const float* __restrict__ B,
                                              OutT* __restrict__ Cbase) {
    constexpr int BM = 128, BN = 128, BK = 32;
    constexpr int APAD = 8, BPAD = 8;
    __shared__ __half Ah[2][BM][BK + APAD];
    __shared__ __half Bh[2][BK][BN + BPAD];

    const int tid  = threadIdx.x;
    const int lane = tid & 31;
    const int wid  = tid >> 5;
    const int wm   = wid & 1;
    const int wn   = wid >> 1;
    const size_t m0 = (size_t)blockIdx.y * BM;
    const size_t n0 = (size_t)blockIdx.x * BN;
    const int kc0 = blockIdx.z * KC;
    OutT* __restrict__ C = Cbase + (size_t)blockIdx.z * M * N;

    const __half* Abp = A + m0 * K;
    const float*  Bbp = B + n0;

    float acc[4][4][4];
    #pragma unroll
    for (int i = 0; i < 4; i++)
        #pragma unroll
        for (int j = 0; j < 4; j++)
            #pragma unroll
            for (int e = 0; e < 4; e++) acc[i][j][e] = 0.f;

    const int ar  = lane & 15;
    const int ac8 = (lane >> 4) << 3;
    const int nIter = KC / BK;

    uint4  pa[2];
    float4 pb[4];

    #pragma unroll
    for (int i = 0; i < 2; i++) {
        int q = tid + 256 * i;
        int row = q >> 2, c8 = (q & 3) * 8;
        pa[i] = *(const uint4*)(Abp + (size_t)row * K + kc0 + c8);
    }
    #pragma unroll
    for (int i = 0; i < 4; i++) {
        int q = tid + 256 * i;
        int row = q >> 5, col = (q & 31) << 2;
        pb[i] = *(const float4*)(Bbp + (size_t)(kc0 + row) * N + col);
    }

    for (int it = 0; it < nIter; ++it) {
        const int s = it & 1;
        #pragma unroll
        for (int i = 0; i < 2; i++) {
            int q = tid + 256 * i;
            int row = q >> 2, c8 = (q & 3) * 8;
            *(uint4*)&Ah[s][row][c8] = pa[i];
        }
        #pragma unroll
        for (int i = 0; i < 4; i++) {
            int q = tid + 256 * i;
            int row = q >> 5, col = (q & 31) << 2;
            uint2 h;
            cvt4(pb[i], h);
            *(uint2*)&Bh[s][row][col] = h;
        }
        __syncthreads();

        if (it + 1 < nIter) {
            int k0n = kc0 + (it + 1) * BK;
            #pragma unroll
            for (int i = 0; i < 2; i++) {
                int q = tid + 256 * i;
                int row = q >> 2, c8 = (q & 3) * 8;
                pa[i] = *(const uint4*)(Abp + (size_t)row * K + k0n + c8);
            }
            #pragma unroll
            for (int i = 0; i < 4; i++) {
                int q = tid + 256 * i;
                int row = q >> 5, col = (q & 31) << 2;
                pb[i] = *(const float4*)(Bbp + (size_t)(k0n + row) * N + col);
            }
        }

        #pragma unroll
        for (int kk = 0; kk < 2; kk++) {
            uint32_t af[4][4], bf[2][4];
            #pragma unroll
            for (int mi = 0; mi < 4; mi++)
                ldsm4(af[mi][0], af[mi][1], af[mi][2], af[mi][3],
                      &Ah[s][wm * 64 + mi * 16 + ar][kk * 16 + ac8]);
            #pragma unroll
            for (int ni = 0; ni < 2; ni++)
                ldsm4t(bf[ni][0], bf[ni][1], bf[ni][2], bf[ni][3],
                       &Bh[s][kk * 16 + ar][wn * 32 + ni * 16 + ac8]);
            #pragma unroll
            for (int mi = 0; mi < 4; mi++)
                #pragma unroll
                for (int nj = 0; nj < 4; nj++) {
                    int ni = nj >> 1, pr = (nj & 1) << 1;
                    mma_f16(acc[mi][nj], af[mi], bf[ni][pr], bf[ni][pr + 1]);
                }
        }
    }

    const int gid = lane >> 2, tig = lane & 3;
    #pragma unroll
    for (int mi = 0; mi < 4; mi++) {
        size_t r0 = m0 + wm * 64 + mi * 16 + gid;
        #pragma unroll
        for (int nj = 0; nj < 4; nj++) {
            size_t cc = n0 + wn * 32 + nj * 8 + tig * 2;
            store2(C, r0 * N + cc,       acc[mi][nj][0], acc[mi][nj][1]);
            store2(C, (r0 + 8) * N + cc, acc[mi][nj][2], acc[mi][nj][3]);
        }
    }
}

__global__ void __launch_bounds__(256) mm_qkp(const float* __restrict__ W) {
    gemm_mma_body<NTOK_P, 2*PD, PD, PD>((const __half*)g_fl, W, (__half*)g_qkp);
}
__global__ void __launch_bounds__(256) mm_pv(const float* __restrict__ W) {
    gemm_mma_body<NTOK_P, PD, PD, PD>((const __half*)g_fl, W, (__half*)g_pv);
}
__global__ void __launch_bounds__(256) mm_pfo(const float* __restrict__ W) {
    gemm_mma_body<NTOK_P, PD, PD, PD>((const __half*)g_pf, W, (__half*)g_pfo);
}
__global__ void __launch_bounds__(256) mm_qkw(const float* __restrict__ W) {
    gemm_mma_body<NTOK_W, 2*WIN_INNER, PLD, PLD>((const __half*)g_plln, W, (__half*)g_qkw);
}
__global__ void __launch_bounds__(256) mm_wv(const float* __restrict__ W) {
    gemm_mma_body<NTOK_W, WIN_INNER, WD, WD / WV_SPLITK>((const __half*)g_lnxw, W, g_wv_part);
}
__global__ void __launch_bounds__(256) mm_wfo(const float* __restrict__ W) {
    gemm_mma_body<NTOK_W, WD, WIN_INNER, WIN_INNER>((const __half*)g_wf, W, (__half*)g_wfo);
}

// split-K reduction for wv (deterministic)
__global__ void kR_wv() {
    size_t i = (size_t)blockIdx.x * blockDim.x + threadIdx.x;
    if (i >= (size_t)NTOK_W * WIN_INNER) return;
    float s = 0.f;
    #pragma unroll
    for (int z = 0; z < WV_SPLITK; z++)
        s += g_wv_part[(size_t)z * NTOK_W * WIN_INNER + i];
    g_wv[i] = s;
}

// ---------------------------------------------------------------------------
// Block reduce
// ---------------------------------------------------------------------------
__device__ __forceinline__ float blockReduceSum(float v, float* sh) {
    int lane = threadIdx.x & 31, wid = threadIdx.x >> 5;
    #pragma unroll
    for (int o = 16; o > 0; o >>= 1) v += __shfl_down_sync(0xffffffffu, v, o);
    if (lane == 0) sh[wid] = v;
    __syncthreads();
    int nw = blockDim.x >> 5;
    v = (threadIdx.x < (unsigned)nw) ? sh[threadIdx.x] : 0.f;
    if (wid == 0) {
        #pragma unroll
        for (int o = 16; o > 0; o >>= 1) v += __shfl_down_sync(0xffffffffu, v, o);
        if (lane == 0) sh[0] = v;
    }
    __syncthreads();
    float r = sh[0];
    __syncthreads();
    return r;
}

// ---------------------------------------------------------------------------
// kA: gather patch token + LayerNorm -> g_fl (fp16), COALESCED channel-major
// reads + smem transpose for pixel-major output.
// ---------------------------------------------------------------------------
__global__ void kA_fl(const float* __restrict__ x,
                      const float* __restrict__ gam, const float* __restrict__ bet) {
    int t = blockIdx.x;
    int b = t >> 8, w = (t >> 4) & 15, p = t & 15;
    int wy = w >> 2, wx = w & 3, py = p >> 2, px = p & 3;
    int i0 = wy * WS + py * PS, j0 = wx * WS + px * PS;
    __shared__ float red[32];
    __shared__ float sv[16][65];     // [channel][pixel]
    float s = 0.f, s2 = 0.f;
    #pragma unroll
    for (int r = 0; r < 4; r++) {
        int e = threadIdx.x + r * 256;
        int c = e >> 6, pix = e & 63;
        int sy = pix >> 3, sx = pix & 7;
        float v = x[(((size_t)b * CCH + c) * SZ + (i0 + sy)) * SZ + (j0 + sx)];
        sv[c][pix] = v;
        s += v; s2 += v * v;
    }
    s  = blockReduceSum(s,  red);
    s2 = blockReduceSum(s2, red);
    float m  = s  * (1.f / PD);
    float rs = rsqrtf(s2 * (1.f / PD) - m * m + 1e-5f);
    __half* out = (__half*)g_fl;
    #pragma unroll
    for (int r = 0; r < 4; r++) {
        int d = threadIdx.x + r * 256;
        int sidx = d >> 4, c = d & 15;
        float v = sv[c][sidx];
        out[(size_t)t * PD + d] = __float2half_rn((v - m) * rs * gam[d] + bet[d]);
    }
}

// ---------------------------------------------------------------------------
// kB: patch attention + LePE conv -> g_pf (fp16); reads fp16 qkp/pv
// ---------------------------------------------------------------------------
__global__ void kB_pattn(const float* __restrict__ cw, const float* __restrict__ cb) {
    int bid = blockIdx.x;
    int h = bid & 7;
    size_t tb = (size_t)(bid >> 3) * NPAT;
    __shared__ float qs[NPAT][129], ks[NPAT][129], S[NPAT][NPAT];
    int tid = threadIdx.x;
    const __half* qk = (const __half*)g_qkp;
    const __half* pv = (const __half*)g_pv;
    #pragma unroll
    for (int r = 0; r < 8; r++) {
        int idx = tid + r * 256;
        int p = idx >> 7, d = idx & 127;
        qs[p][d] = __half2float(qk[(tb + p) * (2 * PD) + h * PDH + d]);
        ks[p][d] = __half2float(qk[(tb + p) * (2 * PD) + PD + h * PDH + d]);
    }
    __syncthreads();
    {
        int p = tid >> 4, v = tid & 15;
        float acc = 0.f;
        #pragma unroll 8
        for (int d = 0; d < PDH; d++) acc += qs[p][d] * ks[v][d];
        S[p][v] = acc * ATT_SCALE;
    }
    __syncthreads();
    if (tid < NPAT) {
        float mx = -1e30f;
        #pragma unroll
        for (int v = 0; v < NPAT; v++) mx = fmaxf(mx, S[tid][v]);
        float e[NPAT], sum = 0.f;
        #pragma unroll
        for (int v = 0; v < NPAT; v++) { e[v] = __expf(S[tid][v] - mx); sum += e[v]; }
        float inv = 1.f / sum;
        #pragma unroll
        for (int v = 0; v < NPAT; v++) S[tid][v] = e[v] * inv;
    }
    __syncthreads();
    #pragma unroll
    for (int r = 0; r < 8; r++) {
        int idx = tid + r * 256;
        int p = idx >> 7, d = idx & 127;
        ks[p][d] = __half2float(pv[(tb + p) * PD + h * PDH + d]);
    }
    __syncthreads();
    __half* out = (__half*)g_pf;
    #pragma unroll
    for (int r = 0; r < 8; r++) {
        int idx = tid + r * 256;
        int p = idx >> 7, d = idx & 127;
        float acc = 0.f;
        #pragma unroll
        for (int v = 0; v < NPAT; v++) acc += S[p][v] * ks[v][d];
        int py = p >> 2, px = p & 3;
        #pragma unroll
        for (int ky = 0; ky < 3; ky++) {
            int yy = py + ky - 1;
            if (yy < 0 || yy > 3) continue;
            #pragma unroll
            for (int kx = 0; kx < 3; kx++) {
                int xx = px + kx - 1;
                if (xx < 0 || xx > 3) continue;
                acc += cw[d * 9 + ky * 3 + kx] * ks[yy * 4 + xx][d];
            }
        }
        acc += cb[d];
        out[(tb + p) * PD + h * PDH + d] = __float2half_rn(acc);
    }
}

// ---------------------------------------------------------------------------
// kC: 4x4 average pool + gather + LayerNorm -> g_plln (fp16)
// ---------------------------------------------------------------------------
__global__ void kC_pl(const float* __restrict__ x,
                      const float* __restrict__ gam, const float* __restrict__ bet) {
    int t = blockIdx.x;
    int b = t >> 4, w = t & 15, wy = w >> 2, wx = w & 3;
    __shared__ float red[32];
    float vals[4], s = 0.f, s2 = 0.f;
    #pragma unroll
    for (int r = 0; r < 4; r++) {
        int d = threadIdx.x + r * 256;
        int uy = (d >> 4) >> 3, ux = (d >> 4) & 7, c = d & 15;
        int i0 = wy * WS + uy * 4, j0 = wx * WS + ux * 4;
        const float* xb = x + (((size_t)b * CCH + c) * SZ + i0) * SZ + j0;
        float acc = 0.f;
        #pragma unroll
        for (int a = 0; a < 4; a++)
            #pragma unroll
            for (int e = 0; e < 4; e++) acc += xb[a * SZ + e];
        float v = acc * (1.f / 16.f);
        vals[r] = v; s += v; s2 += v * v;
    }
    s  = blockReduceSum(s,  red);
    s2 = blockReduceSum(s2, red);
    float m  = s  * (1.f / PLD);
    float rs = rsqrtf(s2 * (1.f / PLD) - m * m + 1e-5f);
    __half* out = (__half*)g_plln;
    #pragma unroll
    for (int r = 0; r < 4; r++) {
        int d = threadIdx.x + r * 256;
        float v = (vals[r] - m) * rs * gam[d] + bet[d];
        out[(size_t)t * PLD + d] = __float2half_rn(v);
    }
}

// ---------------------------------------------------------------------------
// kD: window attention scores + diag/non-diag rescale; reads fp16 qkw
// ---------------------------------------------------------------------------
__global__ void kD_wscores() {
    int bid = blockIdx.x;
    int h = bid & 7, b = bid >> 3;
    __shared__ float qs[NWIN][129], ks[NWIN][129], S[NWIN][NWIN];
    int tid = threadIdx.x;
    const __half* qk = (const __half*)g_qkw;
    #pragma unroll
    for (int r = 0; r < 8; r++) {
        int idx = tid + r * 256;
        int n = idx >> 7, d = idx & 127;
        qs[n][d] = __half2float(qk[((size_t)b * NWIN + n) * (2 * WIN_INNER) + h * WDH + d]);
        ks[n][d] = __half2float(qk[((size_t)b * NWIN + n) * (2 * WIN_INNER) + WIN_INNER + h * WDH + d]);
    }
    __syncthreads();
    int n = tid >> 4, m = tid & 15;
    {
        float acc = 0.f;
        #pragma unroll 8
        for (int d = 0; d < WDH; d++) acc += qs[n][d] * ks[m][d];
        S[n][m] = acc * ATT_SCALE;
    }
    __syncthreads();
    if (tid < NWIN) {
        float mx = -1e30f;
        #pragma unroll
        for (int v = 0; v < NWIN; v++) mx = fmaxf(mx, S[tid][v]);
        float e[NWIN], sum = 0.f;
        #pragma unroll
        for (int v = 0; v < NWIN; v++) { e[v] = __expf(S[tid][v] - mx); sum += e[v]; }
        float inv = 1.f / sum;
        #pragma unroll
        for (int v = 0; v < NWIN; v++) S[tid][v] = e[v] * inv;
    }
    __syncthreads();
    float dn = S[n][n];
    bool line = dn < 0.5f;
    if (m == 0) g_ds[((size_t)b * NH + h) * NWIN + n] = line ? 0.5f : dn;
    float val = (m == n) ? 0.f : S[n][m];
    if (line) val *= 0.5f / (1.f - dn);
    g_nds[(((size_t)b * NH + h) * NWIN + n) * NWIN + m] = val;
}

// ---------------------------------------------------------------------------
// kE: window gather + LN(WD) -> g_lnxw (fp16), COALESCED channel-major reads
// (pass 1 sums; pass 2 stages 128-pixel chunks in smem, writes pixel-major).
// ---------------------------------------------------------------------------
__global__ void kE_lnxw(const float* __restrict__ x,
                        const float* __restrict__ gam, const float* __restrict__ bet) {
    int t = blockIdx.x;
    int b = t >> 4, w = t & 15, wy = w >> 2, wx = w & 3;
    __shared__ float red[32];
    __shared__ float sv[16][129];
    float s = 0.f, s2 = 0.f;
    #pragma unroll
    for (int cc = 0; cc < 16; cc++) {
        const float* xc = x + (((size_t)b * CCH + cc) * SZ + wy * WS) * SZ + wx * WS;
        #pragma unroll
        for (int i = 0; i < 4; i++) {
            int pix = threadIdx.x + i * 256;
            int sy = pix >> 5, sx = pix & 31;
            float v = xc[(size_t)sy * SZ + sx];
            s += v; s2 += v * v;
        }
    }
    s  = blockReduceSum(s,  red);
    s2 = blockReduceSum(s2, red);
    float m  = s  * (1.f / WD);
    float rs = rsqrtf(s2 * (1.f / WD) - m * m + 1e-5f);
    __half* out = (__half*)g_lnxw;
    for (int ch = 0; ch < 8; ch++) {
        __syncthreads();
        #pragma unroll
        for (int i = 0; i < 8; i++) {
            int q = threadIdx.x + i * 256;
            int c = q >> 7, pix = q & 127;
            int gp = ch * 128 + pix;
            int sy = gp >> 5, sx = gp & 31;
            sv[c][pix] = x[(((size_t)b * CCH + c) * SZ + wy * WS + sy) * SZ + wx * WS + sx];
        }
        __syncthreads();
        #pragma unroll
        for (int i = 0; i < 8; i++) {
            int q = threadIdx.x + i * 256;
            int d = ch * 2048 + q;
            int sidx = q >> 4, c = q & 15;
            float v = sv[c][sidx];
            out[(size_t)t * WD + d] = __float2half_rn((v - m) * rs * gam[d] + bet[d]);
        }
    }
}

// ---------------------------------------------------------------------------
// kF: window value mixing with nds + LePE conv -> g_wf (fp16)
// ---------------------------------------------------------------------------
__global__ void kF_wattn(const float* __restrict__ cw, const float* __restrict__ cb) {
    int bid = blockIdx.x;
    int h = bid & 7, b = bid >> 3;
    __shared__ float vs[NWIN][129], P[NWIN][NWIN];
    int tid = threadIdx.x;
    #pragma unroll
    for (int r = 0; r < 8; r++) {
        int idx = tid + r * 256;
        int n = idx >> 7, d = idx & 127;
        vs[n][d] = g_wv[((size_t)b * NWIN + n) * WIN_INNER + h * WDH + d];
    }
    {
        int n = tid >> 4, m = tid & 15;
        P[n][m] = g_nds[(((size_t)b * NH + h) * NWIN + n) * NWIN + m];
    }
    __syncthreads();
    __half* out = (__half*)g_wf;
    #pragma unroll
    for (int r = 0; r < 8; r++) {
        int idx = tid + r * 256;
        int n = idx >> 7, d = idx & 127;
        float acc = 0.f;
        #pragma unroll
        for (int m = 0; m < NWIN; m++) acc += P[n][m] * vs[m][d];
        int wyy = n >> 2, wxx = n & 3;
        #pragma unroll
        for (int ky = 0; ky < 3; ky++) {
            int yy = wyy + ky - 1;
            if (yy < 0 || yy > 3) continue;
            #pragma unroll
            for (int kx = 0; kx < 3; kx++) {
                int xx = wxx + kx - 1;
                if (xx < 0 || xx > 3) continue;
                acc += cw[d * 9 + ky * 3 + kx] * vs[yy * 4 + xx][d];
            }
        }
        acc += cb[d];
        out[((size_t)b * NWIN + n) * WIN_INNER + h * WDH + d] = __float2half_rn(acc);
    }
}

// ---------------------------------------------------------------------------
// kG: out = ds*pfo + wfo + x, smem-transposed for coalescing on both sides.
// Grid: NTOK_W * 8 chunks; per chunk head h == chunk index (2048 == 2^11).
// ---------------------------------------------------------------------------
__global__ void kG_out(const float* __restrict__ x, float* __restrict__ out) {
    int bid = blockIdx.x;
    int ch = bid & 7, t = bid >> 3;
    int b = t >> 4, n = t & 15;
    int wy = n >> 2, wx = n & 3;
    __shared__ float sv[16][129];
    const __half* pfo = (const __half*)g_pfo;
    const __half* wfo = (const __half*)g_wfo;
    const float ds = g_ds[((size_t)b * NH + ch) * NWIN + n];
    size_t base = (size_t)t * WD + (size_t)ch * 2048;
    #pragma unroll
    for (int i = 0; i < 8; i++) {
        int q = threadIdx.x + i * 256;
        float v = ds * __half2float(pfo[base + q]) + __half2float(wfo[base + q]);
        sv[q & 15][q >> 4] = v;
    }
    __syncthreads();
    #pragma unroll
    for (int i = 0; i < 8; i++) {
        int q = threadIdx.x + i * 256;
        int c = q >> 7, pix = q & 127;
        int gp = ch * 128 + pix;
        int sy = gp >> 5, sx = gp & 31;
        size_t xi = (((size_t)b * CCH + c) * SZ + wy * WS + sy) * SZ + wx * WS + sx;
        out[xi] = sv[c][pix] + x[xi];
    }
}

// ---------------------------------------------------------------------------
// Launch: fork window branch onto a second stream; join before kG.
// ---------------------------------------------------------------------------
extern "C" void kernel_launch(void* const* d_in, const int* in_sizes, int n_in,
                              void* d_out, int out_size) {
    const float* x       = (const float*)d_in[0];
    const float* pn_g    = (const float*)d_in[1];
    const float* pn_b    = (const float*)d_in[2];
    const float* Wqk_p   = (const float*)d_in[3];
    const float* Wv_p    = (const float*)d_in[4];
    const float* conv_pw = (const float*)d_in[5];
    const float* conv_pb = (const float*)d_in[6];
    const float* Wout_p  = (const float*)d_in[7];
    const float* pln_g   = (const float*)d_in[8];
    const float* pln_b   = (const float*)d_in[9];
    const float* Wqk_w   = (const float*)d_in[10];
    const float* wn_g    = (const float*)d_in[11];
    const float* wn_b    = (const float*)d_in[12];
    const float* Wv_w    = (const float*)d_in[13];
    const float* conv_ww = (const float*)d_in[14];
    const float* conv_wb = (const float*)d_in[15];
    const float* Wout_w  = (const float*)d_in[16];
    float* out = (float*)d_out;

    cudaStream_t s2;
    cudaStreamCreateWithFlags(&s2, cudaStreamNonBlocking);
    cudaEvent_t evFork, evJoin;
    cudaEventCreateWithFlags(&evFork, cudaEventDisableTiming);
    cudaEventCreateWithFlags(&evJoin, cudaEventDisableTiming);

    cudaEventRecord(evFork, 0);
    cudaStreamWaitEvent(s2, evFork, 0);

    // --- window branch (stream s2) ---
    kC_pl<<<NTOK_W, 256, 0, s2>>>(x, pln_g, pln_b);
    mm_qkw<<<dim3((2*WIN_INNER)/128, NTOK_W/128), 256, 0, s2>>>(Wqk_w);
    kD_wscores<<<BATCH*NH, 256, 0, s2>>>();
    kE_lnxw<<<NTOK_W, 256, 0, s2>>>(x, wn_g, wn_b);
    mm_wv <<<dim3(WIN_INNER/128, NTOK_W/128, WV_SPLITK), 256, 0, s2>>>(Wv_w);
    kR_wv<<<(NTOK_W * WIN_INNER + 255) / 256, 256, 0, s2>>>();
    kF_wattn<<<BATCH*NH, 256, 0, s2>>>(conv_ww, conv_wb);
    mm_wfo<<<dim3(WD/128, NTOK_W/128), 256, 0, s2>>>(Wout_w);
    cudaEventRecord(evJoin, s2);

    // --- patch branch (default stream) ---
    kA_fl<<<NTOK_P, 256>>>(x, pn_g, pn_b);
    mm_qkp<<<dim3((2*PD)/128, NTOK_P/128), 256>>>(Wqk_p);
    mm_pv <<<dim3(PD/128,     NTOK_P/128), 256>>>(Wv_p);
    kB_pattn<<<BATCH*NWIN*NH, 256>>>(conv_pw, conv_pb);
    mm_pfo<<<dim3(PD/128,     NTOK_P/128), 256>>>(Wout_p);

    cudaStreamWaitEvent(0, evJoin, 0);

    // --- combine + residual (grid: NTOK_W windows x 8 head-chunks) ---
    kG_out<<<NTOK_W * 8, 256>>>(x, out);
}

// round 14
// speedup vs baseline: 7.9062x; 1.3586x over previous
#include <cuda_runtime.h>
#include <cuda_fp16.h>
#include <cstdint>

// ---------------------------------------------------------------------------
// Problem dims (compile-time)
// ---------------------------------------------------------------------------
#define BATCH 64
#define CCH   16
#define SZ    128
#define WS    32
#define PS    8
#define NH    8
#define WN    4
#define PPW   4
#define NWIN  16
#define NPAT  16
#define PD    1024
#define PDH   128
#define PLD   1024
#define WDH   128
#define WIN_INNER 1024
#define WD    16384
#define NTOK_P (BATCH*NWIN*NPAT)   // 16384
#define NTOK_W (BATCH*NWIN)        // 1024
#define ATT_SCALE 0.08838834764831845f

#define WV_SPLITK 8

// ---------------------------------------------------------------------------
// Scratch (device globals) — EXACT R2/R7 set (known delta=0).
// fp16 regions (via (__half*) casts):
//   heads:  g_fl, g_pf, g_plln, g_lnxw, g_wf (A), g_qkp, g_pv, g_qkw,
//           g_pfo, g_wfo (C)
//   tails (unused upper halves) now cache fp16 weights:
//     g_qkp +32M : Wqk_p   g_pv  +16M : Wv_p    g_pfo +16M : Wout_p
//     g_fl  +16M : Wqk_w   g_lnxw+16M : Wv_w    g_wfo +16M : Wout_w
//   fp32: g_wv_part, g_wv, g_nds, g_ds
// ---------------------------------------------------------------------------
__device__ float g_fl  [(size_t)NTOK_P * PD];
__device__ float g_qkp [(size_t)NTOK_P * 2 * PD];
__device__ float g_pv  [(size_t)NTOK_P * PD];
__device__ float g_pf  [(size_t)NTOK_P * PD];
__device__ float g_pfo [(size_t)NTOK_P * PD];
__device__ float g_plln[(size_t)NTOK_W * PLD];
__device__ float g_qkw [(size_t)NTOK_W * 2 * WIN_INNER];
__device__ float g_nds [(size_t)BATCH * NH * NWIN * NWIN];
__device__ float g_ds  [(size_t)BATCH * NH * NWIN];
__device__ float g_lnxw[(size_t)NTOK_W * WD];
__device__ float g_wv  [(size_t)NTOK_W * WIN_INNER];
__device__ float g_wv_part[(size_t)WV_SPLITK * NTOK_W * WIN_INNER];
__device__ float g_wf  [(size_t)NTOK_W * WIN_INNER];
__device__ float g_wfo [(size_t)NTOK_W * WD];

#define OFF_QKP  ((size_t)NTOK_P * 2 * PD)        // halves: 33554432
#define OFF_PV   ((size_t)NTOK_P * PD)            // 16777216
#define OFF_PFO  ((size_t)NTOK_P * PD)
#define OFF_FL   ((size_t)NTOK_P * PD)
#define OFF_LNXW ((size_t)NTOK_W * WD)            // 16777216
#define OFF_WFO  ((size_t)NTOK_W * WD)

// ---------------------------------------------------------------------------
// MMA helpers
// ---------------------------------------------------------------------------
__device__ __forceinline__ void ldsm4(uint32_t& r0, uint32_t& r1, uint32_t& r2,
                                      uint32_t& r3, const void* p) {
    uint32_t a = (uint32_t)__cvta_generic_to_shared(p);
    asm volatile("ldmatrix.sync.aligned.m8n8.x4.shared.b16 {%0,%1,%2,%3}, [%4];"
                 : "=r"(r0), "=r"(r1), "=r"(r2), "=r"(r3) : "r"(a));
}
__device__ __forceinline__ void ldsm4t(uint32_t& r0, uint32_t& r1, uint32_t& r2,
                                       uint32_t& r3, const void* p) {
    uint32_t a = (uint32_t)__cvta_generic_to_shared(p);
    asm volatile("ldmatrix.sync.aligned.m8n8.x4.trans.shared.b16 {%0,%1,%2,%3}, [%4];"
                 : "=r"(r0), "=r"(r1), "=r"(r2), "=r"(r3) : "r"(a));
}
__device__ __forceinline__ void mma_f16(float* c, const uint32_t* a, uint32_t b0, uint32_t b1) {
    asm volatile(
        "mma.sync.aligned.m16n8k16.row.col.f32.f16.f16.f32 "
        "{%0,%1,%2,%3},{%4,%5,%6,%7},{%8,%9},{%0,%1,%2,%3};"
        : "+f"(c[0]), "+f"(c[1]), "+f"(c[2]), "+f"(c[3])
        : "r"(a[0]), "r"(a[1]), "r"(a[2]), "r"(a[3]), "r"(b0), "r"(b1));
}

__device__ __forceinline__ void cvt4(float4 v, uint2& h) {
    __half2 h01 = __floats2half2_rn(v.x, v.y);
    __half2 h23 = __floats2half2_rn(v.z, v.w);
    h.x = *reinterpret_cast<uint32_t*>(&h01);
    h.y = *reinterpret_cast<uint32_t*>(&h23);
}

__device__ __forceinline__ void store2(float* C, size_t off, float a, float b) {
    *(float2*)(C + off) = make_float2(a, b);
}
__device__ __forceinline__ void store2(__half* C, size_t off, float a, float b) {
    *(__half2*)(C + off) = __floats2half2_rn(a, b);
}

// ---------------------------------------------------------------------------
// fp16 tensor-core GEMM: C = A(fp16) @ B(fp16), fp32 accum, OutT output.
// Double-buffered smem; register prefetch. 128x128x32, 256 thr, warp 64x32.
// ---------------------------------------------------------------------------
template<int M, int N, int K, int KC, typename OutT>
__device__ __forceinline__ void gemm_mma_body(const __half* __restrict__ A,
                                              const __half* __restrict__ B,
                                              OutT* __restrict__ Cbase) {
    constexpr int BM = 128, BN = 128, BK = 32;
    constexpr int APAD = 8, BPAD = 8;
    __shared__ __half Ah[2][BM][BK + APAD];
    __shared__ __half Bh[2][BK][BN + BPAD];

    const int tid  = threadIdx.x;
    const int lane = tid & 31;
    const int wid  = tid >> 5;
    const int wm   = wid & 1;
    const int wn   = wid >> 1;
    const size_t m0 = (size_t)blockIdx.y * BM;
    const size_t n0 = (size_t)blockIdx.x * BN;
    const int kc0 = blockIdx.z * KC;
    OutT* __restrict__ C = Cbase + (size_t)blockIdx.z * M * N;

    const __half* Abp = A + m0 * K;
    const __half* Bbp = B + n0;

    float acc[4][4][4];
    #pragma unroll
    for (int i = 0; i < 4; i++)
        #pragma unroll
        for (int j = 0; j < 4; j++)
            #pragma unroll
            for (int e = 0; e < 4; e++) acc[i][j][e] = 0.f;

    const int ar  = lane & 15;
    const int ac8 = (lane >> 4) << 3;
    const int nIter = KC / BK;

    uint4 pa[2], pb[2];

    #pragma unroll
    for (int i = 0; i < 2; i++) {
        int q = tid + 256 * i;
        int row = q >> 2, c8 = (q & 3) * 8;
        pa[i] = *(const uint4*)(Abp + (size_t)row * K + kc0 + c8);
        int rb = q >> 4, cb8 = (q & 15) * 8;
        pb[i] = *(const uint4*)(Bbp + (size_t)(kc0 + rb) * N + cb8);
    }

    for (int it = 0; it < nIter; ++it) {
        const int s = it & 1;
        #pragma unroll
        for (int i = 0; i < 2; i++) {
            int q = tid + 256 * i;
            int row = q >> 2, c8 = (q & 3) * 8;
            *(uint4*)&Ah[s][row][c8] = pa[i];
            int rb = q >> 4, cb8 = (q & 15) * 8;
            *(uint4*)&Bh[s][rb][cb8] = pb[i];
        }
        __syncthreads();

        if (it + 1 < nIter) {
            int k0n = kc0 + (it + 1) * BK;
            #pragma unroll
            for (int i = 0; i < 2; i++) {
                int q = tid + 256 * i;
                int row = q >> 2, c8 = (q & 3) * 8;
                pa[i] = *(const uint4*)(Abp + (size_t)row * K + k0n + c8);
                int rb = q >> 4, cb8 = (q & 15) * 8;
                pb[i] = *(const uint4*)(Bbp + (size_t)(k0n + rb) * N + cb8);
            }
        }

        #pragma unroll
        for (int kk = 0; kk < 2; kk++) {
            uint32_t af[4][4], bf[2][4];
            #pragma unroll
            for (int mi = 0; mi < 4; mi++)
                ldsm4(af[mi][0], af[mi][1], af[mi][2], af[mi][3],
                      &Ah[s][wm * 64 + mi * 16 + ar][kk * 16 + ac8]);
            #pragma unroll
            for (int ni = 0; ni < 2; ni++)
                ldsm4t(bf[ni][0], bf[ni][1], bf[ni][2], bf[ni][3],
                       &Bh[s][kk * 16 + ar][wn * 32 + ni * 16 + ac8]);
            #pragma unroll
            for (int mi = 0; mi < 4; mi++)
                #pragma unroll
                for (int nj = 0; nj < 4; nj++) {
                    int ni = nj >> 1, pr = (nj & 1) << 1;
                    mma_f16(acc[mi][nj], af[mi], bf[ni][pr], bf[ni][pr + 1]);
                }
        }
    }

    const int gid = lane >> 2, tig = lane & 3;
    #pragma unroll
    for (int mi = 0; mi < 4; mi++) {
        size_t r0 = m0 + wm * 64 + mi * 16 + gid;
        #pragma unroll
        for (int nj = 0; nj < 4; nj++) {
            size_t cc = n0 + wn * 32 + nj * 8 + tig * 2;
            store2(C, r0 * N + cc,       acc[mi][nj][0], acc[mi][nj][1]);
            store2(C, (r0 + 8) * N + cc, acc[mi][nj][2], acc[mi][nj][3]);
        }
    }
}

__global__ void __launch_bounds__(256) mm_qkp() {
    gemm_mma_body<NTOK_P, 2*PD, PD, PD>((const __half*)g_fl,
        (const __half*)g_qkp + OFF_QKP, (__half*)g_qkp);
}
__global__ void __launch_bounds__(256) mm_pv() {
    gemm_mma_body<NTOK_P, PD, PD, PD>((const __half*)g_fl,
        (const __half*)g_pv + OFF_PV, (__half*)g_pv);
}
__global__ void __launch_bounds__(256) mm_pfo() {
    gemm_mma_body<NTOK_P, PD, PD, PD>((const __half*)g_pf,
        (const __half*)g_pfo + OFF_PFO, (__half*)g_pfo);
}
__global__ void __launch_bounds__(256) mm_qkw() {
    gemm_mma_body<NTOK_W, 2*WIN_INNER, PLD, PLD>((const __half*)g_plln,
        (const __half*)g_fl + OFF_FL, (__half*)g_qkw);
}
__global__ void __launch_bounds__(256) mm_wv() {
    gemm_mma_body<NTOK_W, WIN_INNER, WD, WD / WV_SPLITK>((const __half*)g_lnxw,
        (const __half*)g_lnxw + OFF_LNXW, g_wv_part);
}
__global__ void __launch_bounds__(256) mm_wfo() {
    gemm_mma_body<NTOK_W, WD, WIN_INNER, WIN_INNER>((const __half*)g_wf,
        (const __half*)g_wfo + OFF_WFO, (__half*)g_wfo);
}

// weight fp32 -> fp16 into spare buffer tails (device-symbol addressed)
#define DEF_KW(name, dstbuf, dstoff)                                          \
__global__ void name(const float4* __restrict__ in, int n4) {                 \
    int i = blockIdx.x * blockDim.x + threadIdx.x;                            \
    if (i >= n4) return;                                                      \
    uint2 h;                                                                  \
    cvt4(in[i], h);                                                           \
    *(uint2*)((__half*)dstbuf + dstoff + (size_t)i * 4) = h;                  \
}
DEF_KW(kW_qkp,  g_qkp,  OFF_QKP)
DEF_KW(kW_vp,   g_pv,   OFF_PV)
DEF_KW(kW_outp, g_pfo,  OFF_PFO)
DEF_KW(kW_qkw,  g_fl,   OFF_FL)
DEF_KW(kW_vw,   g_lnxw, OFF_LNXW)
DEF_KW(kW_outw, g_wfo,  OFF_WFO)

// split-K reduction for wv (deterministic)
__global__ void kR_wv() {
    size_t i = (size_t)blockIdx.x * blockDim.x + threadIdx.x;
    if (i >= (size_t)NTOK_W * WIN_INNER) return;
    float s = 0.f;
    #pragma unroll
    for (int z = 0; z < WV_SPLITK; z++)
        s += g_wv_part[(size_t)z * NTOK_W * WIN_INNER + i];
    g_wv[i] = s;
}

// ---------------------------------------------------------------------------
__device__ __forceinline__ float blockReduceSum(float v, float* sh) {
    int lane = threadIdx.x & 31, wid = threadIdx.x >> 5;
    #pragma unroll
    for (int o = 16; o > 0; o >>= 1) v += __shfl_down_sync(0xffffffffu, v, o);
    if (lane == 0) sh[wid] = v;
    __syncthreads();
    int nw = blockDim.x >> 5;
    v = (threadIdx.x < (unsigned)nw) ? sh[threadIdx.x] : 0.f;
    if (wid == 0) {
        #pragma unroll
        for (int o = 16; o > 0; o >>= 1) v += __shfl_down_sync(0xffffffffu, v, o);
        if (lane == 0) sh[0] = v;
    }
    __syncthreads();
    float r = sh[0];
    __syncthreads();
    return r;
}

// ---------------------------------------------------------------------------
// kA: gather + LN -> g_fl (fp16), coalesced + smem transpose
// ---------------------------------------------------------------------------
__global__ void kA_fl(const float* __restrict__ x,
                      const float* __restrict__ gam, const float* __restrict__ bet) {
    int t = blockIdx.x;
    int b = t >> 8, w = (t >> 4) & 15, p = t & 15;
    int wy = w >> 2, wx = w & 3, py = p >> 2, px = p & 3;
    int i0 = wy * WS + py * PS, j0 = wx * WS + px * PS;
    __shared__ float red[32];
    __shared__ float sv[16][65];
    float s = 0.f, s2 = 0.f;
    #pragma unroll
    for (int r = 0; r < 4; r++) {
        int e = threadIdx.x + r * 256;
        int c = e >> 6, pix = e & 63;
        int sy = pix >> 3, sx = pix & 7;
        float v = x[(((size_t)b * CCH + c) * SZ + (i0 + sy)) * SZ + (j0 + sx)];
        sv[c][pix] = v;
        s += v; s2 += v * v;
    }
    s  = blockReduceSum(s,  red);
    s2 = blockReduceSum(s2, red);
    float m  = s  * (1.f / PD);
    float rs = rsqrtf(s2 * (1.f / PD) - m * m + 1e-5f);
    __half* out = (__half*)g_fl;
    #pragma unroll
    for (int r = 0; r < 4; r++) {
        int d = threadIdx.x + r * 256;
        int sidx = d >> 4, c = d & 15;
        float v = sv[c][sidx];
        out[(size_t)t * PD + d] = __float2half_rn((v - m) * rs * gam[d] + bet[d]);
    }
}

// ---------------------------------------------------------------------------
// kB: patch attention + LePE conv -> g_pf (fp16)
// ---------------------------------------------------------------------------
__global__ void kB_pattn(const float* __restrict__ cw, const float* __restrict__ cb) {
    int bid = blockIdx.x;
    int h = bid & 7;
    size_t tb = (size_t)(bid >> 3) * NPAT;
    __shared__ float qs[NPAT][129], ks[NPAT][129], S[NPAT][NPAT];
    int tid = threadIdx.x;
    const __half* qk = (const __half*)g_qkp;
    const __half* pv = (const __half*)g_pv;
    #pragma unroll
    for (int r = 0; r < 8; r++) {
        int idx = tid + r * 256;
        int p = idx >> 7, d = idx & 127;
        qs[p][d] = __half2float(qk[(tb + p) * (2 * PD) + h * PDH + d]);
        ks[p][d] = __half2float(qk[(tb + p) * (2 * PD) + PD + h * PDH + d]);
    }
    __syncthreads();
    {
        int p = tid >> 4, v = tid & 15;
        float acc = 0.f;
        #pragma unroll 8
        for (int d = 0; d < PDH; d++) acc += qs[p][d] * ks[v][d];
        S[p][v] = acc * ATT_SCALE;
    }
    __syncthreads();
    if (tid < NPAT) {
        float mx = -1e30f;
        #pragma unroll
        for (int v = 0; v < NPAT; v++) mx = fmaxf(mx, S[tid][v]);
        float e[NPAT], sum = 0.f;
        #pragma unroll
        for (int v = 0; v < NPAT; v++) { e[v] = __expf(S[tid][v] - mx); sum += e[v]; }
        float inv = 1.f / sum;
        #pragma unroll
        for (int v = 0; v < NPAT; v++) S[tid][v] = e[v] * inv;
    }
    __syncthreads();
    #pragma unroll
    for (int r = 0; r < 8; r++) {
        int idx = tid + r * 256;
        int p = idx >> 7, d = idx & 127;
        ks[p][d] = __half2float(pv[(tb + p) * PD + h * PDH + d]);
    }
    __syncthreads();
    __half* out = (__half*)g_pf;
    #pragma unroll
    for (int r = 0; r < 8; r++) {
        int idx = tid + r * 256;
        int p = idx >> 7, d = idx & 127;
        float acc = 0.f;
        #pragma unroll
        for (int v = 0; v < NPAT; v++) acc += S[p][v] * ks[v][d];
        int py = p >> 2, px = p & 3;
        #pragma unroll
        for (int ky = 0; ky < 3; ky++) {
            int yy = py + ky - 1;
            if (yy < 0 || yy > 3) continue;
            #pragma unroll
            for (int kx = 0; kx < 3; kx++) {
                int xx = px + kx - 1;
                if (xx < 0 || xx > 3) continue;
                acc += cw[d * 9 + ky * 3 + kx] * ks[yy * 4 + xx][d];
            }
        }
        acc += cb[d];
        out[(tb + p) * PD + h * PDH + d] = __float2half_rn(acc);
    }
}

// ---------------------------------------------------------------------------
// kC: 4x4 pool + gather + LN -> g_plln (fp16)
// ---------------------------------------------------------------------------
__global__ void kC_pl(const float* __restrict__ x,
                      const float* __restrict__ gam, const float* __restrict__ bet) {
    int t = blockIdx.x;
    int b = t >> 4, w = t & 15, wy = w >> 2, wx = w & 3;
    __shared__ float red[32];
    float vals[4], s = 0.f, s2 = 0.f;
    #pragma unroll
    for (int r = 0; r < 4; r++) {
        int d = threadIdx.x + r * 256;
        int uy = (d >> 4) >> 3, ux = (d >> 4) & 7, c = d & 15;
        int i0 = wy * WS + uy * 4, j0 = wx * WS + ux * 4;
        const float* xb = x + (((size_t)b * CCH + c) * SZ + i0) * SZ + j0;
        float acc = 0.f;
        #pragma unroll
        for (int a = 0; a < 4; a++)
            #pragma unroll
            for (int e = 0; e < 4; e++) acc += xb[a * SZ + e];
        float v = acc * (1.f / 16.f);
        vals[r] = v; s += v; s2 += v * v;
    }
    s  = blockReduceSum(s,  red);
    s2 = blockReduceSum(s2, red);
    float m  = s  * (1.f / PLD);
    float rs = rsqrtf(s2 * (1.f / PLD) - m * m + 1e-5f);
    __half* out = (__half*)g_plln;
    #pragma unroll
    for (int r = 0; r < 4; r++) {
        int d = threadIdx.x + r * 256;
        float v = (vals[r] - m) * rs * gam[d] + bet[d];
        out[(size_t)t * PLD + d] = __float2half_rn(v);
    }
}

// ---------------------------------------------------------------------------
// kD: window scores + diag logic (reads fp16 qkw)
// ---------------------------------------------------------------------------
__global__ void kD_wscores() {
    int bid = blockIdx.x;
    int h = bid & 7, b = bid >> 3;
    __shared__ float qs[NWIN][129], ks[NWIN][129], S[NWIN][NWIN];
    int tid = threadIdx.x;
    const __half* qk = (const __half*)g_qkw;
    #pragma unroll
    for (int r = 0; r < 8; r++) {
        int idx = tid + r * 256;
        int n = idx >> 7, d = idx & 127;
        qs[n][d] = __half2float(qk[((size_t)b * NWIN + n) * (2 * WIN_INNER) + h * WDH + d]);
        ks[n][d] = __half2float(qk[((size_t)b * NWIN + n) * (2 * WIN_INNER) + WIN_INNER + h * WDH + d]);
    }
    __syncthreads();
    int n = tid >> 4, m = tid & 15;
    {
        float acc = 0.f;
        #pragma unroll 8
        for (int d = 0; d < WDH; d++) acc += qs[n][d] * ks[m][d];
        S[n][m] = acc * ATT_SCALE;
    }
    __syncthreads();
    if (tid < NWIN) {
        float mx = -1e30f;
        #pragma unroll
        for (int v = 0; v < NWIN; v++) mx = fmaxf(mx, S[tid][v]);
        float e[NWIN], sum = 0.f;
        #pragma unroll
        for (int v = 0; v < NWIN; v++) { e[v] = __expf(S[tid][v] - mx); sum += e[v]; }
        float inv = 1.f / sum;
        #pragma unroll
        for (int v = 0; v < NWIN; v++) S[tid][v] = e[v] * inv;
    }
    __syncthreads();
    float dn = S[n][n];
    bool line = dn < 0.5f;
    if (m == 0) g_ds[((size_t)b * NH + h) * NWIN + n] = line ? 0.5f : dn;
    float val = (m == n) ? 0.f : S[n][m];
    if (line) val *= 0.5f / (1.f - dn);
    g_nds[(((size_t)b * NH + h) * NWIN + n) * NWIN + m] = val;
}

// ---------------------------------------------------------------------------
// kE: window gather + LN(WD) -> g_lnxw (fp16), SINGLE gmem pass:
// stage whole 32x32x16 window as fp16 in smem during the sum pass.
// ---------------------------------------------------------------------------
__global__ void kE_lnxw(const float* __restrict__ x,
                        const float* __restrict__ gam, const float* __restrict__ bet) {
    int t = blockIdx.x;
    int b = t >> 4, w = t & 15, wy = w >> 2, wx = w & 3;
    __shared__ float red[32];
    __shared__ __half sx16[16][1032];   // [channel][pixel], ~33 KB
    float s = 0.f, s2 = 0.f;
    #pragma unroll
    for (int cc = 0; cc < 16; cc++) {
        const float* xc = x + (((size_t)b * CCH + cc) * SZ + wy * WS) * SZ + wx * WS;
        #pragma unroll
        for (int i = 0; i < 4; i++) {
            int pix = threadIdx.x + i * 256;
            int sy = pix >> 5, sx = pix & 31;
            float v = xc[(size_t)sy * SZ + sx];
            sx16[cc][pix] = __float2half_rn(v);
            s += v; s2 += v * v;
        }
    }
    s  = blockReduceSum(s,  red);
    s2 = blockReduceSum(s2, red);
    float m  = s  * (1.f / WD);
    float rs = rsqrtf(s2 * (1.f / WD) - m * m + 1e-5f);
    __half* out = (__half*)g_lnxw;
    #pragma unroll
    for (int i = 0; i < 64; i++) {
        int d = threadIdx.x + i * 256;
        int sidx = d >> 4, c = d & 15;
        float v = __half2float(sx16[c][sidx]);
        out[(size_t)t * WD + d] = __float2half_rn((v - m) * rs * gam[d] + bet[d]);
    }
}

// ---------------------------------------------------------------------------
// kF: nds value mixing + LePE conv -> g_wf (fp16)
// ---------------------------------------------------------------------------
__global__ void kF_wattn(const float* __restrict__ cw, const float* __restrict__ cb) {
    int bid = blockIdx.x;
    int h = bid & 7, b = bid >> 3;
    __shared__ float vs[NWIN][129], P[NWIN][NWIN];
    int tid = threadIdx.x;
    #pragma unroll
    for (int r = 0; r < 8; r++) {
        int idx = tid + r * 256;
        int n = idx >> 7, d = idx & 127;
        vs[n][d] = g_wv[((size_t)b * NWIN + n) * WIN_INNER + h * WDH + d];
    }
    {
        int n = tid >> 4, m = tid & 15;
        P[n][m] = g_nds[(((size_t)b * NH + h) * NWIN + n) * NWIN + m];
    }
    __syncthreads();
    __half* out = (__half*)g_wf;
    #pragma unroll
    for (int r = 0; r < 8; r++) {
        int idx = tid + r * 256;
        int n = idx >> 7, d = idx & 127;
        float acc = 0.f;
        #pragma unroll
        for (int m = 0; m < NWIN; m++) acc += P[n][m] * vs[m][d];
        int wyy = n >> 2, wxx = n & 3;
        #pragma unroll
        for (int ky = 0; ky < 3; ky++) {
            int yy = wyy + ky - 1;
            if (yy < 0 || yy > 3) continue;
            #pragma unroll
            for (int kx = 0; kx < 3; kx++) {
                int xx = wxx + kx - 1;
                if (xx < 0 || xx > 3) continue;
                acc += cw[d * 9 + ky * 3 + kx] * vs[yy * 4 + xx][d];
            }
        }
        acc += cb[d];
        out[((size_t)b * NWIN + n) * WIN_INNER + h * WDH + d] = __float2half_rn(acc);
    }
}

// ---------------------------------------------------------------------------
// kG: out = ds*pfo + wfo + x, smem-transposed both sides.
// ---------------------------------------------------------------------------
__global__ void kG_out(const float* __restrict__ x, float* __restrict__ out) {
    int bid = blockIdx.x;
    int ch = bid & 7, t = bid >> 3;
    int b = t >> 4, n = t & 15;
    int wy = n >> 2, wx = n & 3;
    __shared__ float sv[16][129];
    const __half* pfo = (const __half*)g_pfo;
    const __half* wfo = (const __half*)g_wfo;
    const float ds = g_ds[((size_t)b * NH + ch) * NWIN + n];
    size_t base = (size_t)t * WD + (size_t)ch * 2048;
    #pragma unroll
    for (int i = 0; i < 8; i++) {
        int q = threadIdx.x + i * 256;
        float v = ds * __half2float(pfo[base + q]) + __half2float(wfo[base + q]);
        sv[q & 15][q >> 4] = v;
    }
    __syncthreads();
    #pragma unroll
    for (int i = 0; i < 8; i++) {
        int q = threadIdx.x + i * 256;
        int c = q >> 7, pix = q & 127;
        int gp = ch * 128 + pix;
        int sy = gp >> 5, sx = gp & 31;
        size_t xi = (((size_t)b * CCH + c) * SZ + wy * WS + sy) * SZ + wx * WS + sx;
        out[xi] = sv[c][pix] + x[xi];
    }
}

// ---------------------------------------------------------------------------
// Launch
// ---------------------------------------------------------------------------
extern "C" void kernel_launch(void* const* d_in, const int* in_sizes, int n_in,
                              void* d_out, int out_size) {
    const float* x       = (const float*)d_in[0];
    const float* pn_g    = (const float*)d_in[1];
    const float* pn_b    = (const float*)d_in[2];
    const float* Wqk_p   = (const float*)d_in[3];
    const float* Wv_p    = (const float*)d_in[4];
    const float* conv_pw = (const float*)d_in[5];
    const float* conv_pb = (const float*)d_in[6];
    const float* Wout_p  = (const float*)d_in[7];
    const float* pln_g   = (const float*)d_in[8];
    const float* pln_b   = (const float*)d_in[9];
    const float* Wqk_w   = (const float*)d_in[10];
    const float* wn_g    = (const float*)d_in[11];
    const float* wn_b    = (const float*)d_in[12];
    const float* Wv_w    = (const float*)d_in[13];
    const float* conv_ww = (const float*)d_in[14];
    const float* conv_wb = (const float*)d_in[15];
    const float* Wout_w  = (const float*)d_in[16];
    float* out = (float*)d_out;

    cudaStream_t s2;
    cudaStreamCreateWithFlags(&s2, cudaStreamNonBlocking);
    cudaEvent_t evFork, evJoin;
    cudaEventCreateWithFlags(&evFork, cudaEventDisableTiming);
    cudaEventCreateWithFlags(&evJoin, cudaEventDisableTiming);

    cudaEventRecord(evFork, 0);
    cudaStreamWaitEvent(s2, evFork, 0);

    auto nb4 = [](size_t n) { return (unsigned)((n / 4 + 255) / 256); };

    // --- window branch (stream s2) ---
    kW_qkw <<<nb4((size_t)PLD*2*WIN_INNER), 256, 0, s2>>>((const float4*)Wqk_w, PLD*2*WIN_INNER/4);
    kW_vw  <<<nb4((size_t)WD*WIN_INNER),    256, 0, s2>>>((const float4*)Wv_w,  WD*WIN_INNER/4);
    kW_outw<<<nb4((size_t)WIN_INNER*WD),    256, 0, s2>>>((const float4*)Wout_w, WIN_INNER*WD/4);
    kC_pl<<<NTOK_W, 256, 0, s2>>>(x, pln_g, pln_b);
    mm_qkw<<<dim3((2*WIN_INNER)/128, NTOK_W/128), 256, 0, s2>>>();
    kD_wscores<<<BATCH*NH, 256, 0, s2>>>();
    kE_lnxw<<<NTOK_W, 256, 0, s2>>>(x, wn_g, wn_b);
    mm_wv <<<dim3(WIN_INNER/128, NTOK_W/128, WV_SPLITK), 256, 0, s2>>>();
    kR_wv<<<(NTOK_W * WIN_INNER + 255) / 256, 256, 0, s2>>>();
    kF_wattn<<<BATCH*NH, 256, 0, s2>>>(conv_ww, conv_wb);
    mm_wfo<<<dim3(WD/128, NTOK_W/128), 256, 0, s2>>>();
    cudaEventRecord(evJoin, s2);

    // --- patch branch (default stream) ---
    kW_qkp <<<nb4((size_t)PD*2*PD), 256>>>((const float4*)Wqk_p,  PD*2*PD/4);
    kW_vp  <<<nb4((size_t)PD*PD),   256>>>((const float4*)Wv_p,   PD*PD/4);
    kW_outp<<<nb4((size_t)PD*PD),   256>>>((const float4*)Wout_p, PD*PD/4);
    kA_fl<<<NTOK_P, 256>>>(x, pn_g, pn_b);
    mm_qkp<<<dim3((2*PD)/128, NTOK_P/128), 256>>>();
    mm_pv <<<dim3(PD/128,     NTOK_P/128), 256>>>();
    kB_pattn<<<BATCH*NWIN*NH, 256>>>(conv_pw, conv_pb);
    mm_pfo<<<dim3(PD/128,     NTOK_P/128), 256>>>();

    cudaStreamWaitEvent(0, evJoin, 0);

    // --- combine + residual ---
    kG_out<<<NTOK_W * 8, 256>>>(x, out);
}

// round 16
// speedup vs baseline: 8.0557x; 1.0189x over previous
#include <cuda_runtime.h>
#include <cuda_fp16.h>
#include <cstdint>

// ---------------------------------------------------------------------------
// Problem dims (compile-time)
// ---------------------------------------------------------------------------
#define BATCH 64
#define CCH   16
#define SZ    128
#define WS    32
#define PS    8
#define NH    8
#define WN    4
#define PPW   4
#define NWIN  16
#define NPAT  16
#define PD    1024
#define PDH   128
#define PLD   1024
#define WDH   128
#define WIN_INNER 1024
#define WD    16384
#define NTOK_P (BATCH*NWIN*NPAT)   // 16384
#define NTOK_W (BATCH*NWIN)        // 1024
#define ATT_SCALE 0.08838834764831845f

#define WV_SPLITK 8

// ---------------------------------------------------------------------------
// Scratch (device globals) — EXACT R2/R7 set (known delta=0).
// fp16 regions (via (__half*) casts):
//   heads:  g_fl, g_pf, g_plln, g_lnxw, g_wf (A), g_qkp, g_pv, g_qkw,
//           g_pfo, g_wfo (C)
//   tails (unused upper halves) cache fp16 weights:
//     g_qkp +32M : Wqk_p   g_pv  +16M : Wv_p    g_pfo +16M : Wout_p
//     g_fl  +16M : Wqk_w   g_lnxw+16M : Wv_w    g_wfo +16M : Wout_w
//   fp32: g_wv_part, g_nds, g_ds
// ---------------------------------------------------------------------------
__device__ float g_fl  [(size_t)NTOK_P * PD];
__device__ float g_qkp [(size_t)NTOK_P * 2 * PD];
__device__ float g_pv  [(size_t)NTOK_P * PD];
__device__ float g_pf  [(size_t)NTOK_P * PD];
__device__ float g_pfo [(size_t)NTOK_P * PD];
__device__ float g_plln[(size_t)NTOK_W * PLD];
__device__ float g_qkw [(size_t)NTOK_W * 2 * WIN_INNER];
__device__ float g_nds [(size_t)BATCH * NH * NWIN * NWIN];
__device__ float g_ds  [(size_t)BATCH * NH * NWIN];
__device__ float g_lnxw[(size_t)NTOK_W * WD];
__device__ float g_wv  [(size_t)NTOK_W * WIN_INNER];
__device__ float g_wv_part[(size_t)WV_SPLITK * NTOK_W * WIN_INNER];
__device__ float g_wf  [(size_t)NTOK_W * WIN_INNER];
__device__ float g_wfo [(size_t)NTOK_W * WD];

#define OFF_QKP  ((size_t)NTOK_P * 2 * PD)
#define OFF_PV   ((size_t)NTOK_P * PD)
#define OFF_PFO  ((size_t)NTOK_P * PD)
#define OFF_FL   ((size_t)NTOK_P * PD)
#define OFF_LNXW ((size_t)NTOK_W * WD)
#define OFF_WFO  ((size_t)NTOK_W * WD)

// ---------------------------------------------------------------------------
// MMA helpers
// ---------------------------------------------------------------------------
__device__ __forceinline__ void ldsm4(uint32_t& r0, uint32_t& r1, uint32_t& r2,
                                      uint32_t& r3, const void* p) {
    uint32_t a = (uint32_t)__cvta_generic_to_shared(p);
    asm volatile("ldmatrix.sync.aligned.m8n8.x4.shared.b16 {%0,%1,%2,%3}, [%4];"
                 : "=r"(r0), "=r"(r1), "=r"(r2), "=r"(r3) : "r"(a));
}
__device__ __forceinline__ void ldsm4t(uint32_t& r0, uint32_t& r1, uint32_t& r2,
                                       uint32_t& r3, const void* p) {
    uint32_t a = (uint32_t)__cvta_generic_to_shared(p);
    asm volatile("ldmatrix.sync.aligned.m8n8.x4.trans.shared.b16 {%0,%1,%2,%3}, [%4];"
                 : "=r"(r0), "=r"(r1), "=r"(r2), "=r"(r3) : "r"(a));
}
__device__ __forceinline__ void mma_f16(float* c, const uint32_t* a, uint32_t b0, uint32_t b1) {
    asm volatile(
        "mma.sync.aligned.m16n8k16.row.col.f32.f16.f16.f32 "
        "{%0,%1,%2,%3},{%4,%5,%6,%7},{%8,%9},{%0,%1,%2,%3};"
        : "+f"(c[0]), "+f"(c[1]), "+f"(c[2]), "+f"(c[3])
        : "r"(a[0]), "r"(a[1]), "r"(a[2]), "r"(a[3]), "r"(b0), "r"(b1));
}

__device__ __forceinline__ void cvt4(float4 v, uint2& h) {
    __half2 h01 = __floats2half2_rn(v.x, v.y);
    __half2 h23 = __floats2half2_rn(v.z, v.w);
    h.x = *reinterpret_cast<uint32_t*>(&h01);
    h.y = *reinterpret_cast<uint32_t*>(&h23);
}

__device__ __forceinline__ void store2(float* C, size_t off, float a, float b) {
    *(float2*)(C + off) = make_float2(a, b);
}
__device__ __forceinline__ void store2(__half* C, size_t off, float a, float b) {
    *(__half2*)(C + off) = __floats2half2_rn(a, b);
}

// ---------------------------------------------------------------------------
// fp16 tensor-core GEMM: C = A(fp16) @ B(fp16), fp32 accum, OutT output.
// Double-buffered smem; register prefetch. 128x128x32, 256 thr, warp 64x32.
// ---------------------------------------------------------------------------
template<int M, int N, int K, int KC, typename OutT>
__device__ __forceinline__ void gemm_mma_body(const __half* __restrict__ A,
                                              const __half* __restrict__ B,
                                              OutT* __restrict__ Cbase) {
    constexpr int BM = 128, BN = 128, BK = 32;
    constexpr int APAD = 8, BPAD = 8;
    __shared__ __half Ah[2][BM][BK + APAD];
    __shared__ __half Bh[2][BK][BN + BPAD];

    const int tid  = threadIdx.x;
    const int lane = tid & 31;
    const int wid  = tid >> 5;
    const int wm   = wid & 1;
    const int wn   = wid >> 1;
    const size_t m0 = (size_t)blockIdx.y * BM;
    const size_t n0 = (size_t)blockIdx.x * BN;
    const int kc0 = blockIdx.z * KC;
    OutT* __restrict__ C = Cbase + (size_t)blockIdx.z * M * N;

    const __half* Abp = A + m0 * K;
    const __half* Bbp = B + n0;

    float acc[4][4][4];
    #pragma unroll
    for (int i = 0; i < 4; i++)
        #pragma unroll
        for (int j = 0; j < 4; j++)
            #pragma unroll
            for (int e = 0; e < 4; e++) acc[i][j][e] = 0.f;

    const int ar  = lane & 15;
    const int ac8 = (lane >> 4) << 3;
    const int nIter = KC / BK;

    uint4 pa[2], pb[2];

    #pragma unroll
    for (int i = 0; i < 2; i++) {
        int q = tid + 256 * i;
        int row = q >> 2, c8 = (q & 3) * 8;
        pa[i] = *(const uint4*)(Abp + (size_t)row * K + kc0 + c8);
        int rb = q >> 4, cb8 = (q & 15) * 8;
        pb[i] = *(const uint4*)(Bbp + (size_t)(kc0 + rb) * N + cb8);
    }

    for (int it = 0; it < nIter; ++it) {
        const int s = it & 1;
        #pragma unroll
        for (int i = 0; i < 2; i++) {
            int q = tid + 256 * i;
            int row = q >> 2, c8 = (q & 3) * 8;
            *(uint4*)&Ah[s][row][c8] = pa[i];
            int rb = q >> 4, cb8 = (q & 15) * 8;
            *(uint4*)&Bh[s][rb][cb8] = pb[i];
        }
        __syncthreads();

        if (it + 1 < nIter) {
            int k0n = kc0 + (it + 1) * BK;
            #pragma unroll
            for (int i = 0; i < 2; i++) {
                int q = tid + 256 * i;
                int row = q >> 2, c8 = (q & 3) * 8;
                pa[i] = *(const uint4*)(Abp + (size_t)row * K + k0n + c8);
                int rb = q >> 4, cb8 = (q & 15) * 8;
                pb[i] = *(const uint4*)(Bbp + (size_t)(k0n + rb) * N + cb8);
            }
        }

        #pragma unroll
        for (int kk = 0; kk < 2; kk++) {
            uint32_t af[4][4], bf[2][4];
            #pragma unroll
            for (int mi = 0; mi < 4; mi++)
                ldsm4(af[mi][0], af[mi][1], af[mi][2], af[mi][3],
                      &Ah[s][wm * 64 + mi * 16 + ar][kk * 16 + ac8]);
            #pragma unroll
            for (int ni = 0; ni < 2; ni++)
                ldsm4t(bf[ni][0], bf[ni][1], bf[ni][2], bf[ni][3],
                       &Bh[s][kk * 16 + ar][wn * 32 + ni * 16 + ac8]);
            #pragma unroll
            for (int mi = 0; mi < 4; mi++)
                #pragma unroll
                for (int nj = 0; nj < 4; nj++) {
                    int ni = nj >> 1, pr = (nj & 1) << 1;
                    mma_f16(acc[mi][nj], af[mi], bf[ni][pr], bf[ni][pr + 1]);
                }
        }
    }

    const int gid = lane >> 2, tig = lane & 3;
    #pragma unroll
    for (int mi = 0; mi < 4; mi++) {
        size_t r0 = m0 + wm * 64 + mi * 16 + gid;
        #pragma unroll
        for (int nj = 0; nj < 4; nj++) {
            size_t cc = n0 + wn * 32 + nj * 8 + tig * 2;
            store2(C, r0 * N + cc,       acc[mi][nj][0], acc[mi][nj][1]);
            store2(C, (r0 + 8) * N + cc, acc[mi][nj][2], acc[mi][nj][3]);
        }
    }
}

__global__ void __launch_bounds__(256) mm_qkp() {
    gemm_mma_body<NTOK_P, 2*PD, PD, PD>((const __half*)g_fl,
        (const __half*)g_qkp + OFF_QKP, (__half*)g_qkp);
}
__global__ void __launch_bounds__(256) mm_pv() {
    gemm_mma_body<NTOK_P, PD, PD, PD>((const __half*)g_fl,
        (const __half*)g_pv + OFF_PV, (__half*)g_pv);
}
__global__ void __launch_bounds__(256) mm_pfo() {
    gemm_mma_body<NTOK_P, PD, PD, PD>((const __half*)g_pf,
        (const __half*)g_pfo + OFF_PFO, (__half*)g_pfo);
}
__global__ void __launch_bounds__(256) mm_qkw() {
    gemm_mma_body<NTOK_W, 2*WIN_INNER, PLD, PLD>((const __half*)g_plln,
        (const __half*)g_fl + OFF_FL, (__half*)g_qkw);
}
__global__ void __launch_bounds__(256) mm_wv() {
    gemm_mma_body<NTOK_W, WIN_INNER, WD, WD / WV_SPLITK>((const __half*)g_lnxw,
        (const __half*)g_lnxw + OFF_LNXW, g_wv_part);
}
__global__ void __launch_bounds__(256) mm_wfo() {
    gemm_mma_body<NTOK_W, WD, WIN_INNER, WIN_INNER>((const __half*)g_wf,
        (const __half*)g_wfo + OFF_WFO, (__half*)g_wfo);
}

// weight fp32 -> fp16 into spare buffer tails
#define DEF_KW(name, dstbuf, dstoff)                                          \
__global__ void name(const float4* __restrict__ in, int n4) {                 \
    int i = blockIdx.x * blockDim.x + threadIdx.x;                            \
    if (i >= n4) return;                                                      \
    uint2 h;                                                                  \
    cvt4(in[i], h);                                                           \
    *(uint2*)((__half*)dstbuf + dstoff + (size_t)i * 4) = h;                  \
}
DEF_KW(kW_qkp,  g_qkp,  OFF_QKP)
DEF_KW(kW_vp,   g_pv,   OFF_PV)
DEF_KW(kW_outp, g_pfo,  OFF_PFO)
DEF_KW(kW_qkw,  g_fl,   OFF_FL)
DEF_KW(kW_vw,   g_lnxw, OFF_LNXW)
DEF_KW(kW_outw, g_wfo,  OFF_WFO)

// ---------------------------------------------------------------------------
__device__ __forceinline__ float blockReduceSum(float v, float* sh) {
    int lane = threadIdx.x & 31, wid = threadIdx.x >> 5;
    #pragma unroll
    for (int o = 16; o > 0; o >>= 1) v += __shfl_down_sync(0xffffffffu, v, o);
    if (lane == 0) sh[wid] = v;
    __syncthreads();
    int nw = blockDim.x >> 5;
    v = (threadIdx.x < (unsigned)nw) ? sh[threadIdx.x] : 0.f;
    if (wid == 0) {
        #pragma unroll
        for (int o = 16; o > 0; o >>= 1) v += __shfl_down_sync(0xffffffffu, v, o);
        if (lane == 0) sh[0] = v;
    }
    __syncthreads();
    float r = sh[0];
    __syncthreads();
    return r;
}

// ---------------------------------------------------------------------------
// kA: gather + LN -> g_fl (fp16), coalesced + smem transpose
// ---------------------------------------------------------------------------
__global__ void kA_fl(const float* __restrict__ x,
                      const float* __restrict__ gam, const float* __restrict__ bet) {
    int t = blockIdx.x;
    int b = t >> 8, w = (t >> 4) & 15, p = t & 15;
    int wy = w >> 2, wx = w & 3, py = p >> 2, px = p & 3;
    int i0 = wy * WS + py * PS, j0 = wx * WS + px * PS;
    __shared__ float red[32];
    __shared__ float sv[16][65];
    float s = 0.f, s2 = 0.f;
    #pragma unroll
    for (int r = 0; r < 4; r++) {
        int e = threadIdx.x + r * 256;
        int c = e >> 6, pix = e & 63;
        int sy = pix >> 3, sx = pix & 7;
        float v = x[(((size_t)b * CCH + c) * SZ + (i0 + sy)) * SZ + (j0 + sx)];
        sv[c][pix] = v;
        s += v; s2 += v * v;
    }
    s  = blockReduceSum(s,  red);
    s2 = blockReduceSum(s2, red);
    float m  = s  * (1.f / PD);
    float rs = rsqrtf(s2 * (1.f / PD) - m * m + 1e-5f);
    __half* out = (__half*)g_fl;
    #pragma unroll
    for (int r = 0; r < 4; r++) {
        int d = threadIdx.x + r * 256;
        int sidx = d >> 4, c = d & 15;
        float v = sv[c][sidx];
        out[(size_t)t * PD + d] = __float2half_rn((v - m) * rs * gam[d] + bet[d]);
    }
}

// ---------------------------------------------------------------------------
// kB: patch attention + LePE conv -> g_pf (fp16). Vectorized smem loops:
// float4 in the S-compute, float2 in the AV+conv phase.
// ---------------------------------------------------------------------------
__global__ void kB_pattn(const float* __restrict__ cw, const float* __restrict__ cb) {
    int bid = blockIdx.x;
    int h = bid & 7;
    size_t tb = (size_t)(bid >> 3) * NPAT;
    __shared__ float qs[NPAT][132], ks[NPAT][132], S[NPAT][17];
    int tid = threadIdx.x;
    const __half* qk = (const __half*)g_qkp;
    const __half* pv = (const __half*)g_pv;
    #pragma unroll
    for (int r = 0; r < 8; r++) {
        int idx = tid + r * 256;
        int p = idx >> 7, d = idx & 127;
        qs[p][d] = __half2float(qk[(tb + p) * (2 * PD) + h * PDH + d]);
        ks[p][d] = __half2float(qk[(tb + p) * (2 * PD) + PD + h * PDH + d]);
    }
    __syncthreads();
    {
        int p = tid >> 4, v = tid & 15;
        float acc = 0.f;
        #pragma unroll
        for (int d4 = 0; d4 < PDH; d4 += 4) {
            float4 q = *(const float4*)&qs[p][d4];
            float4 k = *(const float4*)&ks[v][d4];
            acc += q.x * k.x + q.y * k.y + q.z * k.z + q.w * k.w;
        }
        S[p][v] = acc * ATT_SCALE;
    }
    __syncthreads();
    if (tid < NPAT) {
        float mx = -1e30f;
        #pragma unroll
        for (int v = 0; v < NPAT; v++) mx = fmaxf(mx, S[tid][v]);
        float e[NPAT], sum = 0.f;
        #pragma unroll
        for (int v = 0; v < NPAT; v++) { e[v] = __expf(S[tid][v] - mx); sum += e[v]; }
        float inv = 1.f / sum;
        #pragma unroll
        for (int v = 0; v < NPAT; v++) S[tid][v] = e[v] * inv;
    }
    __syncthreads();
    #pragma unroll
    for (int r = 0; r < 8; r++) {
        int idx = tid + r * 256;
        int p = idx >> 7, d = idx & 127;
        ks[p][d] = __half2float(pv[(tb + p) * PD + h * PDH + d]);
    }
    __syncthreads();
    __half* out = (__half*)g_pf;
    #pragma unroll
    for (int r = 0; r < 4; r++) {
        int e = tid + r * 256;            // 1024 float2 outputs
        int p = e >> 6, d = (e & 63) * 2;
        float ax = 0.f, ay = 0.f;
        #pragma unroll
        for (int v = 0; v < NPAT; v++) {
            float sc = S[p][v];
            float2 kv = *(const float2*)&ks[v][d];
            ax += sc * kv.x;
            ay += sc * kv.y;
        }
        int py = p >> 2, px = p & 3;
        #pragma unroll
        for (int ky = 0; ky < 3; ky++) {
            int yy = py + ky - 1;
            if (yy < 0 || yy > 3) continue;
            #pragma unroll
            for (int kx = 0; kx < 3; kx++) {
                int xx = px + kx - 1;
                if (xx < 0 || xx > 3) continue;
                float2 kv = *(const float2*)&ks[yy * 4 + xx][d];
                ax += cw[d * 9 + ky * 3 + kx] * kv.x;
                ay += cw[(d + 1) * 9 + ky * 3 + kx] * kv.y;
            }
        }
        ax += cb[d];
        ay += cb[d + 1];
        *(__half2*)&out[(tb + p) * PD + h * PDH + d] = __floats2half2_rn(ax, ay);
    }
}

// ---------------------------------------------------------------------------
// kC: 4x4 pool + gather + LN -> g_plln (fp16). Coalesced channel-chunked
// staging (4 ch x 1024 px per pass), pool from smem, transposed write buffer.
// ---------------------------------------------------------------------------
__global__ void kC_pl(const float* __restrict__ x,
                      const float* __restrict__ gam, const float* __restrict__ bet) {
    int t = blockIdx.x;
    int b = t >> 4, w = t & 15, wy = w >> 2, wx = w & 3;
    __shared__ float red[32];
    __shared__ float sv[4][1028];     // 4 channels x 1024 pixels
    __shared__ float po2[16][65];     // pooled, [channel][region]
    int tid = threadIdx.x;
    float s = 0.f, s2 = 0.f;
    #pragma unroll
    for (int cc = 0; cc < 4; cc++) {
        __syncthreads();
        #pragma unroll
        for (int i = 0; i < 16; i++) {
            int q = tid + i * 256;
            int c = q >> 10, pix = q & 1023;
            int sy = pix >> 5, sx = pix & 31;
            sv[c][pix] = x[(((size_t)b * CCH + cc * 4 + c) * SZ + wy * WS + sy) * SZ + wx * WS + sx];
        }
        __syncthreads();
        int c = tid >> 6, reg = tid & 63;
        int uy = reg >> 3, ux = reg & 7;
        float acc = 0.f;
        #pragma unroll
        for (int a = 0; a < 4; a++)
            #pragma unroll
            for (int e = 0; e < 4; e++)
                acc += sv[c][(uy * 4 + a) * 32 + ux * 4 + e];
        float v = acc * (1.f / 16.f);
        po2[cc * 4 + c][reg] = v;
        s += v; s2 += v * v;
    }
    s  = blockReduceSum(s,  red);
    s2 = blockReduceSum(s2, red);
    float m  = s  * (1.f / PLD);
    float rs = rsqrtf(s2 * (1.f / PLD) - m * m + 1e-5f);
    __half* out = (__half*)g_plln;
    #pragma unroll
    for (int r = 0; r < 4; r++) {
        int d = tid + r * 256;
        int reg = d >> 4, c = d & 15;
        float v = po2[c][reg];
        out[(size_t)t * PLD + d] = __float2half_rn((v - m) * rs * gam[d] + bet[d]);
    }
}

// ---------------------------------------------------------------------------
// kD: window scores + diag logic (reads fp16 qkw)
// ---------------------------------------------------------------------------
__global__ void kD_wscores() {
    int bid = blockIdx.x;
    int h = bid & 7, b = bid >> 3;
    __shared__ float qs[NWIN][132], ks[NWIN][132], S[NWIN][17];
    int tid = threadIdx.x;
    const __half* qk = (const __half*)g_qkw;
    #pragma unroll
    for (int r = 0; r < 8; r++) {
        int idx = tid + r * 256;
        int n = idx >> 7, d = idx & 127;
        qs[n][d] = __half2float(qk[((size_t)b * NWIN + n) * (2 * WIN_INNER) + h * WDH + d]);
        ks[n][d] = __half2float(qk[((size_t)b * NWIN + n) * (2 * WIN_INNER) + WIN_INNER + h * WDH + d]);
    }
    __syncthreads();
    int n = tid >> 4, m = tid & 15;
    {
        float acc = 0.f;
        #pragma unroll
        for (int d4 = 0; d4 < WDH; d4 += 4) {
            float4 q = *(const float4*)&qs[n][d4];
            float4 k = *(const float4*)&ks[m][d4];
            acc += q.x * k.x + q.y * k.y + q.z * k.z + q.w * k.w;
        }
        S[n][m] = acc * ATT_SCALE;
    }
    __syncthreads();
    if (tid < NWIN) {
        float mx = -1e30f;
        #pragma unroll
        for (int v = 0; v < NWIN; v++) mx = fmaxf(mx, S[tid][v]);
        float e[NWIN], sum = 0.f;
        #pragma unroll
        for (int v = 0; v < NWIN; v++) { e[v] = __expf(S[tid][v] - mx); sum += e[v]; }
        float inv = 1.f / sum;
        #pragma unroll
        for (int v = 0; v < NWIN; v++) S[tid][v] = e[v] * inv;
    }
    __syncthreads();
    float dn = S[n][n];
    bool line = dn < 0.5f;
    if (m == 0) g_ds[((size_t)b * NH + h) * NWIN + n] = line ? 0.5f : dn;
    float val = (m == n) ? 0.f : S[n][m];
    if (line) val *= 0.5f / (1.f - dn);
    g_nds[(((size_t)b * NH + h) * NWIN + n) * NWIN + m] = val;
}

// ---------------------------------------------------------------------------
// kE: window gather + LN(WD) -> g_lnxw (fp16), single gmem pass via fp16 smem
// ---------------------------------------------------------------------------
__global__ void kE_lnxw(const float* __restrict__ x,
                        const float* __restrict__ gam, const float* __restrict__ bet) {
    int t = blockIdx.x;
    int b = t >> 4, w = t & 15, wy = w >> 2, wx = w & 3;
    __shared__ float red[32];
    __shared__ __half sx16[16][1032];
    float s = 0.f, s2 = 0.f;
    #pragma unroll
    for (int cc = 0; cc < 16; cc++) {
        const float* xc = x + (((size_t)b * CCH + cc) * SZ + wy * WS) * SZ + wx * WS;
        #pragma unroll
        for (int i = 0; i < 4; i++) {
            int pix = threadIdx.x + i * 256;
            int sy = pix >> 5, sx = pix & 31;
            float v = xc[(size_t)sy * SZ + sx];
            sx16[cc][pix] = __float2half_rn(v);
            s += v; s2 += v * v;
        }
    }
    s  = blockReduceSum(s,  red);
    s2 = blockReduceSum(s2, red);
    float m  = s  * (1.f / WD);
    float rs = rsqrtf(s2 * (1.f / WD) - m * m + 1e-5f);
    __half* out = (__half*)g_lnxw;
    #pragma unroll
    for (int i = 0; i < 64; i++) {
        int d = threadIdx.x + i * 256;
        int sidx = d >> 4, c = d & 15;
        float v = __half2float(sx16[c][sidx]);
        out[(size_t)t * WD + d] = __float2half_rn((v - m) * rs * gam[d] + bet[d]);
    }
}

// ---------------------------------------------------------------------------
// kF: nds value mixing + LePE conv -> g_wf (fp16); split-K sum inlined.
// ---------------------------------------------------------------------------
__global__ void kF_wattn(const float* __restrict__ cw, const float* __restrict__ cb) {
    int bid = blockIdx.x;
    int h = bid & 7, b = bid >> 3;
    __shared__ float vs[NWIN][132], P[NWIN][17];
    int tid = threadIdx.x;
    #pragma unroll
    for (int r = 0; r < 8; r++) {
        int idx = tid + r * 256;
        int n = idx >> 7, d = idx & 127;
        size_t off = ((size_t)b * NWIN + n) * WIN_INNER + h * WDH + d;
        float a = 0.f;
        #pragma unroll
        for (int z = 0; z < WV_SPLITK; z++)
            a += g_wv_part[(size_t)z * NTOK_W * WIN_INNER + off];
        vs[n][d] = a;
    }
    {
        int n = tid >> 4, m = tid & 15;
        if (tid < 256) P[n][m] = g_nds[(((size_t)b * NH + h) * NWIN + n) * NWIN + m];
    }
    __syncthreads();
    __half* out = (__half*)g_wf;
    #pragma unroll
    for (int r = 0; r < 4; r++) {
        int e = tid + r * 256;            // 1024 float2 outputs
        int n = e >> 6, d = (e & 63) * 2;
        float ax = 0.f, ay = 0.f;
        #pragma unroll
        for (int m = 0; m < NWIN; m++) {
            float sc = P[n][m];
            float2 kv = *(const float2*)&vs[m][d];
            ax += sc * kv.x;
            ay += sc * kv.y;
        }
        int wyy = n >> 2, wxx = n & 3;
        #pragma unroll
        for (int ky = 0; ky < 3; ky++) {
            int yy = wyy + ky - 1;
            if (yy < 0 || yy > 3) continue;
            #pragma unroll
            for (int kx = 0; kx < 3; kx++) {
                int xx = wxx + kx - 1;
                if (xx < 0 || xx > 3) continue;
                float2 kv = *(const float2*)&vs[yy * 4 + xx][d];
                ax += cw[d * 9 + ky * 3 + kx] * kv.x;
                ay += cw[(d + 1) * 9 + ky * 3 + kx] * kv.y;
            }
        }
        ax += cb[d];
        ay += cb[d + 1];
        *(__half2*)&out[((size_t)b * NWIN + n) * WIN_INNER + h * WDH + d] =
            __floats2half2_rn(ax, ay);
    }
}

// ---------------------------------------------------------------------------
// kG: out = ds*pfo + wfo + x, smem-transposed both sides.
// ---------------------------------------------------------------------------
__global__ void kG_out(const float* __restrict__ x, float* __restrict__ out) {
    int bid = blockIdx.x;
    int ch = bid & 7, t = bid >> 3;
    int b = t >> 4, n = t & 15;
    int wy = n >> 2, wx = n & 3;
    __shared__ float sv[16][129];
    const __half* pfo = (const __half*)g_pfo;
    const __half* wfo = (const __half*)g_wfo;
    const float ds = g_ds[((size_t)b * NH + ch) * NWIN + n];
    size_t base = (size_t)t * WD + (size_t)ch * 2048;
    #pragma unroll
    for (int i = 0; i < 8; i++) {
        int q = threadIdx.x + i * 256;
        float v = ds * __half2float(pfo[base + q]) + __half2float(wfo[base + q]);
        sv[q & 15][q >> 4] = v;
    }
    __syncthreads();
    #pragma unroll
    for (int i = 0; i < 8; i++) {
        int q = threadIdx.x + i * 256;
        int c = q >> 7, pix = q & 127;
        int gp = ch * 128 + pix;
        int sy = gp >> 5, sx = gp & 31;
        size_t xi = (((size_t)b * CCH + c) * SZ + wy * WS + sy) * SZ + wx * WS + sx;
        out[xi] = sv[c][pix] + x[xi];
    }
}

// ---------------------------------------------------------------------------
// Launch
// ---------------------------------------------------------------------------
extern "C" void kernel_launch(void* const* d_in, const int* in_sizes, int n_in,
                              void* d_out, int out_size) {
    const float* x       = (const float*)d_in[0];
    const float* pn_g    = (const float*)d_in[1];
    const float* pn_b    = (const float*)d_in[2];
    const float* Wqk_p   = (const float*)d_in[3];
    const float* Wv_p    = (const float*)d_in[4];
    const float* conv_pw = (const float*)d_in[5];
    const float* conv_pb = (const float*)d_in[6];
    const float* Wout_p  = (const float*)d_in[7];
    const float* pln_g   = (const float*)d_in[8];
    const float* pln_b   = (const float*)d_in[9];
    const float* Wqk_w   = (const float*)d_in[10];
    const float* wn_g    = (const float*)d_in[11];
    const float* wn_b    = (const float*)d_in[12];
    const float* Wv_w    = (const float*)d_in[13];
    const float* conv_ww = (const float*)d_in[14];
    const float* conv_wb = (const float*)d_in[15];
    const float* Wout_w  = (const float*)d_in[16];
    float* out = (float*)d_out;

    cudaStream_t s2;
    cudaStreamCreateWithFlags(&s2, cudaStreamNonBlocking);
    cudaEvent_t evFork, evJoin;
    cudaEventCreateWithFlags(&evFork, cudaEventDisableTiming);
    cudaEventCreateWithFlags(&evJoin, cudaEventDisableTiming);

    cudaEventRecord(evFork, 0);
    cudaStreamWaitEvent(s2, evFork, 0);

    auto nb4 = [](size_t n) { return (unsigned)((n / 4 + 255) / 256); };

    // --- window branch (stream s2) ---
    kW_qkw <<<nb4((size_t)PLD*2*WIN_INNER), 256, 0, s2>>>((const float4*)Wqk_w, PLD*2*WIN_INNER/4);
    kW_vw  <<<nb4((size_t)WD*WIN_INNER),    256, 0, s2>>>((const float4*)Wv_w,  WD*WIN_INNER/4);
    kW_outw<<<nb4((size_t)WIN_INNER*WD),    256, 0, s2>>>((const float4*)Wout_w, WIN_INNER*WD/4);
    kC_pl<<<NTOK_W, 256, 0, s2>>>(x, pln_g, pln_b);
    mm_qkw<<<dim3((2*WIN_INNER)/128, NTOK_W/128), 256, 0, s2>>>();
    kD_wscores<<<BATCH*NH, 256, 0, s2>>>();
    kE_lnxw<<<NTOK_W, 256, 0, s2>>>(x, wn_g, wn_b);
    mm_wv <<<dim3(WIN_INNER/128, NTOK_W/128, WV_SPLITK), 256, 0, s2>>>();
    kF_wattn<<<BATCH*NH, 256, 0, s2>>>(conv_ww, conv_wb);
    mm_wfo<<<dim3(WD/128, NTOK_W/128), 256, 0, s2>>>();
    cudaEventRecord(evJoin, s2);

    // --- patch branch (default stream) ---
    kW_qkp <<<nb4((size_t)PD*2*PD), 256>>>((const float4*)Wqk_p,  PD*2*PD/4);
    kW_vp  <<<nb4((size_t)PD*PD),   256>>>((const float4*)Wv_p,   PD*PD/4);
    kW_outp<<<nb4((size_t)PD*PD),   256>>>((const float4*)Wout_p, PD*PD/4);
    kA_fl<<<NTOK_P, 256>>>(x, pn_g, pn_b);
    mm_qkp<<<dim3((2*PD)/128, NTOK_P/128), 256>>>();
    mm_pv <<<dim3(PD/128,     NTOK_P/128), 256>>>();
    kB_pattn<<<BATCH*NWIN*NH, 256>>>(conv_pw, conv_pb);
    mm_pfo<<<dim3(PD/128,     NTOK_P/128), 256>>>();

    cudaStreamWaitEvent(0, evJoin, 0);

    // --- combine + residual ---
    kG_out<<<NTOK_W * 8, 256>>>(x, out);
}

// round 17
// speedup vs baseline: 8.0575x; 1.0002x over previous
#include <cuda_runtime.h>
#include <cuda_fp16.h>
#include <cstdint>

// ---------------------------------------------------------------------------
// Problem dims (compile-time)
// ---------------------------------------------------------------------------
#define BATCH 64
#define CCH   16
#define SZ    128
#define WS    32
#define PS    8
#define NH    8
#define WN    4
#define PPW   4
#define NWIN  16
#define NPAT  16
#define PD    1024
#define PDH   128
#define PLD   1024
#define WDH   128
#define WIN_INNER 1024
#define WD    16384
#define NTOK_P (BATCH*NWIN*NPAT)   // 16384
#define NTOK_W (BATCH*NWIN)        // 1024
#define ATT_SCALE 0.08838834764831845f

#define WV_SPLITK 8

// ---------------------------------------------------------------------------
// Scratch (device globals) — EXACT R2/R7 set (known delta=0).
// fp16 regions (via (__half*) casts):
//   heads:  g_fl, g_pf, g_plln, g_lnxw, g_wf (A), g_qkp, g_pv, g_qkw,
//           g_pfo, g_wfo (C)
//   tails (unused upper halves) cache fp16 weights:
//     g_qkp +32M : Wqk_p   g_pv  +16M : Wv_p    g_pfo +16M : Wout_p
//     g_fl  +16M : Wqk_w   g_lnxw+16M : Wv_w    g_wfo +16M : Wout_w
//   fp32: g_wv_part, g_nds, g_ds
// ---------------------------------------------------------------------------
__device__ float g_fl  [(size_t)NTOK_P * PD];
__device__ float g_qkp [(size_t)NTOK_P * 2 * PD];
__device__ float g_pv  [(size_t)NTOK_P * PD];
__device__ float g_pf  [(size_t)NTOK_P * PD];
__device__ float g_pfo [(size_t)NTOK_P * PD];
__device__ float g_plln[(size_t)NTOK_W * PLD];
__device__ float g_qkw [(size_t)NTOK_W * 2 * WIN_INNER];
__device__ float g_nds [(size_t)BATCH * NH * NWIN * NWIN];
__device__ float g_ds  [(size_t)BATCH * NH * NWIN];
__device__ float g_lnxw[(size_t)NTOK_W * WD];
__device__ float g_wv  [(size_t)NTOK_W * WIN_INNER];
__device__ float g_wv_part[(size_t)WV_SPLITK * NTOK_W * WIN_INNER];
__device__ float g_wf  [(size_t)NTOK_W * WIN_INNER];
__device__ float g_wfo [(size_t)NTOK_W * WD];

#define OFF_QKP  ((size_t)NTOK_P * 2 * PD)
#define OFF_PV   ((size_t)NTOK_P * PD)
#define OFF_PFO  ((size_t)NTOK_P * PD)
#define OFF_FL   ((size_t)NTOK_P * PD)
#define OFF_LNXW ((size_t)NTOK_W * WD)
#define OFF_WFO  ((size_t)NTOK_W * WD)

// ---------------------------------------------------------------------------
// MMA helpers
// ---------------------------------------------------------------------------
__device__ __forceinline__ void ldsm4(uint32_t& r0, uint32_t& r1, uint32_t& r2,
                                      uint32_t& r3, const void* p) {
    uint32_t a = (uint32_t)__cvta_generic_to_shared(p);
    asm volatile("ldmatrix.sync.aligned.m8n8.x4.shared.b16 {%0,%1,%2,%3}, [%4];"
                 : "=r"(r0), "=r"(r1), "=r"(r2), "=r"(r3) : "r"(a));
}
__device__ __forceinline__ void ldsm4t(uint32_t& r0, uint32_t& r1, uint32_t& r2,
                                       uint32_t& r3, const void* p) {
    uint32_t a = (uint32_t)__cvta_generic_to_shared(p);
    asm volatile("ldmatrix.sync.aligned.m8n8.x4.trans.shared.b16 {%0,%1,%2,%3}, [%4];"
                 : "=r"(r0), "=r"(r1), "=r"(r2), "=r"(r3) : "r"(a));
}
__device__ __forceinline__ void mma_f16(float* c, const uint32_t* a, uint32_t b0, uint32_t b1) {
    asm volatile(
        "mma.sync.aligned.m16n8k16.row.col.f32.f16.f16.f32 "
        "{%0,%1,%2,%3},{%4,%5,%6,%7},{%8,%9},{%0,%1,%2,%3};"
        : "+f"(c[0]), "+f"(c[1]), "+f"(c[2]), "+f"(c[3])
        : "r"(a[0]), "r"(a[1]), "r"(a[2]), "r"(a[3]), "r"(b0), "r"(b1));
}

__device__ __forceinline__ void cvt4(float4 v, uint2& h) {
    __half2 h01 = __floats2half2_rn(v.x, v.y);
    __half2 h23 = __floats2half2_rn(v.z, v.w);
    h.x = *reinterpret_cast<uint32_t*>(&h01);
    h.y = *reinterpret_cast<uint32_t*>(&h23);
}

__device__ __forceinline__ void store2(float* C, size_t off, float a, float b) {
    *(float2*)(C + off) = make_float2(a, b);
}
__device__ __forceinline__ void store2(__half* C, size_t off, float a, float b) {
    *(__half2*)(C + off) = __floats2half2_rn(a, b);
}

// ---------------------------------------------------------------------------
// fp16 tensor-core GEMM: C = A(fp16) @ B(fp16), fp32 accum, OutT output.
// Double-buffered smem; register prefetch. 128x128x32, 256 thr, warp 64x32.
// ---------------------------------------------------------------------------
template<int M, int N, int K, int KC, typename OutT>
__device__ __forceinline__ void gemm_mma_body(const __half* __restrict__ A,
                                              const __half* __restrict__ B,
                                              OutT* __restrict__ Cbase) {
    constexpr int BM = 128, BN = 128, BK = 32;
    constexpr int APAD = 8, BPAD = 8;
    __shared__ __half Ah[2][BM][BK + APAD];
    __shared__ __half Bh[2][BK][BN + BPAD];

    const int tid  = threadIdx.x;
    const int lane = tid & 31;
    const int wid  = tid >> 5;
    const int wm   = wid & 1;
    const int wn   = wid >> 1;
    const size_t m0 = (size_t)blockIdx.y * BM;
    const size_t n0 = (size_t)blockIdx.x * BN;
    const int kc0 = blockIdx.z * KC;
    OutT* __restrict__ C = Cbase + (size_t)blockIdx.z * M * N;

    const __half* Abp = A + m0 * K;
    const __half* Bbp = B + n0;

    float acc[4][4][4];
    #pragma unroll
    for (int i = 0; i < 4; i++)
        #pragma unroll
        for (int j = 0; j < 4; j++)
            #pragma unroll
            for (int e = 0; e < 4; e++) acc[i][j][e] = 0.f;

    const int ar  = lane & 15;
    const int ac8 = (lane >> 4) << 3;
    const int nIter = KC / BK;

    uint4 pa[2], pb[2];

    #pragma unroll
    for (int i = 0; i < 2; i++) {
        int q = tid + 256 * i;
        int row = q >> 2, c8 = (q & 3) * 8;
        pa[i] = *(const uint4*)(Abp + (size_t)row * K + kc0 + c8);
        int rb = q >> 4, cb8 = (q & 15) * 8;
        pb[i] = *(const uint4*)(Bbp + (size_t)(kc0 + rb) * N + cb8);
    }

    for (int it = 0; it < nIter; ++it) {
        const int s = it & 1;
        #pragma unroll
        for (int i = 0; i < 2; i++) {
            int q = tid + 256 * i;
            int row = q >> 2, c8 = (q & 3) * 8;
            *(uint4*)&Ah[s][row][c8] = pa[i];
            int rb = q >> 4, cb8 = (q & 15) * 8;
            *(uint4*)&Bh[s][rb][cb8] = pb[i];
        }
        __syncthreads();

        if (it + 1 < nIter) {
            int k0n = kc0 + (it + 1) * BK;
            #pragma unroll
            for (int i = 0; i < 2; i++) {
                int q = tid + 256 * i;
                int row = q >> 2, c8 = (q & 3) * 8;
                pa[i] = *(const uint4*)(Abp + (size_t)row * K + k0n + c8);
                int rb = q >> 4, cb8 = (q & 15) * 8;
                pb[i] = *(const uint4*)(Bbp + (size_t)(k0n + rb) * N + cb8);
            }
        }

        #pragma unroll
        for (int kk = 0; kk < 2; kk++) {
            uint32_t af[4][4], bf[2][4];
            #pragma unroll
            for (int mi = 0; mi < 4; mi++)
                ldsm4(af[mi][0], af[mi][1], af[mi][2], af[mi][3],
                      &Ah[s][wm * 64 + mi * 16 + ar][kk * 16 + ac8]);
            #pragma unroll
            for (int ni = 0; ni < 2; ni++)
                ldsm4t(bf[ni][0], bf[ni][1], bf[ni][2], bf[ni][3],
                       &Bh[s][kk * 16 + ar][wn * 32 + ni * 16 + ac8]);
            #pragma unroll
            for (int mi = 0; mi < 4; mi++)
                #pragma unroll
                for (int nj = 0; nj < 4; nj++) {
                    int ni = nj >> 1, pr = (nj & 1) << 1;
                    mma_f16(acc[mi][nj], af[mi], bf[ni][pr], bf[ni][pr + 1]);
                }
        }
    }

    const int gid = lane >> 2, tig = lane & 3;
    #pragma unroll
    for (int mi = 0; mi < 4; mi++) {
        size_t r0 = m0 + wm * 64 + mi * 16 + gid;
        #pragma unroll
        for (int nj = 0; nj < 4; nj++) {
            size_t cc = n0 + wn * 32 + nj * 8 + tig * 2;
            store2(C, r0 * N + cc,       acc[mi][nj][0], acc[mi][nj][1]);
            store2(C, (r0 + 8) * N + cc, acc[mi][nj][2], acc[mi][nj][3]);
        }
    }
}

__global__ void __launch_bounds__(256) mm_qkp() {
    gemm_mma_body<NTOK_P, 2*PD, PD, PD>((const __half*)g_fl,
        (const __half*)g_qkp + OFF_QKP, (__half*)g_qkp);
}
__global__ void __launch_bounds__(256) mm_pv() {
    gemm_mma_body<NTOK_P, PD, PD, PD>((const __half*)g_fl,
        (const __half*)g_pv + OFF_PV, (__half*)g_pv);
}
__global__ void __launch_bounds__(256) mm_pfo() {
    gemm_mma_body<NTOK_P, PD, PD, PD>((const __half*)g_pf,
        (const __half*)g_pfo + OFF_PFO, (__half*)g_pfo);
}
__global__ void __launch_bounds__(256) mm_qkw() {
    gemm_mma_body<NTOK_W, 2*WIN_INNER, PLD, PLD>((const __half*)g_plln,
        (const __half*)g_fl + OFF_FL, (__half*)g_qkw);
}
__global__ void __launch_bounds__(256) mm_wv() {
    gemm_mma_body<NTOK_W, WIN_INNER, WD, WD / WV_SPLITK>((const __half*)g_lnxw,
        (const __half*)g_lnxw + OFF_LNXW, g_wv_part);
}
__global__ void __launch_bounds__(256) mm_wfo() {
    gemm_mma_body<NTOK_W, WD, WIN_INNER, WIN_INNER>((const __half*)g_wf,
        (const __half*)g_wfo + OFF_WFO, (__half*)g_wfo);
}

// weight fp32 -> fp16 into spare buffer tails
#define DEF_KW(name, dstbuf, dstoff)                                          \
__global__ void name(const float4* __restrict__ in, int n4) {                 \
    int i = blockIdx.x * blockDim.x + threadIdx.x;                            \
    if (i >= n4) return;                                                      \
    uint2 h;                                                                  \
    cvt4(in[i], h);                                                           \
    *(uint2*)((__half*)dstbuf + dstoff + (size_t)i * 4) = h;                  \
}
DEF_KW(kW_qkp,  g_qkp,  OFF_QKP)
DEF_KW(kW_vp,   g_pv,   OFF_PV)
DEF_KW(kW_outp, g_pfo,  OFF_PFO)
DEF_KW(kW_qkw,  g_fl,   OFF_FL)
DEF_KW(kW_vw,   g_lnxw, OFF_LNXW)
DEF_KW(kW_outw, g_wfo,  OFF_WFO)

// ---------------------------------------------------------------------------
__device__ __forceinline__ float blockReduceSum(float v, float* sh) {
    int lane = threadIdx.x & 31, wid = threadIdx.x >> 5;
    #pragma unroll
    for (int o = 16; o > 0; o >>= 1) v += __shfl_down_sync(0xffffffffu, v, o);
    if (lane == 0) sh[wid] = v;
    __syncthreads();
    int nw = blockDim.x >> 5;
    v = (threadIdx.x < (unsigned)nw) ? sh[threadIdx.x] : 0.f;
    if (wid == 0) {
        #pragma unroll
        for (int o = 16; o > 0; o >>= 1) v += __shfl_down_sync(0xffffffffu, v, o);
        if (lane == 0) sh[0] = v;
    }
    __syncthreads();
    float r = sh[0];
    __syncthreads();
    return r;
}

// ---------------------------------------------------------------------------
// kA: gather + LN -> g_fl (fp16), coalesced + smem transpose
// ---------------------------------------------------------------------------
__global__ void kA_fl(const float* __restrict__ x,
                      const float* __restrict__ gam, const float* __restrict__ bet) {
    int t = blockIdx.x;
    int b = t >> 8, w = (t >> 4) & 15, p = t & 15;
    int wy = w >> 2, wx = w & 3, py = p >> 2, px = p & 3;
    int i0 = wy * WS + py * PS, j0 = wx * WS + px * PS;
    __shared__ float red[32];
    __shared__ float sv[16][65];
    float s = 0.f, s2 = 0.f;
    #pragma unroll
    for (int r = 0; r < 4; r++) {
        int e = threadIdx.x + r * 256;
        int c = e >> 6, pix = e & 63;
        int sy = pix >> 3, sx = pix & 7;
        float v = x[(((size_t)b * CCH + c) * SZ + (i0 + sy)) * SZ + (j0 + sx)];
        sv[c][pix] = v;
        s += v; s2 += v * v;
    }
    s  = blockReduceSum(s,  red);
    s2 = blockReduceSum(s2, red);
    float m  = s  * (1.f / PD);
    float rs = rsqrtf(s2 * (1.f / PD) - m * m + 1e-5f);
    __half* out = (__half*)g_fl;
    #pragma unroll
    for (int r = 0; r < 4; r++) {
        int d = threadIdx.x + r * 256;
        int sidx = d >> 4, c = d & 15;
        float v = sv[c][sidx];
        out[(size_t)t * PD + d] = __float2half_rn((v - m) * rs * gam[d] + bet[d]);
    }
}

// ---------------------------------------------------------------------------
// kB: patch attention + LePE conv -> g_pf (fp16). Vectorized smem loops:
// float4 in the S-compute, float2 in the AV+conv phase.
// ---------------------------------------------------------------------------
__global__ void kB_pattn(const float* __restrict__ cw, const float* __restrict__ cb) {
    int bid = blockIdx.x;
    int h = bid & 7;
    size_t tb = (size_t)(bid >> 3) * NPAT;
    __shared__ float qs[NPAT][132], ks[NPAT][132], S[NPAT][17];
    int tid = threadIdx.x;
    const __half* qk = (const __half*)g_qkp;
    const __half* pv = (const __half*)g_pv;
    #pragma unroll
    for (int r = 0; r < 8; r++) {
        int idx = tid + r * 256;
        int p = idx >> 7, d = idx & 127;
        qs[p][d] = __half2float(qk[(tb + p) * (2 * PD) + h * PDH + d]);
        ks[p][d] = __half2float(qk[(tb + p) * (2 * PD) + PD + h * PDH + d]);
    }
    __syncthreads();
    {
        int p = tid >> 4, v = tid & 15;
        float acc = 0.f;
        #pragma unroll
        for (int d4 = 0; d4 < PDH; d4 += 4) {
            float4 q = *(const float4*)&qs[p][d4];
            float4 k = *(const float4*)&ks[v][d4];
            acc += q.x * k.x + q.y * k.y + q.z * k.z + q.w * k.w;
        }
        S[p][v] = acc * ATT_SCALE;
    }
    __syncthreads();
    if (tid < NPAT) {
        float mx = -1e30f;
        #pragma unroll
        for (int v = 0; v < NPAT; v++) mx = fmaxf(mx, S[tid][v]);
        float e[NPAT], sum = 0.f;
        #pragma unroll
        for (int v = 0; v < NPAT; v++) { e[v] = __expf(S[tid][v] - mx); sum += e[v]; }
        float inv = 1.f / sum;
        #pragma unroll
        for (int v = 0; v < NPAT; v++) S[tid][v] = e[v] * inv;
    }
    __syncthreads();
    #pragma unroll
    for (int r = 0; r < 8; r++) {
        int idx = tid + r * 256;
        int p = idx >> 7, d = idx & 127;
        ks[p][d] = __half2float(pv[(tb + p) * PD + h * PDH + d]);
    }
    __syncthreads();
    __half* out = (__half*)g_pf;
    #pragma unroll
    for (int r = 0; r < 4; r++) {
        int e = tid + r * 256;            // 1024 float2 outputs
        int p = e >> 6, d = (e & 63) * 2;
        float ax = 0.f, ay = 0.f;
        #pragma unroll
        for (int v = 0; v < NPAT; v++) {
            float sc = S[p][v];
            float2 kv = *(const float2*)&ks[v][d];
            ax += sc * kv.x;
            ay += sc * kv.y;
        }
        int py = p >> 2, px = p & 3;
        #pragma unroll
        for (int ky = 0; ky < 3; ky++) {
            int yy = py + ky - 1;
            if (yy < 0 || yy > 3) continue;
            #pragma unroll
            for (int kx = 0; kx < 3; kx++) {
                int xx = px + kx - 1;
                if (xx < 0 || xx > 3) continue;
                float2 kv = *(const float2*)&ks[yy * 4 + xx][d];
                ax += cw[d * 9 + ky * 3 + kx] * kv.x;
                ay += cw[(d + 1) * 9 + ky * 3 + kx] * kv.y;
            }
        }
        ax += cb[d];
        ay += cb[d + 1];
        *(__half2*)&out[(tb + p) * PD + h * PDH + d] = __floats2half2_rn(ax, ay);
    }
}

// ---------------------------------------------------------------------------
// kC: 4x4 pool + gather + LN -> g_plln (fp16). Coalesced channel-chunked
// staging (4 ch x 1024 px per pass), pool from smem, transposed write buffer.
// ---------------------------------------------------------------------------
__global__ void kC_pl(const float* __restrict__ x,
                      const float* __restrict__ gam, const float* __restrict__ bet) {
    int t = blockIdx.x;
    int b = t >> 4, w = t & 15, wy = w >> 2, wx = w & 3;
    __shared__ float red[32];
    __shared__ float sv[4][1028];     // 4 channels x 1024 pixels
    __shared__ float po2[16][65];     // pooled, [channel][region]
    int tid = threadIdx.x;
    float s = 0.f, s2 = 0.f;
    #pragma unroll
    for (int cc = 0; cc < 4; cc++) {
        __syncthreads();
        #pragma unroll
        for (int i = 0; i < 16; i++) {
            int q = tid + i * 256;
            int c = q >> 10, pix = q & 1023;
            int sy = pix >> 5, sx = pix & 31;
            sv[c][pix] = x[(((size_t)b * CCH + cc * 4 + c) * SZ + wy * WS + sy) * SZ + wx * WS + sx];
        }
        __syncthreads();
        int c = tid >> 6, reg = tid & 63;
        int uy = reg >> 3, ux = reg & 7;
        float acc = 0.f;
        #pragma unroll
        for (int a = 0; a < 4; a++)
            #pragma unroll
            for (int e = 0; e < 4; e++)
                acc += sv[c][(uy * 4 + a) * 32 + ux * 4 + e];
        float v = acc * (1.f / 16.f);
        po2[cc * 4 + c][reg] = v;
        s += v; s2 += v * v;
    }
    s  = blockReduceSum(s,  red);
    s2 = blockReduceSum(s2, red);
    float m  = s  * (1.f / PLD);
    float rs = rsqrtf(s2 * (1.f / PLD) - m * m + 1e-5f);
    __half* out = (__half*)g_plln;
    #pragma unroll
    for (int r = 0; r < 4; r++) {
        int d = tid + r * 256;
        int reg = d >> 4, c = d & 15;
        float v = po2[c][reg];
        out[(size_t)t * PLD + d] = __float2half_rn((v - m) * rs * gam[d] + bet[d]);
    }
}

// ---------------------------------------------------------------------------
// kD: window scores + diag logic (reads fp16 qkw)
// ---------------------------------------------------------------------------
__global__ void kD_wscores() {
    int bid = blockIdx.x;
    int h = bid & 7, b = bid >> 3;
    __shared__ float qs[NWIN][132], ks[NWIN][132], S[NWIN][17];
    int tid = threadIdx.x;
    const __half* qk = (const __half*)g_qkw;
    #pragma unroll
    for (int r = 0; r < 8; r++) {
        int idx = tid + r * 256;
        int n = idx >> 7, d = idx & 127;
        qs[n][d] = __half2float(qk[((size_t)b * NWIN + n) * (2 * WIN_INNER) + h * WDH + d]);
        ks[n][d] = __half2float(qk[((size_t)b * NWIN + n) * (2 * WIN_INNER) + WIN_INNER + h * WDH + d]);
    }
    __syncthreads();
    int n = tid >> 4, m = tid & 15;
    {
        float acc = 0.f;
        #pragma unroll
        for (int d4 = 0; d4 < WDH; d4 += 4) {
            float4 q = *(const float4*)&qs[n][d4];
            float4 k = *(const float4*)&ks[m][d4];
            acc += q.x * k.x + q.y * k.y + q.z * k.z + q.w * k.w;
        }
        S[n][m] = acc * ATT_SCALE;
    }
    __syncthreads();
    if (tid < NWIN) {
        float mx = -1e30f;
        #pragma unroll
        for (int v = 0; v < NWIN; v++) mx = fmaxf(mx, S[tid][v]);
        float e[NWIN], sum = 0.f;
        #pragma unroll
        for (int v = 0; v < NWIN; v++) { e[v] = __expf(S[tid][v] - mx); sum += e[v]; }
        float inv = 1.f / sum;
        #pragma unroll
        for (int v = 0; v < NWIN; v++) S[tid][v] = e[v] * inv;
    }
    __syncthreads();
    float dn = S[n][n];
    bool line = dn < 0.5f;
    if (m == 0) g_ds[((size_t)b * NH + h) * NWIN + n] = line ? 0.5f : dn;
    float val = (m == n) ? 0.f : S[n][m];
    if (line) val *= 0.5f / (1.f - dn);
    g_nds[(((size_t)b * NH + h) * NWIN + n) * NWIN + m] = val;
}

// ---------------------------------------------------------------------------
// kE: window gather + LN(WD) -> g_lnxw (fp16), single gmem pass via fp16 smem
// ---------------------------------------------------------------------------
__global__ void kE_lnxw(const float* __restrict__ x,
                        const float* __restrict__ gam, const float* __restrict__ bet) {
    int t = blockIdx.x;
    int b = t >> 4, w = t & 15, wy = w >> 2, wx = w & 3;
    __shared__ float red[32];
    __shared__ __half sx16[16][1032];
    float s = 0.f, s2 = 0.f;
    #pragma unroll
    for (int cc = 0; cc < 16; cc++) {
        const float* xc = x + (((size_t)b * CCH + cc) * SZ + wy * WS) * SZ + wx * WS;
        #pragma unroll
        for (int i = 0; i < 4; i++) {
            int pix = threadIdx.x + i * 256;
            int sy = pix >> 5, sx = pix & 31;
            float v = xc[(size_t)sy * SZ + sx];
            sx16[cc][pix] = __float2half_rn(v);
            s += v; s2 += v * v;
        }
    }
    s  = blockReduceSum(s,  red);
    s2 = blockReduceSum(s2, red);
    float m  = s  * (1.f / WD);
    float rs = rsqrtf(s2 * (1.f / WD) - m * m + 1e-5f);
    __half* out = (__half*)g_lnxw;
    #pragma unroll
    for (int i = 0; i < 64; i++) {
        int d = threadIdx.x + i * 256;
        int sidx = d >> 4, c = d & 15;
        float v = __half2float(sx16[c][sidx]);
        out[(size_t)t * WD + d] = __float2half_rn((v - m) * rs * gam[d] + bet[d]);
    }
}

// ---------------------------------------------------------------------------
// kF: nds value mixing + LePE conv -> g_wf (fp16); split-K sum inlined.
// ---------------------------------------------------------------------------
__global__ void kF_wattn(const float* __restrict__ cw, const float* __restrict__ cb) {
    int bid = blockIdx.x;
    int h = bid & 7, b = bid >> 3;
    __shared__ float vs[NWIN][132], P[NWIN][17];
    int tid = threadIdx.x;
    #pragma unroll
    for (int r = 0; r < 8; r++) {
        int idx = tid + r * 256;
        int n = idx >> 7, d = idx & 127;
        size_t off = ((size_t)b * NWIN + n) * WIN_INNER + h * WDH + d;
        float a = 0.f;
        #pragma unroll
        for (int z = 0; z < WV_SPLITK; z++)
            a += g_wv_part[(size_t)z * NTOK_W * WIN_INNER + off];
        vs[n][d] = a;
    }
    {
        int n = tid >> 4, m = tid & 15;
        if (tid < 256) P[n][m] = g_nds[(((size_t)b * NH + h) * NWIN + n) * NWIN + m];
    }
    __syncthreads();
    __half* out = (__half*)g_wf;
    #pragma unroll
    for (int r = 0; r < 4; r++) {
        int e = tid + r * 256;            // 1024 float2 outputs
        int n = e >> 6, d = (e & 63) * 2;
        float ax = 0.f, ay = 0.f;
        #pragma unroll
        for (int m = 0; m < NWIN; m++) {
            float sc = P[n][m];
            float2 kv = *(const float2*)&vs[m][d];
            ax += sc * kv.x;
            ay += sc * kv.y;
        }
        int wyy = n >> 2, wxx = n & 3;
        #pragma unroll
        for (int ky = 0; ky < 3; ky++) {
            int yy = wyy + ky - 1;
            if (yy < 0 || yy > 3) continue;
            #pragma unroll
            for (int kx = 0; kx < 3; kx++) {
                int xx = wxx + kx - 1;
                if (xx < 0 || xx > 3) continue;
                float2 kv = *(const float2*)&vs[yy * 4 + xx][d];
                ax += cw[d * 9 + ky * 3 + kx] * kv.x;
                ay += cw[(d + 1) * 9 + ky * 3 + kx] * kv.y;
            }
        }
        ax += cb[d];
        ay += cb[d + 1];
        *(__half2*)&out[((size_t)b * NWIN + n) * WIN_INNER + h * WDH + d] =
            __floats2half2_rn(ax, ay);
    }
}

// ---------------------------------------------------------------------------
// kG: out = ds*pfo + wfo + x, smem-transposed both sides.
// ---------------------------------------------------------------------------
__global__ void kG_out(const float* __restrict__ x, float* __restrict__ out) {
    int bid = blockIdx.x;
    int ch = bid & 7, t = bid >> 3;
    int b = t >> 4, n = t & 15;
    int wy = n >> 2, wx = n & 3;
    __shared__ float sv[16][129];
    const __half* pfo = (const __half*)g_pfo;
    const __half* wfo = (const __half*)g_wfo;
    const float ds = g_ds[((size_t)b * NH + ch) * NWIN + n];
    size_t base = (size_t)t * WD + (size_t)ch * 2048;
    #pragma unroll
    for (int i = 0; i < 8; i++) {
        int q = threadIdx.x + i * 256;
        float v = ds * __half2float(pfo[base + q]) + __half2float(wfo[base + q]);
        sv[q & 15][q >> 4] = v;
    }
    __syncthreads();
    #pragma unroll
    for (int i = 0; i < 8; i++) {
        int q = threadIdx.x + i * 256;
        int c = q >> 7, pix = q & 127;
        int gp = ch * 128 + pix;
        int sy = gp >> 5, sx = gp & 31;
        size_t xi = (((size_t)b * CCH + c) * SZ + wy * WS + sy) * SZ + wx * WS + sx;
        out[xi] = sv[c][pix] + x[xi];
    }
}

// ---------------------------------------------------------------------------
// Launch
// ---------------------------------------------------------------------------
extern "C" void kernel_launch(void* const* d_in, const int* in_sizes, int n_in,
                              void* d_out, int out_size) {
    const float* x       = (const float*)d_in[0];
    const float* pn_g    = (const float*)d_in[1];
    const float* pn_b    = (const float*)d_in[2];
    const float* Wqk_p   = (const float*)d_in[3];
    const float* Wv_p    = (const float*)d_in[4];
    const float* conv_pw = (const float*)d_in[5];
    const float* conv_pb = (const float*)d_in[6];
    const float* Wout_p  = (const float*)d_in[7];
    const float* pln_g   = (const float*)d_in[8];
    const float* pln_b   = (const float*)d_in[9];
    const float* Wqk_w   = (const float*)d_in[10];
    const float* wn_g    = (const float*)d_in[11];
    const float* wn_b    = (const float*)d_in[12];
    const float* Wv_w    = (const float*)d_in[13];
    const float* conv_ww = (const float*)d_in[14];
    const float* conv_wb = (const float*)d_in[15];
    const float* Wout_w  = (const float*)d_in[16];
    float* out = (float*)d_out;

    cudaStream_t s2;
    cudaStreamCreateWithFlags(&s2, cudaStreamNonBlocking);
    cudaEvent_t evFork, evJoin;
    cudaEventCreateWithFlags(&evFork, cudaEventDisableTiming);
    cudaEventCreateWithFlags(&evJoin, cudaEventDisableTiming);

    cudaEventRecord(evFork, 0);
    cudaStreamWaitEvent(s2, evFork, 0);

    auto nb4 = [](size_t n) { return (unsigned)((n / 4 + 255) / 256); };

    // --- window branch (stream s2) ---
    kW_qkw <<<nb4((size_t)PLD*2*WIN_INNER), 256, 0, s2>>>((const float4*)Wqk_w, PLD*2*WIN_INNER/4);
    kW_vw  <<<nb4((size_t)WD*WIN_INNER),    256, 0, s2>>>((const float4*)Wv_w,  WD*WIN_INNER/4);
    kW_outw<<<nb4((size_t)WIN_INNER*WD),    256, 0, s2>>>((const float4*)Wout_w, WIN_INNER*WD/4);
    kC_pl<<<NTOK_W, 256, 0, s2>>>(x, pln_g, pln_b);
    mm_qkw<<<dim3((2*WIN_INNER)/128, NTOK_W/128), 256, 0, s2>>>();
    kD_wscores<<<BATCH*NH, 256, 0, s2>>>();
    kE_lnxw<<<NTOK_W, 256, 0, s2>>>(x, wn_g, wn_b);
    mm_wv <<<dim3(WIN_INNER/128, NTOK_W/128, WV_SPLITK), 256, 0, s2>>>();
    kF_wattn<<<BATCH*NH, 256, 0, s2>>>(conv_ww, conv_wb);
    mm_wfo<<<dim3(WD/128, NTOK_W/128), 256, 0, s2>>>();
    cudaEventRecord(evJoin, s2);

    // --- patch branch (default stream) ---
    kW_qkp <<<nb4((size_t)PD*2*PD), 256>>>((const float4*)Wqk_p,  PD*2*PD/4);
    kW_vp  <<<nb4((size_t)PD*PD),   256>>>((const float4*)Wv_p,   PD*PD/4);
    kW_outp<<<nb4((size_t)PD*PD),   256>>>((const float4*)Wout_p, PD*PD/4);
    kA_fl<<<NTOK_P, 256>>>(x, pn_g, pn_b);
    mm_qkp<<<dim3((2*PD)/128, NTOK_P/128), 256>>>();
    mm_pv <<<dim3(PD/128,     NTOK_P/128), 256>>>();
    kB_pattn<<<BATCH*NWIN*NH, 256>>>(conv_pw, conv_pb);
    mm_pfo<<<dim3(PD/128,     NTOK_P/128), 256>>>();

    cudaStreamWaitEvent(0, evJoin, 0);

    // --- combine + residual ---
    kG_out<<<NTOK_W * 8, 256>>>(x, out);
}